// round 2
// baseline (speedup 1.0000x reference)
#include <cuda_runtime.h>

#define BATCH 4
#define SEQ   2048
#define DIM   1024
#define HEADS 16
#define HD    64

#define ROWS (BATCH * SEQ)        // 8192

// Scratch (allocation-free rule: device globals)
__device__ float g_qkv[(size_t)ROWS * 3 * DIM];  // [8192, 3072]
__device__ float g_att[(size_t)ROWS * DIM];      // [8192, 1024]

// ---------------------------------------------------------------------------
// SGEMM body: C[M,N] = A[M,K] @ B[K,N] + bias[N]
// BM=BN=128, BK=8, 256 threads, 8x8 per thread.
// ---------------------------------------------------------------------------
template<int M, int N, int K>
__device__ __forceinline__ void sgemm_body(const float* __restrict__ A,
                                           const float* __restrict__ B,
                                           const float* __restrict__ bias,
                                           float* __restrict__ C) {
    constexpr int BM = 128, BN = 128, BK = 8;
    __shared__ float As[BK][BM];
    __shared__ float Bs[BK][BN];

    const int tid = threadIdx.x;
    const int bm = blockIdx.y * BM;
    const int bn = blockIdx.x * BN;
    const int tx = tid % 16, ty = tid / 16;

    float acc[8][8];
    #pragma unroll
    for (int i = 0; i < 8; i++)
        #pragma unroll
        for (int j = 0; j < 8; j++) acc[i][j] = 0.f;

    // loader mapping
    const int arow = tid >> 1;          // 0..127
    const int acol = (tid & 1) * 4;     // 0 or 4
    const int brow = tid >> 5;          // 0..7
    const int bcol = (tid & 31) * 4;    // 0..124

    const float* Aptr = A + (size_t)(bm + arow) * K + acol;
    const float* Bptr = B + (size_t)brow * N + bn + bcol;

    for (int k0 = 0; k0 < K; k0 += BK) {
        float4 a4 = *(const float4*)(Aptr + k0);
        float4 b4 = *(const float4*)(Bptr + (size_t)k0 * N);
        As[acol + 0][arow] = a4.x;
        As[acol + 1][arow] = a4.y;
        As[acol + 2][arow] = a4.z;
        As[acol + 3][arow] = a4.w;
        *(float4*)&Bs[brow][bcol] = b4;
        __syncthreads();

        #pragma unroll
        for (int kk = 0; kk < BK; kk++) {
            float ar[8], br[8];
            *(float4*)(ar)     = *(float4*)&As[kk][ty * 8];
            *(float4*)(ar + 4) = *(float4*)&As[kk][ty * 8 + 4];
            *(float4*)(br)     = *(float4*)&Bs[kk][tx * 8];
            *(float4*)(br + 4) = *(float4*)&Bs[kk][tx * 8 + 4];
            #pragma unroll
            for (int i = 0; i < 8; i++)
                #pragma unroll
                for (int j = 0; j < 8; j++)
                    acc[i][j] += ar[i] * br[j];
        }
        __syncthreads();
    }

    #pragma unroll
    for (int i = 0; i < 8; i++) {
        const int row = bm + ty * 8 + i;
        #pragma unroll
        for (int j = 0; j < 8; j += 4) {
            const int col = bn + tx * 8 + j;
            float4 o;
            o.x = acc[i][j + 0] + bias[col + 0];
            o.y = acc[i][j + 1] + bias[col + 1];
            o.z = acc[i][j + 2] + bias[col + 2];
            o.w = acc[i][j + 3] + bias[col + 3];
            *(float4*)&C[(size_t)row * N + col] = o;
        }
    }
}

__global__ __launch_bounds__(256)
void qkv_gemm_kernel(const float* __restrict__ x,
                     const float* __restrict__ w_qkv,
                     const float* __restrict__ b_qkv) {
    sgemm_body<ROWS, 3 * DIM, DIM>(x, w_qkv, b_qkv, g_qkv);
}

__global__ __launch_bounds__(256)
void out_gemm_kernel(const float* __restrict__ w_out,
                     const float* __restrict__ b_out,
                     float* __restrict__ out) {
    sgemm_body<ROWS, DIM, DIM>(g_att, w_out, b_out, out);
}

// ---------------------------------------------------------------------------
// Causal flash attention.
// grid = (SEQ/128, HEADS, BATCH), block = 128 threads (1 thread = 1 q row).
// Dynamic smem: Ks[64][64] | Vs[64][64] | Ssm[128][65]
// ---------------------------------------------------------------------------
#define QT 128
#define KT 64
#define ATTN_SMEM ((KT * HD + KT * HD + QT * (KT + 1)) * (int)sizeof(float))

__global__ __launch_bounds__(QT)
void attn_kernel() {
    extern __shared__ float smem[];
    float (*Ks)[HD]      = (float(*)[HD])(smem);
    float (*Vs)[HD]      = (float(*)[HD])(smem + KT * HD);
    float (*Ssm)[KT + 1] = (float(*)[KT + 1])(smem + 2 * KT * HD);

    const int qt  = blockIdx.x;
    const int h   = blockIdx.y;
    const int b   = blockIdx.z;
    const int tid = threadIdx.x;
    const int q_idx = qt * QT + tid;

    // Load this thread's q row (pre-scaled by 1/sqrt(Hd))
    float qv[HD];
    {
        const size_t qb = ((size_t)(b * SEQ + q_idx)) * (3 * DIM) + h * HD;
        #pragma unroll
        for (int d = 0; d < HD; d += 4) {
            float4 t = *(const float4*)&g_qkv[qb + d];
            qv[d + 0] = t.x * 0.125f;
            qv[d + 1] = t.y * 0.125f;
            qv[d + 2] = t.z * 0.125f;
            qv[d + 3] = t.w * 0.125f;
        }
    }

    float acc[HD];
    #pragma unroll
    for (int d = 0; d < HD; d++) acc[d] = 0.f;
    float m = -1e30f, l = 0.f;

    const int nkt = qt * 2 + 2;  // causal: only tiles with k_start <= q_max
    for (int kt = 0; kt < nkt; kt++) {
        // cooperative K/V tile load: 2 threads per row, 32 floats each
        {
            const int r  = tid >> 1;
            const int c0 = (tid & 1) * 32;
            const size_t kb = ((size_t)(b * SEQ + kt * KT + r)) * (3 * DIM) + DIM + h * HD + c0;
            const size_t vb = kb + DIM;
            #pragma unroll
            for (int c = 0; c < 32; c += 4) {
                *(float4*)&Ks[r][c0 + c] = *(const float4*)&g_qkv[kb + c];
                *(float4*)&Vs[r][c0 + c] = *(const float4*)&g_qkv[vb + c];
            }
        }
        __syncthreads();

        // scores for this thread's q row
        float tmax = -1e30f;
        #pragma unroll 4
        for (int k = 0; k < KT; k++) {
            float s = 0.f;
            #pragma unroll
            for (int d = 0; d < HD; d += 4) {
                float4 kk = *(float4*)&Ks[k][d];
                s += qv[d] * kk.x + qv[d + 1] * kk.y + qv[d + 2] * kk.z + qv[d + 3] * kk.w;
            }
            if (kt * KT + k > q_idx) s = -1e30f;  // causal mask
            Ssm[tid][k] = s;
            tmax = fmaxf(tmax, s);
        }

        // online softmax rescale
        const float mnew = fmaxf(m, tmax);
        const float corr = __expf(m - mnew);
        l *= corr;
        #pragma unroll
        for (int d = 0; d < HD; d++) acc[d] *= corr;

        // P @ V
        #pragma unroll 2
        for (int k = 0; k < KT; k++) {
            const float p = __expf(Ssm[tid][k] - mnew);
            l += p;
            #pragma unroll
            for (int d = 0; d < HD; d += 4) {
                float4 vv = *(float4*)&Vs[k][d];
                acc[d + 0] += p * vv.x;
                acc[d + 1] += p * vv.y;
                acc[d + 2] += p * vv.z;
                acc[d + 3] += p * vv.w;
            }
        }
        m = mnew;
        __syncthreads();
    }

    const float inv = 1.f / l;
    const size_t ob = ((size_t)(b * SEQ + q_idx)) * DIM + h * HD;
    #pragma unroll
    for (int d = 0; d < HD; d += 4) {
        float4 o;
        o.x = acc[d + 0] * inv;
        o.y = acc[d + 1] * inv;
        o.z = acc[d + 2] * inv;
        o.w = acc[d + 3] * inv;
        *(float4*)&g_att[ob + d] = o;
    }
}

// ---------------------------------------------------------------------------
extern "C" void kernel_launch(void* const* d_in, const int* in_sizes, int n_in,
                              void* d_out, int out_size) {
    const float* x     = (const float*)d_in[0];
    const float* w_qkv = (const float*)d_in[1];
    const float* b_qkv = (const float*)d_in[2];
    const float* w_out = (const float*)d_in[3];
    const float* b_out = (const float*)d_in[4];
    float* out = (float*)d_out;

    // attention kernel needs > 48KB smem
    cudaFuncSetAttribute(attn_kernel, cudaFuncAttributeMaxDynamicSharedMemorySize,
                         ATTN_SMEM);

    // 1) QKV projection: [8192,1024] @ [1024,3072] + b
    {
        dim3 grid(3 * DIM / 128, ROWS / 128);
        qkv_gemm_kernel<<<grid, 256>>>(x, w_qkv, b_qkv);
    }
    // 2) causal multi-head attention
    {
        dim3 grid(SEQ / QT, HEADS, BATCH);
        attn_kernel<<<grid, QT, ATTN_SMEM>>>();
    }
    // 3) output projection: [8192,1024] @ [1024,1024] + b
    {
        dim3 grid(DIM / 128, ROWS / 128);
        out_gemm_kernel<<<grid, 256>>>(w_out, b_out, out);
    }
}

// round 3
// speedup vs baseline: 3.9042x; 3.9042x over previous
#include <cuda_runtime.h>
#include <cstdint>

#define BATCH 4
#define SEQ   2048
#define DIM   1024
#define HEADS 16
#define HD    64
#define ROWS (BATCH * SEQ)        // 8192

// Scratch (allocation-free rule: device globals)
__device__ float g_qkv[(size_t)ROWS * 3 * DIM];  // [8192, 3072]
__device__ float g_att[(size_t)ROWS * DIM];      // [8192, 1024]

// ---------------------------------------------------------------------------
// helpers
// ---------------------------------------------------------------------------
__device__ __forceinline__ uint32_t f2tf(float x) {
    uint32_t r;
    asm("cvt.rna.tf32.f32 %0, %1;" : "=r"(r) : "f"(x));
    return r;
}
__device__ __forceinline__ float f2tf_f(float x) { return __uint_as_float(f2tf(x)); }

__device__ __forceinline__ void mma8(float* c, const uint32_t* a, const uint32_t* b) {
    asm volatile(
        "mma.sync.aligned.m16n8k8.row.col.f32.tf32.tf32.f32 "
        "{%0,%1,%2,%3}, {%4,%5,%6,%7}, {%8,%9}, {%0,%1,%2,%3};"
        : "+f"(c[0]), "+f"(c[1]), "+f"(c[2]), "+f"(c[3])
        : "r"(a[0]), "r"(a[1]), "r"(a[2]), "r"(a[3]), "r"(b[0]), "r"(b[1]));
}

__device__ __forceinline__ uint32_t sptr(const void* p) {
    return (uint32_t)__cvta_generic_to_shared(p);
}
__device__ __forceinline__ void cp16(uint32_t s, const void* g) {
    asm volatile("cp.async.ca.shared.global [%0], [%1], 16;" :: "r"(s), "l"(g));
}
#define CP_COMMIT()  asm volatile("cp.async.commit_group;")
#define CP_WAIT0()   asm volatile("cp.async.wait_group 0;")

// ---------------------------------------------------------------------------
// TF32 MMA GEMM: C[M,N] = A[M,K=1024] @ B[1024,N] + bias
// block 128x128, BK=32, 256 threads (8 warps, 2x4), warp tile 64x32.
// smem: A [128][36] row-major, B [32][136] row-major, double buffered.
// ---------------------------------------------------------------------------
#define GK 1024
#define SAW 36
#define SBW 136
#define ASZ (128 * SAW)               // floats
#define BSZ (32 * SBW)
#define GSTAGE (ASZ + BSZ)
#define GEMM_SMEM (2 * GSTAGE * (int)sizeof(float))   // 71680 B

template<int N>
__device__ __forceinline__ void gemm_load_tile(float* smA, float* smB,
                                               const float* __restrict__ A,
                                               const float* __restrict__ B,
                                               int bm, int bn, int k0, int tid) {
    #pragma unroll
    for (int i = 0; i < 4; i++) {
        int t = tid + i * 256;            // 0..1023
        int row = t >> 3, c4 = (t & 7) * 4;
        cp16(sptr(smA + row * SAW + c4), A + (size_t)(bm + row) * GK + k0 + c4);
    }
    #pragma unroll
    for (int i = 0; i < 4; i++) {
        int t = tid + i * 256;
        int row = t >> 5, c4 = (t & 31) * 4;
        cp16(sptr(smB + row * SBW + c4), B + (size_t)(k0 + row) * N + bn + c4);
    }
}

template<int N>
__global__ __launch_bounds__(256)
void tf32_gemm_kernel(const float* __restrict__ A, const float* __restrict__ B,
                      const float* __restrict__ bias, float* __restrict__ C) {
    extern __shared__ float sm[];
    const int tid  = threadIdx.x;
    const int lane = tid & 31;
    const int wid  = tid >> 5;
    const int g    = lane >> 2;        // group id (row within fragment)
    const int tig  = lane & 3;         // thread in group (k / col pair)
    const int wm   = wid >> 2;         // 0..1
    const int wn   = wid & 3;          // 0..3
    const int bm   = blockIdx.y * 128;
    const int bn   = blockIdx.x * 128;

    float acc[4][4][4];
    #pragma unroll
    for (int mi = 0; mi < 4; mi++)
        #pragma unroll
        for (int ni = 0; ni < 4; ni++)
            #pragma unroll
            for (int j = 0; j < 4; j++) acc[mi][ni][j] = 0.f;

    constexpr int NT = GK / 32;        // 32 k-tiles

    gemm_load_tile<N>(sm, sm + ASZ, A, B, bm, bn, 0, tid);
    CP_COMMIT();

    for (int t = 0; t < NT; t++) {
        CP_WAIT0();
        __syncthreads();
        if (t + 1 < NT) {
            float* nsm = sm + ((t + 1) & 1) * GSTAGE;
            gemm_load_tile<N>(nsm, nsm + ASZ, A, B, bm, bn, (t + 1) * 32, tid);
            CP_COMMIT();
        }
        const float* As = sm + (t & 1) * GSTAGE;
        const float* Bs = As + ASZ;

        #pragma unroll
        for (int ks = 0; ks < 4; ks++) {
            const int k = ks * 8 + tig;
            uint32_t a[4][4];
            #pragma unroll
            for (int mi = 0; mi < 4; mi++) {
                const int m = wm * 64 + mi * 16 + g;
                a[mi][0] = f2tf(As[m * SAW + k]);
                a[mi][1] = f2tf(As[(m + 8) * SAW + k]);
                a[mi][2] = f2tf(As[m * SAW + k + 4]);
                a[mi][3] = f2tf(As[(m + 8) * SAW + k + 4]);
            }
            #pragma unroll
            for (int ni = 0; ni < 4; ni++) {
                const int n = wn * 32 + ni * 8 + g;
                uint32_t b[2];
                b[0] = f2tf(Bs[k * SBW + n]);
                b[1] = f2tf(Bs[(k + 4) * SBW + n]);
                #pragma unroll
                for (int mi = 0; mi < 4; mi++) mma8(acc[mi][ni], a[mi], b);
            }
        }
        __syncthreads();
    }

    // epilogue: bias + store
    #pragma unroll
    for (int mi = 0; mi < 4; mi++) {
        const int r0 = bm + wm * 64 + mi * 16 + g;
        #pragma unroll
        for (int ni = 0; ni < 4; ni++) {
            const int col = bn + wn * 32 + ni * 8 + 2 * tig;
            const float b0 = bias[col], b1 = bias[col + 1];
            float2 v0 = make_float2(acc[mi][ni][0] + b0, acc[mi][ni][1] + b1);
            float2 v1 = make_float2(acc[mi][ni][2] + b0, acc[mi][ni][3] + b1);
            *(float2*)&C[(size_t)r0 * N + col]       = v0;
            *(float2*)&C[(size_t)(r0 + 8) * N + col] = v1;
        }
    }
}

// ---------------------------------------------------------------------------
// TF32 MMA causal flash attention.
// grid = (SEQ/64, HEADS, BATCH), 128 threads = 4 warps, warp = 16 q rows.
// smem: Qs[64][68] | Ks[64][72] | Vs[64][72] | Ps[64][68]  (tf32-bit floats)
// ---------------------------------------------------------------------------
#define SQW 68
#define SKW 72
#define ATTN_SMEM ((64 * SQW + 64 * SKW + 64 * SKW + 64 * SQW) * (int)sizeof(float))

__global__ __launch_bounds__(128)
void attn_mma_kernel() {
    extern __shared__ float sm[];
    float* Qs = sm;
    float* Ks = Qs + 64 * SQW;
    float* Vs = Ks + 64 * SKW;
    float* Ps = Vs + 64 * SKW;

    const int qt   = blockIdx.x;
    const int h    = blockIdx.y;
    const int b    = blockIdx.z;
    const int tid  = threadIdx.x;
    const int lane = tid & 31;
    const int wid  = tid >> 5;
    const int g    = lane >> 2;
    const int tig  = lane & 3;

    // ---- load + convert Q tile (scaled by 1/sqrt(64)) ----
    {
        const size_t qb = ((size_t)(b * SEQ + qt * 64)) * (3 * DIM) + h * HD;
        #pragma unroll
        for (int i = 0; i < 8; i++) {
            int t = tid + i * 128;          // 0..1023
            int row = t >> 4, c4 = (t & 15) * 4;
            float4 v = *(const float4*)&g_qkv[qb + (size_t)row * 3 * DIM + c4];
            Qs[row * SQW + c4 + 0] = f2tf_f(v.x * 0.125f);
            Qs[row * SQW + c4 + 1] = f2tf_f(v.y * 0.125f);
            Qs[row * SQW + c4 + 2] = f2tf_f(v.z * 0.125f);
            Qs[row * SQW + c4 + 3] = f2tf_f(v.w * 0.125f);
        }
    }
    __syncthreads();

    // ---- Q fragments held in registers across the whole KV loop ----
    uint32_t qf[8][4];
    const int qrow = wid * 16 + g;
    #pragma unroll
    for (int ks = 0; ks < 8; ks++) {
        const int k = ks * 8 + tig;
        qf[ks][0] = __float_as_uint(Qs[qrow * SQW + k]);
        qf[ks][1] = __float_as_uint(Qs[(qrow + 8) * SQW + k]);
        qf[ks][2] = __float_as_uint(Qs[qrow * SQW + k + 4]);
        qf[ks][3] = __float_as_uint(Qs[(qrow + 8) * SQW + k + 4]);
    }

    float oacc[8][4];
    #pragma unroll
    for (int ni = 0; ni < 8; ni++)
        #pragma unroll
        for (int j = 0; j < 4; j++) oacc[ni][j] = 0.f;
    float m0 = -1e30f, m1 = -1e30f, l0 = 0.f, l1 = 0.f;

    for (int kt = 0; kt <= qt; kt++) {
        // ---- load + convert K,V tiles ----
        {
            const size_t kb = ((size_t)(b * SEQ + kt * 64)) * (3 * DIM) + DIM + h * HD;
            #pragma unroll
            for (int i = 0; i < 8; i++) {
                int t = tid + i * 128;
                int row = t >> 4, c4 = (t & 15) * 4;
                const size_t src = kb + (size_t)row * 3 * DIM + c4;
                float4 kv = *(const float4*)&g_qkv[src];
                float4 vv = *(const float4*)&g_qkv[src + DIM];
                Ks[row * SKW + c4 + 0] = f2tf_f(kv.x);
                Ks[row * SKW + c4 + 1] = f2tf_f(kv.y);
                Ks[row * SKW + c4 + 2] = f2tf_f(kv.z);
                Ks[row * SKW + c4 + 3] = f2tf_f(kv.w);
                Vs[row * SKW + c4 + 0] = f2tf_f(vv.x);
                Vs[row * SKW + c4 + 1] = f2tf_f(vv.y);
                Vs[row * SKW + c4 + 2] = f2tf_f(vv.z);
                Vs[row * SKW + c4 + 3] = f2tf_f(vv.w);
            }
        }
        __syncthreads();

        // ---- S = Q @ K^T ----
        float sacc[8][4];
        #pragma unroll
        for (int ni = 0; ni < 8; ni++)
            #pragma unroll
            for (int j = 0; j < 4; j++) sacc[ni][j] = 0.f;

        #pragma unroll
        for (int ks = 0; ks < 8; ks++) {
            const int k = ks * 8 + tig;
            #pragma unroll
            for (int ni = 0; ni < 8; ni++) {
                const int n = ni * 8 + g;
                uint32_t bfr[2];
                bfr[0] = __float_as_uint(Ks[n * SKW + k]);
                bfr[1] = __float_as_uint(Ks[n * SKW + k + 4]);
                mma8(sacc[ni], qf[ks], bfr);
            }
        }

        // ---- causal mask on diagonal tile ----
        if (kt == qt) {
            const int r0 = qt * 64 + wid * 16 + g;
            const int r1 = r0 + 8;
            #pragma unroll
            for (int ni = 0; ni < 8; ni++) {
                const int c0 = kt * 64 + ni * 8 + 2 * tig;
                if (c0 > r0)     sacc[ni][0] = -1e30f;
                if (c0 + 1 > r0) sacc[ni][1] = -1e30f;
                if (c0 > r1)     sacc[ni][2] = -1e30f;
                if (c0 + 1 > r1) sacc[ni][3] = -1e30f;
            }
        }

        // ---- row max (quad shuffle reduce) ----
        float t0 = -1e30f, t1 = -1e30f;
        #pragma unroll
        for (int ni = 0; ni < 8; ni++) {
            t0 = fmaxf(t0, fmaxf(sacc[ni][0], sacc[ni][1]));
            t1 = fmaxf(t1, fmaxf(sacc[ni][2], sacc[ni][3]));
        }
        t0 = fmaxf(t0, __shfl_xor_sync(0xffffffffu, t0, 1));
        t0 = fmaxf(t0, __shfl_xor_sync(0xffffffffu, t0, 2));
        t1 = fmaxf(t1, __shfl_xor_sync(0xffffffffu, t1, 1));
        t1 = fmaxf(t1, __shfl_xor_sync(0xffffffffu, t1, 2));

        const float nm0 = fmaxf(m0, t0), nm1 = fmaxf(m1, t1);
        const float cr0 = __expf(m0 - nm0), cr1 = __expf(m1 - nm1);
        l0 *= cr0; l1 *= cr1;
        #pragma unroll
        for (int ni = 0; ni < 8; ni++) {
            oacc[ni][0] *= cr0; oacc[ni][1] *= cr0;
            oacc[ni][2] *= cr1; oacc[ni][3] *= cr1;
        }

        // ---- P = exp(S - m), row sums ----
        float s0 = 0.f, s1 = 0.f;
        #pragma unroll
        for (int ni = 0; ni < 8; ni++) {
            float p0 = __expf(sacc[ni][0] - nm0);
            float p1 = __expf(sacc[ni][1] - nm0);
            float p2 = __expf(sacc[ni][2] - nm1);
            float p3 = __expf(sacc[ni][3] - nm1);
            sacc[ni][0] = p0; sacc[ni][1] = p1; sacc[ni][2] = p2; sacc[ni][3] = p3;
            s0 += p0 + p1; s1 += p2 + p3;
        }
        s0 += __shfl_xor_sync(0xffffffffu, s0, 1);
        s0 += __shfl_xor_sync(0xffffffffu, s0, 2);
        s1 += __shfl_xor_sync(0xffffffffu, s1, 1);
        s1 += __shfl_xor_sync(0xffffffffu, s1, 2);
        l0 += s0; l1 += s1;

        // ---- store P (tf32) to smem for re-fragmenting ----
        {
            const int pr = wid * 16 + g;
            #pragma unroll
            for (int ni = 0; ni < 8; ni++) {
                const int c = ni * 8 + 2 * tig;
                Ps[pr * SQW + c]           = f2tf_f(sacc[ni][0]);
                Ps[pr * SQW + c + 1]       = f2tf_f(sacc[ni][1]);
                Ps[(pr + 8) * SQW + c]     = f2tf_f(sacc[ni][2]);
                Ps[(pr + 8) * SQW + c + 1] = f2tf_f(sacc[ni][3]);
            }
        }
        __syncwarp();

        // ---- O += P @ V ----
        #pragma unroll
        for (int ks = 0; ks < 8; ks++) {
            const int k = ks * 8 + tig;
            uint32_t a[4];
            a[0] = __float_as_uint(Ps[qrow * SQW + k]);
            a[1] = __float_as_uint(Ps[(qrow + 8) * SQW + k]);
            a[2] = __float_as_uint(Ps[qrow * SQW + k + 4]);
            a[3] = __float_as_uint(Ps[(qrow + 8) * SQW + k + 4]);
            #pragma unroll
            for (int ni = 0; ni < 8; ni++) {
                const int n = ni * 8 + g;
                uint32_t bfr[2];
                bfr[0] = __float_as_uint(Vs[k * SKW + n]);
                bfr[1] = __float_as_uint(Vs[(k + 4) * SKW + n]);
                mma8(oacc[ni], a, bfr);
            }
        }
        m0 = nm0; m1 = nm1;
        __syncthreads();
    }

    // ---- epilogue ----
    const float inv0 = 1.f / l0, inv1 = 1.f / l1;
    const size_t ob = ((size_t)(b * SEQ + qt * 64)) * DIM + h * HD;
    const int r0 = wid * 16 + g;
    #pragma unroll
    for (int ni = 0; ni < 8; ni++) {
        const int c = ni * 8 + 2 * tig;
        float2 v0 = make_float2(oacc[ni][0] * inv0, oacc[ni][1] * inv0);
        float2 v1 = make_float2(oacc[ni][2] * inv1, oacc[ni][3] * inv1);
        *(float2*)&g_att[ob + (size_t)r0 * DIM + c]       = v0;
        *(float2*)&g_att[ob + (size_t)(r0 + 8) * DIM + c] = v1;
    }
}

// ---------------------------------------------------------------------------
extern "C" void kernel_launch(void* const* d_in, const int* in_sizes, int n_in,
                              void* d_out, int out_size) {
    const float* x     = (const float*)d_in[0];
    const float* w_qkv = (const float*)d_in[1];
    const float* b_qkv = (const float*)d_in[2];
    const float* w_out = (const float*)d_in[3];
    const float* b_out = (const float*)d_in[4];
    float* out = (float*)d_out;

    float* qkv; cudaGetSymbolAddress((void**)&qkv, g_qkv);
    float* att; cudaGetSymbolAddress((void**)&att, g_att);

    cudaFuncSetAttribute(tf32_gemm_kernel<3 * DIM>,
                         cudaFuncAttributeMaxDynamicSharedMemorySize, GEMM_SMEM);
    cudaFuncSetAttribute(tf32_gemm_kernel<DIM>,
                         cudaFuncAttributeMaxDynamicSharedMemorySize, GEMM_SMEM);
    cudaFuncSetAttribute(attn_mma_kernel,
                         cudaFuncAttributeMaxDynamicSharedMemorySize, ATTN_SMEM);

    // 1) QKV projection: [8192,1024] @ [1024,3072] + b
    {
        dim3 grid(3 * DIM / 128, ROWS / 128);
        tf32_gemm_kernel<3 * DIM><<<grid, 256, GEMM_SMEM>>>(x, w_qkv, b_qkv, qkv);
    }
    // 2) causal multi-head attention (tf32 mma flash)
    {
        dim3 grid(SEQ / 64, HEADS, BATCH);
        attn_mma_kernel<<<grid, 128, ATTN_SMEM>>>();
    }
    // 3) output projection: [8192,1024] @ [1024,1024] + b
    {
        dim3 grid(DIM / 128, ROWS / 128);
        tf32_gemm_kernel<DIM><<<grid, 256, GEMM_SMEM>>>(att, w_out, b_out, out);
    }
}

// round 4
// speedup vs baseline: 4.2139x; 1.0793x over previous
#include <cuda_runtime.h>
#include <cstdint>

#define BATCH 4
#define SEQ   2048
#define DIM   1024
#define HEADS 16
#define HD    64
#define ROWS (BATCH * SEQ)        // 8192

// Scratch (allocation-free rule: device globals)
__device__ float g_qkv[(size_t)ROWS * 3 * DIM];   // qkv output, permuted cols
__device__ float g_att[(size_t)ROWS * DIM];       // attention out, permuted cols
__device__ float g_xa[(size_t)ROWS * DIM];        // x, tf32-rounded, permuted cols
__device__ float g_wqkvT[(size_t)(3 * DIM) * DIM];// w_qkv^T [3072][1024], both dims permuted
__device__ float g_woutT[(size_t)DIM * DIM];      // w_out^T [1024][1024], k permuted
__device__ float g_bqkvp[3 * DIM];                // permuted bias

// ---------------------------------------------------------------------------
// helpers
// ---------------------------------------------------------------------------
__device__ __forceinline__ uint32_t f2tf(float x) {
    uint32_t r;
    asm("cvt.rna.tf32.f32 %0, %1;" : "=r"(r) : "f"(x));
    return r;
}
__device__ __forceinline__ float f2tf_f(float x) { return __uint_as_float(f2tf(x)); }

// slot s of a within-8 interleaved array holds true index d(s):
__device__ __forceinline__ int dloc(int s) {
    return (s & ~7) | ((s & 1) << 2) | ((s >> 1) & 3);
}

__device__ __forceinline__ void mma8(float* c, const uint32_t* a, const uint32_t* b) {
    asm volatile(
        "mma.sync.aligned.m16n8k8.row.col.f32.tf32.tf32.f32 "
        "{%0,%1,%2,%3}, {%4,%5,%6,%7}, {%8,%9}, {%0,%1,%2,%3};"
        : "+f"(c[0]), "+f"(c[1]), "+f"(c[2]), "+f"(c[3])
        : "r"(a[0]), "r"(a[1]), "r"(a[2]), "r"(a[3]), "r"(b[0]), "r"(b[1]));
}

__device__ __forceinline__ uint32_t sptr(const void* p) {
    return (uint32_t)__cvta_generic_to_shared(p);
}
__device__ __forceinline__ void cp16(uint32_t s, const void* g) {
    asm volatile("cp.async.ca.shared.global [%0], [%1], 16;" :: "r"(s), "l"(g));
}
#define CP_COMMIT() asm volatile("cp.async.commit_group;")
#define CP_WAIT0()  asm volatile("cp.async.wait_group 0;")
#define CP_WAIT1()  asm volatile("cp.async.wait_group 1;")

// ---------------------------------------------------------------------------
// Pre-pass kernels
// ---------------------------------------------------------------------------
// x -> g_xa : tf32 round + within-8 column interleave. one thread = 8 cols.
__global__ __launch_bounds__(256)
void prep_x_kernel(const float* __restrict__ x) {
    const size_t grp = (size_t)blockIdx.x * 256 + threadIdx.x;
    const size_t base = grp * 8;
    float4 v0 = *(const float4*)&x[base];
    float4 v1 = *(const float4*)&x[base + 4];
    float4 o0, o1;
    o0.x = f2tf_f(v0.x); o0.y = f2tf_f(v1.x); o0.z = f2tf_f(v0.y); o0.w = f2tf_f(v1.y);
    o1.x = f2tf_f(v0.z); o1.y = f2tf_f(v1.z); o1.z = f2tf_f(v0.w); o1.w = f2tf_f(v1.w);
    *(float4*)&g_xa[base]     = o0;
    *(float4*)&g_xa[base + 4] = o1;
}

// w[1024][N] -> wT[N][1024]: dst[ns][ks] = round(src[dloc(ks)][PERMN? dloc(ns): ns])
template<bool PERMN>
__global__ __launch_bounds__(256)
void prep_wT_kernel(const float* __restrict__ src, float* __restrict__ dst, int N) {
    __shared__ float tile[32][33];
    const int tx = threadIdx.x, ty = threadIdx.y;
    const int kb = blockIdx.x * 32;
    const int nb = blockIdx.y * 32;
    #pragma unroll
    for (int i = 0; i < 4; i++)
        tile[ty + i * 8][tx] = src[(size_t)(kb + ty + i * 8) * N + nb + tx];
    __syncthreads();
    #pragma unroll
    for (int i = 0; i < 4; i++) {
        const int ny = ty + i * 8;
        const int nsrc = PERMN ? dloc(ny) : ny;
        dst[(size_t)(nb + ny) * DIM + kb + tx] = f2tf_f(tile[dloc(tx)][nsrc]);
    }
}

__global__ void prep_bias_kernel(const float* __restrict__ b) {
    const int s = blockIdx.x * 256 + threadIdx.x;
    if (s < 3 * DIM) g_bqkvp[s] = b[dloc(s)];
}

// ---------------------------------------------------------------------------
// TF32 MMA GEMM v2: C[M][n-space] = A[M][1024] @ B^T + bias
// A: [M][1024] permuted k cols. B: [N][1024] transposed weight, permuted k.
// block 128x128, BK=32, 256 thr (8 warps 2x4), warp 64x32. double buffered.
// smem rows padded to 40 floats -> conflict-free LDS.64 fragment loads.
// ---------------------------------------------------------------------------
#define GSAW 40
#define GTILE (128 * GSAW)                 // floats per operand tile
#define GSTG  (2 * GTILE)                  // floats per stage
#define GEMM_SMEM (2 * GSTG * (int)sizeof(float))   // 81920 B

__device__ __forceinline__ void gemm_load(float* stage,
                                          const float* __restrict__ A,
                                          const float* __restrict__ B,
                                          int bm, int bn, int k0, int tid) {
    #pragma unroll
    for (int i = 0; i < 4; i++) {
        int t = tid + i * 256;
        int row = t >> 3, c4 = (t & 7) * 4;
        cp16(sptr(stage + row * GSAW + c4), A + (size_t)(bm + row) * DIM + k0 + c4);
        cp16(sptr(stage + GTILE + row * GSAW + c4), B + (size_t)(bn + row) * DIM + k0 + c4);
    }
}

template<bool ROUND>
__global__ __launch_bounds__(256)
void tf32_gemm_v2(const float* __restrict__ A, const float* __restrict__ B,
                  const float* __restrict__ bias, float* __restrict__ C, int N) {
    extern __shared__ float sm[];
    const int tid  = threadIdx.x;
    const int lane = tid & 31;
    const int wid  = tid >> 5;
    const int g    = lane >> 2;
    const int tig  = lane & 3;
    const int wm   = wid >> 2;         // 0..1
    const int wn   = wid & 3;          // 0..3
    const int bm   = blockIdx.y * 128;
    const int bn   = blockIdx.x * 128;

    float acc[4][4][4];
    #pragma unroll
    for (int mi = 0; mi < 4; mi++)
        #pragma unroll
        for (int ni = 0; ni < 4; ni++)
            #pragma unroll
            for (int j = 0; j < 4; j++) acc[mi][ni][j] = 0.f;

    constexpr int NT = DIM / 32;

    gemm_load(sm, A, B, bm, bn, 0, tid);
    CP_COMMIT();

    for (int t = 0; t < NT; t++) {
        if (t + 1 < NT) {
            gemm_load(sm + ((t + 1) & 1) * GSTG, A, B, bm, bn, (t + 1) * 32, tid);
            CP_COMMIT();
            CP_WAIT1();
        } else {
            CP_WAIT0();
        }
        __syncthreads();
        const float* As = sm + (t & 1) * GSTG;
        const float* Bs = As + GTILE;

        #pragma unroll
        for (int ks = 0; ks < 4; ks++) {
            const int k2 = ks * 8 + 2 * tig;
            uint32_t a[4][4], b[4][2];
            #pragma unroll
            for (int mi = 0; mi < 4; mi++) {
                const int m = wm * 64 + mi * 16 + g;
                float2 lo = *(const float2*)&As[m * GSAW + k2];
                float2 hi = *(const float2*)&As[(m + 8) * GSAW + k2];
                a[mi][0] = __float_as_uint(lo.x);
                a[mi][1] = __float_as_uint(hi.x);
                a[mi][2] = __float_as_uint(lo.y);
                a[mi][3] = __float_as_uint(hi.y);
            }
            #pragma unroll
            for (int ni = 0; ni < 4; ni++) {
                const int n = wn * 32 + ni * 8 + g;
                float2 bb = *(const float2*)&Bs[n * GSAW + k2];
                b[ni][0] = __float_as_uint(bb.x);
                b[ni][1] = __float_as_uint(bb.y);
            }
            #pragma unroll
            for (int mi = 0; mi < 4; mi++)
                #pragma unroll
                for (int ni = 0; ni < 4; ni++)
                    mma8(acc[mi][ni], a[mi], b[ni]);
        }
        __syncthreads();
    }

    #pragma unroll
    for (int mi = 0; mi < 4; mi++) {
        const int r0 = bm + wm * 64 + mi * 16 + g;
        #pragma unroll
        for (int ni = 0; ni < 4; ni++) {
            const int col = bn + wn * 32 + ni * 8 + 2 * tig;
            const float b0 = bias[col], b1 = bias[col + 1];
            float v00 = acc[mi][ni][0] + b0, v01 = acc[mi][ni][1] + b1;
            float v10 = acc[mi][ni][2] + b0, v11 = acc[mi][ni][3] + b1;
            if (ROUND) { v00 = f2tf_f(v00); v01 = f2tf_f(v01);
                         v10 = f2tf_f(v10); v11 = f2tf_f(v11); }
            *(float2*)&C[(size_t)r0 * N + col]       = make_float2(v00, v01);
            *(float2*)&C[(size_t)(r0 + 8) * N + col] = make_float2(v10, v11);
        }
    }
}

// ---------------------------------------------------------------------------
// TF32 MMA causal flash attention v2.
// grid = (SEQ/64, HEADS, BATCH), 128 thr = 4 warps, warp = 16 q rows.
// K/V cp.async double-buffered. All inputs pre-rounded (tf32) + d-permuted.
// smem: K[2][64][72] | V[2][64][72] | P[64][72]
// ---------------------------------------------------------------------------
#define AKW 72
#define KST (64 * AKW)
#define ATTN_SMEM ((4 * KST + KST) * (int)sizeof(float))   // 92160 B

__device__ __forceinline__ void attn_load_kv(float* Ks, float* Vs,
                                             int b, int h, int kt, int tid) {
    const size_t base = ((size_t)(b * SEQ + kt * 64)) * (3 * DIM) + DIM + h * HD;
    #pragma unroll
    for (int i = 0; i < 8; i++) {
        int t = tid + i * 128;
        int row = t >> 4, c4 = (t & 15) * 4;
        const float* src = &g_qkv[base + (size_t)row * 3 * DIM + c4];
        cp16(sptr(Ks + row * AKW + c4), src);
        cp16(sptr(Vs + row * AKW + c4), src + DIM);
    }
}

__global__ __launch_bounds__(128)
void attn_mma_v2() {
    extern __shared__ float sm[];
    float* Kb[2] = { sm, sm + KST };
    float* Vb[2] = { sm + 2 * KST, sm + 3 * KST };
    float* Ps = sm + 4 * KST;

    const int qt   = blockIdx.x;
    const int h    = blockIdx.y;
    const int b    = blockIdx.z;
    const int tid  = threadIdx.x;
    const int lane = tid & 31;
    const int wid  = tid >> 5;
    const int g    = lane >> 2;
    const int tig  = lane & 3;
    const int k2   = 2 * tig;
    const int se   = ((tig & 1) << 2) | (tig >> 1);   // P slot for true col 2*tig

    attn_load_kv(Kb[0], Vb[0], b, h, 0, tid);
    CP_COMMIT();

    // Q fragments straight from gmem (permuted cols -> paired float2 loads)
    uint32_t qf[8][4];
    {
        const size_t r0 = ((size_t)(b * SEQ + qt * 64 + wid * 16 + g)) * (3 * DIM) + h * HD;
        #pragma unroll
        for (int ks = 0; ks < 8; ks++) {
            float2 lo = *(const float2*)&g_qkv[r0 + ks * 8 + k2];
            float2 hi = *(const float2*)&g_qkv[r0 + 8 * 3 * DIM + ks * 8 + k2];
            qf[ks][0] = __float_as_uint(lo.x * 0.125f);
            qf[ks][1] = __float_as_uint(hi.x * 0.125f);
            qf[ks][2] = __float_as_uint(lo.y * 0.125f);
            qf[ks][3] = __float_as_uint(hi.y * 0.125f);
        }
    }

    float oacc[8][4];
    #pragma unroll
    for (int ni = 0; ni < 8; ni++)
        #pragma unroll
        for (int j = 0; j < 4; j++) oacc[ni][j] = 0.f;
    float m0 = -1e30f, m1 = -1e30f, l0 = 0.f, l1 = 0.f;

    const int prow = wid * 16 + g;

    for (int kt = 0; kt <= qt; kt++) {
        if (kt < qt) {
            attn_load_kv(Kb[(kt + 1) & 1], Vb[(kt + 1) & 1], b, h, kt + 1, tid);
            CP_COMMIT();
            CP_WAIT1();
        } else {
            CP_WAIT0();
        }
        __syncthreads();
        const float* Ks = Kb[kt & 1];
        const float* Vs = Vb[kt & 1];

        // ---- S = Q @ K^T ----
        float sacc[8][4];
        #pragma unroll
        for (int ni = 0; ni < 8; ni++)
            #pragma unroll
            for (int j = 0; j < 4; j++) sacc[ni][j] = 0.f;

        #pragma unroll
        for (int ks = 0; ks < 8; ks++) {
            #pragma unroll
            for (int ni = 0; ni < 8; ni++) {
                float2 bb = *(const float2*)&Ks[(ni * 8 + g) * AKW + ks * 8 + k2];
                uint32_t bfr[2] = { __float_as_uint(bb.x), __float_as_uint(bb.y) };
                mma8(sacc[ni], qf[ks], bfr);
            }
        }

        // ---- causal mask on diagonal tile ----
        if (kt == qt) {
            const int r0 = qt * 64 + prow, r1 = r0 + 8;
            #pragma unroll
            for (int ni = 0; ni < 8; ni++) {
                const int c0 = kt * 64 + ni * 8 + k2;
                if (c0 > r0)     sacc[ni][0] = -1e30f;
                if (c0 + 1 > r0) sacc[ni][1] = -1e30f;
                if (c0 > r1)     sacc[ni][2] = -1e30f;
                if (c0 + 1 > r1) sacc[ni][3] = -1e30f;
            }
        }

        // ---- row max ----
        float t0 = -1e30f, t1 = -1e30f;
        #pragma unroll
        for (int ni = 0; ni < 8; ni++) {
            t0 = fmaxf(t0, fmaxf(sacc[ni][0], sacc[ni][1]));
            t1 = fmaxf(t1, fmaxf(sacc[ni][2], sacc[ni][3]));
        }
        t0 = fmaxf(t0, __shfl_xor_sync(0xffffffffu, t0, 1));
        t0 = fmaxf(t0, __shfl_xor_sync(0xffffffffu, t0, 2));
        t1 = fmaxf(t1, __shfl_xor_sync(0xffffffffu, t1, 1));
        t1 = fmaxf(t1, __shfl_xor_sync(0xffffffffu, t1, 2));

        const float nm0 = fmaxf(m0, t0), nm1 = fmaxf(m1, t1);
        const float cr0 = __expf(m0 - nm0), cr1 = __expf(m1 - nm1);
        l0 *= cr0; l1 *= cr1;
        #pragma unroll
        for (int ni = 0; ni < 8; ni++) {
            oacc[ni][0] *= cr0; oacc[ni][1] *= cr0;
            oacc[ni][2] *= cr1; oacc[ni][3] *= cr1;
        }

        // ---- P = exp(S-m), sums; store P into permuted slots ----
        float s0 = 0.f, s1 = 0.f;
        #pragma unroll
        for (int ni = 0; ni < 8; ni++) {
            float p0 = __expf(sacc[ni][0] - nm0);
            float p1 = __expf(sacc[ni][1] - nm0);
            float p2 = __expf(sacc[ni][2] - nm1);
            float p3 = __expf(sacc[ni][3] - nm1);
            s0 += p0 + p1; s1 += p2 + p3;
            const int c0 = ni * 8 + se;
            Ps[prow * AKW + c0]           = f2tf_f(p0);
            Ps[prow * AKW + c0 + 2]       = f2tf_f(p1);
            Ps[(prow + 8) * AKW + c0]     = f2tf_f(p2);
            Ps[(prow + 8) * AKW + c0 + 2] = f2tf_f(p3);
        }
        s0 += __shfl_xor_sync(0xffffffffu, s0, 1);
        s0 += __shfl_xor_sync(0xffffffffu, s0, 2);
        s1 += __shfl_xor_sync(0xffffffffu, s1, 1);
        s1 += __shfl_xor_sync(0xffffffffu, s1, 2);
        l0 += s0; l1 += s1;
        __syncwarp();

        // ---- O += P @ V ----
        #pragma unroll
        for (int ks = 0; ks < 8; ks++) {
            float2 lo = *(const float2*)&Ps[prow * AKW + ks * 8 + k2];
            float2 hi = *(const float2*)&Ps[(prow + 8) * AKW + ks * 8 + k2];
            uint32_t a[4] = { __float_as_uint(lo.x), __float_as_uint(hi.x),
                              __float_as_uint(lo.y), __float_as_uint(hi.y) };
            #pragma unroll
            for (int ni = 0; ni < 8; ni++) {
                const int n = ni * 8 + g;
                uint32_t bfr[2];
                bfr[0] = __float_as_uint(Vs[(ks * 8 + tig) * AKW + n]);
                bfr[1] = __float_as_uint(Vs[(ks * 8 + tig + 4) * AKW + n]);
                mma8(oacc[ni], a, bfr);
            }
        }
        m0 = nm0; m1 = nm1;
        __syncthreads();
    }

    // ---- epilogue (round: feeds out-proj A side) ----
    const float inv0 = 1.f / l0, inv1 = 1.f / l1;
    const size_t ob = ((size_t)(b * SEQ + qt * 64 + prow)) * DIM + h * HD;
    #pragma unroll
    for (int ni = 0; ni < 8; ni++) {
        const int c = ni * 8 + k2;
        float2 v0 = make_float2(f2tf_f(oacc[ni][0] * inv0), f2tf_f(oacc[ni][1] * inv0));
        float2 v1 = make_float2(f2tf_f(oacc[ni][2] * inv1), f2tf_f(oacc[ni][3] * inv1));
        *(float2*)&g_att[ob + c]                        = v0;
        *(float2*)&g_att[ob + (size_t)8 * DIM + c]      = v1;
    }
}

// ---------------------------------------------------------------------------
extern "C" void kernel_launch(void* const* d_in, const int* in_sizes, int n_in,
                              void* d_out, int out_size) {
    const float* x     = (const float*)d_in[0];
    const float* w_qkv = (const float*)d_in[1];
    const float* b_qkv = (const float*)d_in[2];
    const float* w_out = (const float*)d_in[3];
    const float* b_out = (const float*)d_in[4];
    float* out = (float*)d_out;

    float* qkv;  cudaGetSymbolAddress((void**)&qkv,  g_qkv);
    float* att;  cudaGetSymbolAddress((void**)&att,  g_att);
    float* xa;   cudaGetSymbolAddress((void**)&xa,   g_xa);
    float* wqT;  cudaGetSymbolAddress((void**)&wqT,  g_wqkvT);
    float* woT;  cudaGetSymbolAddress((void**)&woT,  g_woutT);
    float* bqp;  cudaGetSymbolAddress((void**)&bqp,  g_bqkvp);

    cudaFuncSetAttribute(tf32_gemm_v2<true>,
                         cudaFuncAttributeMaxDynamicSharedMemorySize, GEMM_SMEM);
    cudaFuncSetAttribute(tf32_gemm_v2<false>,
                         cudaFuncAttributeMaxDynamicSharedMemorySize, GEMM_SMEM);
    cudaFuncSetAttribute(attn_mma_v2,
                         cudaFuncAttributeMaxDynamicSharedMemorySize, ATTN_SMEM);

    // --- pre-pass: round + permute + transpose ---
    prep_x_kernel<<<(ROWS * DIM / 8) / 256, 256>>>(x);
    prep_wT_kernel<true><<<dim3(DIM / 32, 3 * DIM / 32), dim3(32, 8)>>>(w_qkv, wqT, 3 * DIM);
    prep_wT_kernel<false><<<dim3(DIM / 32, DIM / 32), dim3(32, 8)>>>(w_out, woT, DIM);
    prep_bias_kernel<<<(3 * DIM + 255) / 256, 256>>>(b_qkv);

    // 1) QKV projection
    {
        dim3 grid(3 * DIM / 128, ROWS / 128);
        tf32_gemm_v2<true><<<grid, 256, GEMM_SMEM>>>(xa, wqT, bqp, qkv, 3 * DIM);
    }
    // 2) causal multi-head attention
    {
        dim3 grid(SEQ / 64, HEADS, BATCH);
        attn_mma_v2<<<grid, 128, ATTN_SMEM>>>();
    }
    // 3) output projection
    {
        dim3 grid(DIM / 128, ROWS / 128);
        tf32_gemm_v2<false><<<grid, 256, GEMM_SMEM>>>(att, woT, b_out, out, DIM);
    }
}

// round 6
// speedup vs baseline: 4.2502x; 1.0086x over previous
#include <cuda_runtime.h>
#include <cstdint>

#define BATCH 4
#define SEQ   2048
#define DIM   1024
#define HEADS 16
#define HD    64
#define ROWS (BATCH * SEQ)        // 8192

// Scratch (allocation-free rule: device globals)
__device__ float g_qkv[(size_t)ROWS * 3 * DIM];   // qkv output, permuted cols
__device__ float g_att[(size_t)ROWS * DIM];       // attention out, permuted cols
__device__ float g_xa[(size_t)ROWS * DIM];        // x, tf32-rounded, permuted cols
__device__ float g_wqkvT[(size_t)(3 * DIM) * DIM];// w_qkv^T [3072][1024]
__device__ float g_woutT[(size_t)DIM * DIM];      // w_out^T [1024][1024]
__device__ float g_bqkvp[3 * DIM];                // permuted bias

// ---------------------------------------------------------------------------
// helpers
// ---------------------------------------------------------------------------
__device__ __forceinline__ uint32_t f2tf(float x) {
    uint32_t r;
    asm("cvt.rna.tf32.f32 %0, %1;" : "=r"(r) : "f"(x));
    return r;
}
__device__ __forceinline__ float f2tf_f(float x) { return __uint_as_float(f2tf(x)); }

// slot s of a within-8 interleaved array holds true index d(s):
__device__ __forceinline__ int dloc(int s) {
    return (s & ~7) | ((s & 1) << 2) | ((s >> 1) & 3);
}

__device__ __forceinline__ void mma8(float* c, const uint32_t* a, const uint32_t* b) {
    asm volatile(
        "mma.sync.aligned.m16n8k8.row.col.f32.tf32.tf32.f32 "
        "{%0,%1,%2,%3}, {%4,%5,%6,%7}, {%8,%9}, {%0,%1,%2,%3};"
        : "+f"(c[0]), "+f"(c[1]), "+f"(c[2]), "+f"(c[3])
        : "r"(a[0]), "r"(a[1]), "r"(a[2]), "r"(a[3]), "r"(b[0]), "r"(b[1]));
}

__device__ __forceinline__ uint32_t sptr(const void* p) {
    return (uint32_t)__cvta_generic_to_shared(p);
}
__device__ __forceinline__ void cp16(uint32_t s, const void* g) {
    asm volatile("cp.async.ca.shared.global [%0], [%1], 16;" :: "r"(s), "l"(g));
}
#define CP_COMMIT() asm volatile("cp.async.commit_group;")
#define CP_WAIT0()  asm volatile("cp.async.wait_group 0;")
#define CP_WAIT1()  asm volatile("cp.async.wait_group 1;")

// ---------------------------------------------------------------------------
// Pre-pass kernels
// ---------------------------------------------------------------------------
__global__ __launch_bounds__(256)
void prep_x_kernel(const float* __restrict__ x) {
    const size_t grp = (size_t)blockIdx.x * 256 + threadIdx.x;
    const size_t base = grp * 8;
    float4 v0 = *(const float4*)&x[base];
    float4 v1 = *(const float4*)&x[base + 4];
    float4 o0, o1;
    o0.x = f2tf_f(v0.x); o0.y = f2tf_f(v1.x); o0.z = f2tf_f(v0.y); o0.w = f2tf_f(v1.y);
    o1.x = f2tf_f(v0.z); o1.y = f2tf_f(v1.z); o1.z = f2tf_f(v0.w); o1.w = f2tf_f(v1.w);
    *(float4*)&g_xa[base]     = o0;
    *(float4*)&g_xa[base + 4] = o1;
}

template<bool PERMN>
__global__ __launch_bounds__(256)
void prep_wT_kernel(const float* __restrict__ src, float* __restrict__ dst, int N) {
    __shared__ float tile[32][33];
    const int tx = threadIdx.x, ty = threadIdx.y;
    const int kb = blockIdx.x * 32;
    const int nb = blockIdx.y * 32;
    #pragma unroll
    for (int i = 0; i < 4; i++)
        tile[ty + i * 8][tx] = src[(size_t)(kb + ty + i * 8) * N + nb + tx];
    __syncthreads();
    #pragma unroll
    for (int i = 0; i < 4; i++) {
        const int ny = ty + i * 8;
        const int nsrc = PERMN ? dloc(ny) : ny;
        dst[(size_t)(nb + ny) * DIM + kb + tx] = f2tf_f(tile[dloc(tx)][nsrc]);
    }
}

__global__ void prep_bias_kernel(const float* __restrict__ b) {
    const int s = blockIdx.x * 256 + threadIdx.x;
    if (s < 3 * DIM) g_bqkvp[s] = b[dloc(s)];
}

// ---------------------------------------------------------------------------
// TF32 MMA GEMM v3: C[M][N] = A[M][1024] @ B[N][1024]^T + bias
// Block tile 256x128, BK=32, 256 thr (8 warps 4x2), warp tile 64x64.
// Double buffered cp.async. smem rows padded to 40 floats.
// ---------------------------------------------------------------------------
#define GSAW 40
#define GA_SZ (256 * GSAW)                 // A tile floats
#define GB_SZ (128 * GSAW)                 // B tile floats
#define GSTG  (GA_SZ + GB_SZ)              // floats per stage
#define GEMM_SMEM (2 * GSTG * (int)sizeof(float))   // 122880 B

__device__ __forceinline__ void gemm_load(float* stage,
                                          const float* __restrict__ A,
                                          const float* __restrict__ B,
                                          int bm, int bn, int k0, int tid) {
    #pragma unroll
    for (int i = 0; i < 8; i++) {
        int t = tid + i * 256;            // 0..2047
        int row = t >> 3, c4 = (t & 7) * 4;
        cp16(sptr(stage + row * GSAW + c4), A + (size_t)(bm + row) * DIM + k0 + c4);
    }
    #pragma unroll
    for (int i = 0; i < 4; i++) {
        int t = tid + i * 256;            // 0..1023
        int row = t >> 3, c4 = (t & 7) * 4;
        cp16(sptr(stage + GA_SZ + row * GSAW + c4), B + (size_t)(bn + row) * DIM + k0 + c4);
    }
}

template<bool ROUND>
__global__ __launch_bounds__(256)
void tf32_gemm_v3(const float* __restrict__ A, const float* __restrict__ B,
                  const float* __restrict__ bias, float* __restrict__ C, int N) {
    extern __shared__ float sm[];
    const int tid  = threadIdx.x;
    const int lane = tid & 31;
    const int wid  = tid >> 5;
    const int g    = lane >> 2;
    const int tig  = lane & 3;
    const int k2   = 2 * tig;
    const int wm   = wid >> 1;         // 0..3 (64-row slabs)
    const int wn   = wid & 1;          // 0..1 (64-col slabs)
    const int bm   = blockIdx.y * 256;
    const int bn   = blockIdx.x * 128;

    float acc[4][8][4];
    #pragma unroll
    for (int mi = 0; mi < 4; mi++)
        #pragma unroll
        for (int ni = 0; ni < 8; ni++)
            #pragma unroll
            for (int j = 0; j < 4; j++) acc[mi][ni][j] = 0.f;

    constexpr int NT = DIM / 32;

    gemm_load(sm, A, B, bm, bn, 0, tid);
    CP_COMMIT();

    for (int t = 0; t < NT; t++) {
        if (t + 1 < NT) {
            gemm_load(sm + ((t + 1) & 1) * GSTG, A, B, bm, bn, (t + 1) * 32, tid);
            CP_COMMIT();
            CP_WAIT1();
        } else {
            CP_WAIT0();
        }
        __syncthreads();
        const float* As = sm + (t & 1) * GSTG;
        const float* Bs = As + GA_SZ;

        #pragma unroll
        for (int ks = 0; ks < 4; ks++) {
            const int kk = ks * 8 + k2;
            uint32_t a[4][4], b[8][2];
            #pragma unroll
            for (int mi = 0; mi < 4; mi++) {
                const int m = wm * 64 + mi * 16 + g;
                float2 lo = *(const float2*)&As[m * GSAW + kk];
                float2 hi = *(const float2*)&As[(m + 8) * GSAW + kk];
                a[mi][0] = __float_as_uint(lo.x);
                a[mi][1] = __float_as_uint(hi.x);
                a[mi][2] = __float_as_uint(lo.y);
                a[mi][3] = __float_as_uint(hi.y);
            }
            #pragma unroll
            for (int ni = 0; ni < 8; ni++) {
                const int n = wn * 64 + ni * 8 + g;
                float2 bb = *(const float2*)&Bs[n * GSAW + kk];
                b[ni][0] = __float_as_uint(bb.x);
                b[ni][1] = __float_as_uint(bb.y);
            }
            #pragma unroll
            for (int mi = 0; mi < 4; mi++)
                #pragma unroll
                for (int ni = 0; ni < 8; ni++)
                    mma8(acc[mi][ni], a[mi], b[ni]);
        }
        __syncthreads();
    }

    #pragma unroll
    for (int mi = 0; mi < 4; mi++) {
        const int r0 = bm + wm * 64 + mi * 16 + g;
        #pragma unroll
        for (int ni = 0; ni < 8; ni++) {
            const int col = bn + wn * 64 + ni * 8 + k2;
            const float b0 = bias[col], b1 = bias[col + 1];
            float v00 = acc[mi][ni][0] + b0, v01 = acc[mi][ni][1] + b1;
            float v10 = acc[mi][ni][2] + b0, v11 = acc[mi][ni][3] + b1;
            if (ROUND) { v00 = f2tf_f(v00); v01 = f2tf_f(v01);
                         v10 = f2tf_f(v10); v11 = f2tf_f(v11); }
            *(float2*)&C[(size_t)r0 * N + col]       = make_float2(v00, v01);
            *(float2*)&C[(size_t)(r0 + 8) * N + col] = make_float2(v10, v11);
        }
    }
}

// ---------------------------------------------------------------------------
// TF32 MMA causal flash attention v3.
// grid = (SEQ/256, HEADS, BATCH), 256 thr = 8 warps, warp = 32 q rows
// (two m16 subtiles). KV tile 64, cp.async double buffered.
// smem: K[2][64][72] | V[2][64][72] | P[256][72]
// ---------------------------------------------------------------------------
#define AQT 256
#define AKW 72
#define KST (64 * AKW)
#define ATTN_SMEM ((4 * KST + AQT * AKW) * (int)sizeof(float))   // 147456 B

__device__ __forceinline__ void attn_load_kv(float* Ks, float* Vs,
                                             int b, int h, int kt, int tid) {
    const size_t base = ((size_t)(b * SEQ + kt * 64)) * (3 * DIM) + DIM + h * HD;
    #pragma unroll
    for (int i = 0; i < 4; i++) {
        int t = tid + i * 256;
        int row = t >> 4, c4 = (t & 15) * 4;
        const float* src = &g_qkv[base + (size_t)row * 3 * DIM + c4];
        cp16(sptr(Ks + row * AKW + c4), src);
        cp16(sptr(Vs + row * AKW + c4), src + DIM);
    }
}

__global__ __launch_bounds__(256)
void attn_mma_v3() {
    extern __shared__ float sm[];
    float* Kb[2] = { sm, sm + KST };
    float* Vb[2] = { sm + 2 * KST, sm + 3 * KST };
    float* Ps = sm + 4 * KST;

    const int qt   = blockIdx.x;
    const int h    = blockIdx.y;
    const int b    = blockIdx.z;
    const int tid  = threadIdx.x;
    const int lane = tid & 31;
    const int wid  = tid >> 5;
    const int g    = lane >> 2;
    const int tig  = lane & 3;
    const int k2   = 2 * tig;
    const int se   = ((tig & 1) << 2) | (tig >> 1);   // P slot for true col 2*tig

    const int qr   = qt * AQT + wid * 32;   // warp's first absolute q row
    const int nkt  = qt * 4 + 4;

    attn_load_kv(Kb[0], Vb[0], b, h, 0, tid);
    CP_COMMIT();

    // Q fragments for both m16 subtiles, straight from gmem (permuted cols)
    uint32_t qf[2][8][4];
    #pragma unroll
    for (int s = 0; s < 2; s++) {
        const size_t r0 = ((size_t)(b * SEQ + qr + s * 16 + g)) * (3 * DIM) + h * HD;
        #pragma unroll
        for (int ks = 0; ks < 8; ks++) {
            float2 lo = *(const float2*)&g_qkv[r0 + ks * 8 + k2];
            float2 hi = *(const float2*)&g_qkv[r0 + 8 * 3 * DIM + ks * 8 + k2];
            qf[s][ks][0] = __float_as_uint(lo.x * 0.125f);
            qf[s][ks][1] = __float_as_uint(hi.x * 0.125f);
            qf[s][ks][2] = __float_as_uint(lo.y * 0.125f);
            qf[s][ks][3] = __float_as_uint(hi.y * 0.125f);
        }
    }

    float oacc[2][8][4];
    #pragma unroll
    for (int s = 0; s < 2; s++)
        #pragma unroll
        for (int ni = 0; ni < 8; ni++)
            #pragma unroll
            for (int j = 0; j < 4; j++) oacc[s][ni][j] = 0.f;
    float mm[2][2] = {{-1e30f, -1e30f}, {-1e30f, -1e30f}};
    float ll[2][2] = {{0.f, 0.f}, {0.f, 0.f}};

    for (int kt = 0; kt < nkt; kt++) {
        if (kt + 1 < nkt) {
            attn_load_kv(Kb[(kt + 1) & 1], Vb[(kt + 1) & 1], b, h, kt + 1, tid);
            CP_COMMIT();
            CP_WAIT1();
        } else {
            CP_WAIT0();
        }
        __syncthreads();
        const float* Ks = Kb[kt & 1];
        const float* Vs = Vb[kt & 1];

        const bool active = (kt * 64 <= qr + 31);
        if (active) {
            const bool diag = ((kt + 1) * 64 > qr);

            // ---- per-subtile: S = Q K^T, mask, softmax, store P ----
            #pragma unroll
            for (int s = 0; s < 2; s++) {
                float sacc[8][4];
                #pragma unroll
                for (int ni = 0; ni < 8; ni++)
                    #pragma unroll
                    for (int j = 0; j < 4; j++) sacc[ni][j] = 0.f;

                #pragma unroll
                for (int ks = 0; ks < 8; ks++) {
                    #pragma unroll
                    for (int ni = 0; ni < 8; ni++) {
                        float2 bb = *(const float2*)&Ks[(ni * 8 + g) * AKW + ks * 8 + k2];
                        uint32_t bfr[2] = { __float_as_uint(bb.x), __float_as_uint(bb.y) };
                        mma8(sacc[ni], qf[s][ks], bfr);
                    }
                }

                const int rA = qr + s * 16 + g;
                const int rB = rA + 8;
                if (diag) {
                    #pragma unroll
                    for (int ni = 0; ni < 8; ni++) {
                        const int c0 = kt * 64 + ni * 8 + k2;
                        if (c0 > rA)     sacc[ni][0] = -1e30f;
                        if (c0 + 1 > rA) sacc[ni][1] = -1e30f;
                        if (c0 > rB)     sacc[ni][2] = -1e30f;
                        if (c0 + 1 > rB) sacc[ni][3] = -1e30f;
                    }
                }

                float t0 = -1e30f, t1 = -1e30f;
                #pragma unroll
                for (int ni = 0; ni < 8; ni++) {
                    t0 = fmaxf(t0, fmaxf(sacc[ni][0], sacc[ni][1]));
                    t1 = fmaxf(t1, fmaxf(sacc[ni][2], sacc[ni][3]));
                }
                t0 = fmaxf(t0, __shfl_xor_sync(0xffffffffu, t0, 1));
                t0 = fmaxf(t0, __shfl_xor_sync(0xffffffffu, t0, 2));
                t1 = fmaxf(t1, __shfl_xor_sync(0xffffffffu, t1, 1));
                t1 = fmaxf(t1, __shfl_xor_sync(0xffffffffu, t1, 2));

                const float nm0 = fmaxf(mm[s][0], t0), nm1 = fmaxf(mm[s][1], t1);
                const float cr0 = __expf(mm[s][0] - nm0), cr1 = __expf(mm[s][1] - nm1);
                ll[s][0] *= cr0; ll[s][1] *= cr1;
                #pragma unroll
                for (int ni = 0; ni < 8; ni++) {
                    oacc[s][ni][0] *= cr0; oacc[s][ni][1] *= cr0;
                    oacc[s][ni][2] *= cr1; oacc[s][ni][3] *= cr1;
                }

                float s0 = 0.f, s1 = 0.f;
                const int pr = wid * 32 + s * 16 + g;
                #pragma unroll
                for (int ni = 0; ni < 8; ni++) {
                    float p0 = __expf(sacc[ni][0] - nm0);
                    float p1 = __expf(sacc[ni][1] - nm0);
                    float p2 = __expf(sacc[ni][2] - nm1);
                    float p3 = __expf(sacc[ni][3] - nm1);
                    s0 += p0 + p1; s1 += p2 + p3;
                    const int c0 = ni * 8 + se;
                    Ps[pr * AKW + c0]           = f2tf_f(p0);
                    Ps[pr * AKW + c0 + 2]       = f2tf_f(p1);
                    Ps[(pr + 8) * AKW + c0]     = f2tf_f(p2);
                    Ps[(pr + 8) * AKW + c0 + 2] = f2tf_f(p3);
                }
                s0 += __shfl_xor_sync(0xffffffffu, s0, 1);
                s0 += __shfl_xor_sync(0xffffffffu, s0, 2);
                s1 += __shfl_xor_sync(0xffffffffu, s1, 1);
                s1 += __shfl_xor_sync(0xffffffffu, s1, 2);
                ll[s][0] += s0; ll[s][1] += s1;
                mm[s][0] = nm0; mm[s][1] = nm1;
            }
            __syncwarp();

            // ---- O += P @ V  (V b-frags shared across both subtiles) ----
            #pragma unroll
            for (int ks = 0; ks < 8; ks++) {
                uint32_t vb[8][2];
                #pragma unroll
                for (int ni = 0; ni < 8; ni++) {
                    const int n = ni * 8 + g;
                    vb[ni][0] = __float_as_uint(Vs[(ks * 8 + tig) * AKW + n]);
                    vb[ni][1] = __float_as_uint(Vs[(ks * 8 + tig + 4) * AKW + n]);
                }
                #pragma unroll
                for (int s = 0; s < 2; s++) {
                    const int pr = wid * 32 + s * 16 + g;
                    float2 lo = *(const float2*)&Ps[pr * AKW + ks * 8 + k2];
                    float2 hi = *(const float2*)&Ps[(pr + 8) * AKW + ks * 8 + k2];
                    uint32_t a[4] = { __float_as_uint(lo.x), __float_as_uint(hi.x),
                                      __float_as_uint(lo.y), __float_as_uint(hi.y) };
                    #pragma unroll
                    for (int ni = 0; ni < 8; ni++)
                        mma8(oacc[s][ni], a, vb[ni]);
                }
            }
        }
        __syncthreads();
    }

    // ---- epilogue (round: feeds out-proj A side) ----
    #pragma unroll
    for (int s = 0; s < 2; s++) {
        const float inv0 = 1.f / ll[s][0], inv1 = 1.f / ll[s][1];
        const size_t ob = ((size_t)(b * SEQ + qr + s * 16 + g)) * DIM + h * HD;
        #pragma unroll
        for (int ni = 0; ni < 8; ni++) {
            const int c = ni * 8 + k2;
            float2 v0 = make_float2(f2tf_f(oacc[s][ni][0] * inv0),
                                    f2tf_f(oacc[s][ni][1] * inv0));
            float2 v1 = make_float2(f2tf_f(oacc[s][ni][2] * inv1),
                                    f2tf_f(oacc[s][ni][3] * inv1));
            *(float2*)&g_att[ob + c]                   = v0;
            *(float2*)&g_att[ob + (size_t)8 * DIM + c] = v1;
        }
    }
}

// ---------------------------------------------------------------------------
extern "C" void kernel_launch(void* const* d_in, const int* in_sizes, int n_in,
                              void* d_out, int out_size) {
    const float* x     = (const float*)d_in[0];
    const float* w_qkv = (const float*)d_in[1];
    const float* b_qkv = (const float*)d_in[2];
    const float* w_out = (const float*)d_in[3];
    const float* b_out = (const float*)d_in[4];
    float* out = (float*)d_out;

    float* qkv;  cudaGetSymbolAddress((void**)&qkv,  g_qkv);
    float* att;  cudaGetSymbolAddress((void**)&att,  g_att);
    float* xa;   cudaGetSymbolAddress((void**)&xa,   g_xa);
    float* wqT;  cudaGetSymbolAddress((void**)&wqT,  g_wqkvT);
    float* woT;  cudaGetSymbolAddress((void**)&woT,  g_woutT);
    float* bqp;  cudaGetSymbolAddress((void**)&bqp,  g_bqkvp);

    cudaFuncSetAttribute(tf32_gemm_v3<true>,
                         cudaFuncAttributeMaxDynamicSharedMemorySize, GEMM_SMEM);
    cudaFuncSetAttribute(tf32_gemm_v3<false>,
                         cudaFuncAttributeMaxDynamicSharedMemorySize, GEMM_SMEM);
    cudaFuncSetAttribute(attn_mma_v3,
                         cudaFuncAttributeMaxDynamicSharedMemorySize, ATTN_SMEM);

    // --- pre-pass: round + permute + transpose ---
    prep_x_kernel<<<(ROWS * DIM / 8) / 256, 256>>>(x);
    prep_wT_kernel<true><<<dim3(DIM / 32, 3 * DIM / 32), dim3(32, 8)>>>(w_qkv, wqT, 3 * DIM);
    prep_wT_kernel<false><<<dim3(DIM / 32, DIM / 32), dim3(32, 8)>>>(w_out, woT, DIM);
    prep_bias_kernel<<<(3 * DIM + 255) / 256, 256>>>(b_qkv);

    // 1) QKV projection
    {
        dim3 grid(3 * DIM / 128, ROWS / 256);
        tf32_gemm_v3<true><<<grid, 256, GEMM_SMEM>>>(xa, wqT, bqp, qkv, 3 * DIM);
    }
    // 2) causal multi-head attention
    {
        dim3 grid(SEQ / AQT, HEADS, BATCH);
        attn_mma_v3<<<grid, 256, ATTN_SMEM>>>();
    }
    // 3) output projection
    {
        dim3 grid(DIM / 128, ROWS / 256);
        tf32_gemm_v3<false><<<grid, 256, GEMM_SMEM>>>(att, woT, b_out, out, DIM);
    }
}

// round 8
// speedup vs baseline: 7.3911x; 1.7390x over previous
#include <cuda_runtime.h>
#include <cuda_fp16.h>
#include <cstdint>

#define BATCH 4
#define SEQ   2048
#define DIM   1024
#define HEADS 16
#define HD    64
#define ROWS (BATCH * SEQ)        // 8192

// Scratch (allocation-free rule: device globals), fp16 operand space
__device__ __half g_qkv[(size_t)ROWS * 3 * DIM];   // qkv, σ-permuted cols
__device__ __half g_att[(size_t)ROWS * DIM];       // attention out, σ-slot cols
__device__ __half g_xa[(size_t)ROWS * DIM];        // x, σ-permuted cols
__device__ __half g_wqkvT[(size_t)(3 * DIM) * DIM];// w_qkv^T, k+n σ-permuted
__device__ __half g_woutT[(size_t)DIM * DIM];      // w_out^T, k σ-permuted
__device__ float  g_bqkvp[3 * DIM];                // σ-permuted bias (fp32)

// ---------------------------------------------------------------------------
// helpers
// ---------------------------------------------------------------------------
// within-16 interleave: slot s holds true index sig(s); pairs stay adjacent.
__device__ __forceinline__ int sig16(int w) {          // w in [0,16)
    return 2 * (w >> 2) + (w & 1) + 8 * ((w >> 1) & 1);
}
__device__ __forceinline__ int sig(int s) { return (s & ~15) | sig16(s & 15); }
// inverse: slot holding true index w  (verified inv16(sig16(s)) == s for all s)
__device__ __forceinline__ int inv16(int w) {
    return 4 * ((w >> 1) & 3) + 2 * ((w >> 3) & 1) + (w & 1);
}

__device__ __forceinline__ void mma16(float* c, const uint32_t* a, const uint32_t* b) {
    asm volatile(
        "mma.sync.aligned.m16n8k16.row.col.f32.f16.f16.f32 "
        "{%0,%1,%2,%3}, {%4,%5,%6,%7}, {%8,%9}, {%0,%1,%2,%3};"
        : "+f"(c[0]), "+f"(c[1]), "+f"(c[2]), "+f"(c[3])
        : "r"(a[0]), "r"(a[1]), "r"(a[2]), "r"(a[3]), "r"(b[0]), "r"(b[1]));
}
__device__ __forceinline__ void ldmx4t(uint32_t* r, uint32_t addr) {
    asm volatile("ldmatrix.sync.aligned.m8n8.x4.trans.shared.b16 "
                 "{%0,%1,%2,%3}, [%4];"
                 : "=r"(r[0]), "=r"(r[1]), "=r"(r[2]), "=r"(r[3]) : "r"(addr));
}
__device__ __forceinline__ uint32_t sptr(const void* p) {
    return (uint32_t)__cvta_generic_to_shared(p);
}
__device__ __forceinline__ void cp16(uint32_t s, const void* g) {
    asm volatile("cp.async.ca.shared.global [%0], [%1], 16;" :: "r"(s), "l"(g));
}
#define CP_COMMIT() asm volatile("cp.async.commit_group;")
#define CP_WAIT0()  asm volatile("cp.async.wait_group 0;")
#define CP_WAIT1()  asm volatile("cp.async.wait_group 1;")

// ---------------------------------------------------------------------------
// Pre-pass kernels (fp32 -> fp16, σ-permute, transpose weights)
// ---------------------------------------------------------------------------
__global__ __launch_bounds__(256)
void prep_x(const float* __restrict__ x) {
    const size_t base = ((size_t)blockIdx.x * 256 + threadIdx.x) * 16;
    float v[16];
    #pragma unroll
    for (int i = 0; i < 16; i += 4) *(float4*)&v[i] = *(const float4*)&x[base + i];
    __half2 h[8];
    #pragma unroll
    for (int u = 0; u < 4; u++) {
        h[2 * u]     = __floats2half2_rn(v[2 * u],     v[2 * u + 1]);
        h[2 * u + 1] = __floats2half2_rn(v[2 * u + 8], v[2 * u + 9]);
    }
    *(uint4*)&g_xa[base]     = *(uint4*)&h[0];
    *(uint4*)&g_xa[base + 8] = *(uint4*)&h[4];
}

// w[1024][N] -> dst[N][1024] fp16: dst[c][ks] = h(w[sig(ks)][PERMN? sig(c): c])
template<bool PERMN>
__global__ void prep_w(const float* __restrict__ src, __half* __restrict__ dst, int N) {
    __shared__ float tile[32][33];
    const int tx = threadIdx.x, ty = threadIdx.y;       // 16 x 16
    const int kb = blockIdx.x * 32, nb = blockIdx.y * 32;
    tile[ty][tx]           = src[(size_t)(kb + ty) * N + nb + tx];
    tile[ty][tx + 16]      = src[(size_t)(kb + ty) * N + nb + tx + 16];
    tile[ty + 16][tx]      = src[(size_t)(kb + ty + 16) * N + nb + tx];
    tile[ty + 16][tx + 16] = src[(size_t)(kb + ty + 16) * N + nb + tx + 16];
    __syncthreads();
    const int s  = 2 * tx;
    const int t0 = (s & 16) | sig16(s & 15);
    #pragma unroll
    for (int i = 0; i < 2; i++) {
        const int ny = ty + 16 * i;
        const int nn = PERMN ? ((ny & ~15) | sig16(ny & 15)) : ny;
        __half2 h = __floats2half2_rn(tile[t0][nn], tile[t0 + 1][nn]);
        *(__half2*)&dst[(size_t)(nb + ny) * DIM + kb + s] = h;
    }
}

__global__ void prep_bias(const float* __restrict__ b) {
    const int s = blockIdx.x * 256 + threadIdx.x;
    if (s < 3 * DIM) g_bqkvp[s] = b[sig(s)];
}

// ---------------------------------------------------------------------------
// FP16 MMA GEMM: C[M][N] = A[M][1024] @ B[N][1024]^T + bias
// Block 256x128, BK=64 halves, 256 thr (8 warps 4x2), warp 64x64.
// smem rows 80 halves (160B). Double buffered cp.async.
// ---------------------------------------------------------------------------
#define GKW 80
#define GA_H (256 * GKW)
#define GB_H (128 * GKW)
#define GSTG_H (GA_H + GB_H)
#define GEMM_SMEM (2 * GSTG_H * 2)          // 122880 B

__device__ __forceinline__ void gemm_load(__half* stage,
                                          const __half* __restrict__ A,
                                          const __half* __restrict__ B,
                                          int bm, int bn, int k0, int tid) {
    #pragma unroll
    for (int i = 0; i < 8; i++) {
        int t = tid + i * 256;              // 0..2047
        int row = t >> 3, c = t & 7;
        cp16(sptr(stage + row * GKW + c * 8), A + (size_t)(bm + row) * DIM + k0 + c * 8);
    }
    #pragma unroll
    for (int i = 0; i < 4; i++) {
        int t = tid + i * 256;              // 0..1023
        int row = t >> 3, c = t & 7;
        cp16(sptr(stage + GA_H + row * GKW + c * 8), B + (size_t)(bn + row) * DIM + k0 + c * 8);
    }
}

template<bool HALF_OUT>
__global__ __launch_bounds__(256)
void hgemm(const __half* __restrict__ A, const __half* __restrict__ B,
           const float* __restrict__ bias, void* __restrict__ Cv, int N) {
    extern __shared__ __half smh[];
    const int tid  = threadIdx.x;
    const int lane = tid & 31;
    const int wid  = tid >> 5;
    const int g    = lane >> 2;
    const int tig  = lane & 3;
    const int wm   = wid >> 1;          // 0..3
    const int wn   = wid & 1;           // 0..1
    const int bm   = blockIdx.y * 256;
    const int bn   = blockIdx.x * 128;

    float acc[4][8][4];
    #pragma unroll
    for (int mi = 0; mi < 4; mi++)
        #pragma unroll
        for (int ni = 0; ni < 8; ni++)
            #pragma unroll
            for (int j = 0; j < 4; j++) acc[mi][ni][j] = 0.f;

    constexpr int NT = DIM / 64;        // 16 k-tiles

    gemm_load(smh, A, B, bm, bn, 0, tid);
    CP_COMMIT();

    for (int t = 0; t < NT; t++) {
        if (t + 1 < NT) {
            gemm_load(smh + ((t + 1) & 1) * GSTG_H, A, B, bm, bn, (t + 1) * 64, tid);
            CP_COMMIT();
            CP_WAIT1();
        } else {
            CP_WAIT0();
        }
        __syncthreads();
        const __half* As = smh + (t & 1) * GSTG_H;
        const __half* Bs = As + GA_H;

        #pragma unroll
        for (int ks = 0; ks < 4; ks++) {
            const int co = ks * 16 + 4 * tig;
            uint32_t a[4][4], b[8][2];
            #pragma unroll
            for (int mi = 0; mi < 4; mi++) {
                const int m = wm * 64 + mi * 16 + g;
                uint2 lo = *(const uint2*)&As[m * GKW + co];
                uint2 hi = *(const uint2*)&As[(m + 8) * GKW + co];
                a[mi][0] = lo.x; a[mi][2] = lo.y;
                a[mi][1] = hi.x; a[mi][3] = hi.y;
            }
            #pragma unroll
            for (int ni = 0; ni < 8; ni++) {
                const int n = wn * 64 + ni * 8 + g;
                uint2 bb = *(const uint2*)&Bs[n * GKW + co];
                b[ni][0] = bb.x; b[ni][1] = bb.y;
            }
            #pragma unroll
            for (int mi = 0; mi < 4; mi++)
                #pragma unroll
                for (int ni = 0; ni < 8; ni++)
                    mma16(acc[mi][ni], a[mi], b[ni]);
        }
        __syncthreads();
    }

    #pragma unroll
    for (int mi = 0; mi < 4; mi++) {
        const int r0 = bm + wm * 64 + mi * 16 + g;
        #pragma unroll
        for (int ni = 0; ni < 8; ni++) {
            const int col = bn + wn * 64 + ni * 8 + 2 * tig;
            const float b0 = bias[col], b1 = bias[col + 1];
            const float v00 = acc[mi][ni][0] + b0, v01 = acc[mi][ni][1] + b1;
            const float v10 = acc[mi][ni][2] + b0, v11 = acc[mi][ni][3] + b1;
            if (HALF_OUT) {
                __half* C = (__half*)Cv;
                *(__half2*)&C[(size_t)r0 * N + col]       = __floats2half2_rn(v00, v01);
                *(__half2*)&C[(size_t)(r0 + 8) * N + col] = __floats2half2_rn(v10, v11);
            } else {
                float* C = (float*)Cv;
                *(float2*)&C[(size_t)r0 * N + col]       = make_float2(v00, v01);
                *(float2*)&C[(size_t)(r0 + 8) * N + col] = make_float2(v10, v11);
            }
        }
    }
}

// ---------------------------------------------------------------------------
// FP16 MMA causal flash attention.
// grid = (SEQ/256, HEADS, BATCH), 256 thr = 8 warps, warp = 32 q rows.
// KV tile 64, cp.async double buffered. V b-frags via ldmatrix.trans.
// smem halves: K[2][64][80] | V[2][64][72] | P[256][80]
// ---------------------------------------------------------------------------
#define AQT 256
#define KW  80
#define VW  72
#define PW  80
#define KT_H (64 * KW)
#define VT_H (64 * VW)
#define ATTN_SMEM ((2 * KT_H + 2 * VT_H + AQT * PW) * 2)   // 79872 B

__device__ __forceinline__ void attn_load_kv(__half* Ks, __half* Vs,
                                             int b, int h, int kt, int tid) {
    const size_t base = ((size_t)(b * SEQ + kt * 64)) * (3 * DIM) + DIM + h * HD;
    #pragma unroll
    for (int i = 0; i < 2; i++) {
        int t = tid + i * 256;              // 0..511
        int row = t >> 3, c = t & 7;
        const __half* src = &g_qkv[base + (size_t)row * 3 * DIM + c * 8];
        cp16(sptr(Ks + row * KW + c * 8), src);
        cp16(sptr(Vs + row * VW + c * 8), src + DIM);
    }
}

__global__ __launch_bounds__(256)
void attn_fp16() {
    extern __shared__ __half smh[];
    __half* Kb[2] = { smh, smh + KT_H };
    __half* Vb[2] = { smh + 2 * KT_H, smh + 2 * KT_H + VT_H };
    __half* Ps = smh + 2 * KT_H + 2 * VT_H;

    const int qt   = blockIdx.x;
    const int h    = blockIdx.y;
    const int b    = blockIdx.z;
    const int tid  = threadIdx.x;
    const int lane = tid & 31;
    const int wid  = tid >> 5;
    const int g    = lane >> 2;
    const int tig  = lane & 3;

    const int qr  = qt * AQT + wid * 32;
    const int nkt = qt * 4 + 4;

    attn_load_kv(Kb[0], Vb[0], b, h, 0, tid);
    CP_COMMIT();

    // Q fragments (fp16, σ-slot cols), scaled by 1/8 once
    const __half2 qsc = __float2half2_rn(0.125f);
    uint32_t qf[2][4][4];
    #pragma unroll
    for (int s = 0; s < 2; s++) {
        const size_t r0 = ((size_t)(b * SEQ + qr + s * 16 + g)) * (3 * DIM) + h * HD;
        const size_t r1 = r0 + (size_t)8 * 3 * DIM;
        #pragma unroll
        for (int ks = 0; ks < 4; ks++) {
            uint2 lo = *(const uint2*)&g_qkv[r0 + ks * 16 + 4 * tig];
            uint2 hi = *(const uint2*)&g_qkv[r1 + ks * 16 + 4 * tig];
            __half2 t;
            t = __hmul2(*(__half2*)&lo.x, qsc); qf[s][ks][0] = *(uint32_t*)&t;
            t = __hmul2(*(__half2*)&hi.x, qsc); qf[s][ks][1] = *(uint32_t*)&t;
            t = __hmul2(*(__half2*)&lo.y, qsc); qf[s][ks][2] = *(uint32_t*)&t;
            t = __hmul2(*(__half2*)&hi.y, qsc); qf[s][ks][3] = *(uint32_t*)&t;
        }
    }

    float oacc[2][8][4];
    #pragma unroll
    for (int s = 0; s < 2; s++)
        #pragma unroll
        for (int ni = 0; ni < 8; ni++)
            #pragma unroll
            for (int j = 0; j < 4; j++) oacc[s][ni][j] = 0.f;
    float mm[2][2] = {{-1e30f, -1e30f}, {-1e30f, -1e30f}};
    float ll[2][2] = {{0.f, 0.f}, {0.f, 0.f}};

    for (int kt = 0; kt < nkt; kt++) {
        if (kt + 1 < nkt) {
            attn_load_kv(Kb[(kt + 1) & 1], Vb[(kt + 1) & 1], b, h, kt + 1, tid);
            CP_COMMIT();
            CP_WAIT1();
        } else {
            CP_WAIT0();
        }
        __syncthreads();
        const __half* Ks = Kb[kt & 1];
        const __half* Vs = Vb[kt & 1];

        const bool active = (kt * 64 <= qr + 31);
        if (active) {
            const bool diag = ((kt + 1) * 64 > qr);

            #pragma unroll
            for (int s = 0; s < 2; s++) {
                float sacc[8][4];
                #pragma unroll
                for (int ni = 0; ni < 8; ni++)
                    #pragma unroll
                    for (int j = 0; j < 4; j++) sacc[ni][j] = 0.f;

                #pragma unroll
                for (int ks = 0; ks < 4; ks++) {
                    const int co = ks * 16 + 4 * tig;
                    #pragma unroll
                    for (int ni = 0; ni < 8; ni++) {
                        uint2 bb = *(const uint2*)&Ks[(ni * 8 + g) * KW + co];
                        uint32_t bfr[2] = { bb.x, bb.y };
                        mma16(sacc[ni], qf[s][ks], bfr);
                    }
                }

                const int rA = qr + s * 16 + g, rB = rA + 8;
                if (diag) {
                    #pragma unroll
                    for (int ni = 0; ni < 8; ni++) {
                        const int c0 = kt * 64 + ni * 8 + 2 * tig;
                        if (c0 > rA)     sacc[ni][0] = -1e30f;
                        if (c0 + 1 > rA) sacc[ni][1] = -1e30f;
                        if (c0 > rB)     sacc[ni][2] = -1e30f;
                        if (c0 + 1 > rB) sacc[ni][3] = -1e30f;
                    }
                }

                float t0 = -1e30f, t1 = -1e30f;
                #pragma unroll
                for (int ni = 0; ni < 8; ni++) {
                    t0 = fmaxf(t0, fmaxf(sacc[ni][0], sacc[ni][1]));
                    t1 = fmaxf(t1, fmaxf(sacc[ni][2], sacc[ni][3]));
                }
                t0 = fmaxf(t0, __shfl_xor_sync(0xffffffffu, t0, 1));
                t0 = fmaxf(t0, __shfl_xor_sync(0xffffffffu, t0, 2));
                t1 = fmaxf(t1, __shfl_xor_sync(0xffffffffu, t1, 1));
                t1 = fmaxf(t1, __shfl_xor_sync(0xffffffffu, t1, 2));

                const float nm0 = fmaxf(mm[s][0], t0), nm1 = fmaxf(mm[s][1], t1);
                const float cr0 = __expf(mm[s][0] - nm0), cr1 = __expf(mm[s][1] - nm1);
                ll[s][0] *= cr0; ll[s][1] *= cr1;
                #pragma unroll
                for (int ni = 0; ni < 8; ni++) {
                    oacc[s][ni][0] *= cr0; oacc[s][ni][1] *= cr0;
                    oacc[s][ni][2] *= cr1; oacc[s][ni][3] *= cr1;
                }

                float s0 = 0.f, s1 = 0.f;
                const int pr = wid * 32 + s * 16 + g;
                #pragma unroll
                for (int ni = 0; ni < 8; ni++) {
                    float p0 = __expf(sacc[ni][0] - nm0);
                    float p1 = __expf(sacc[ni][1] - nm0);
                    float p2 = __expf(sacc[ni][2] - nm1);
                    float p3 = __expf(sacc[ni][3] - nm1);
                    s0 += p0 + p1; s1 += p2 + p3;
                    const int c0 = ni * 8 + 2 * tig;              // true kv col
                    // store at slot inv16(c0): reader assumes slot s holds kv sig16(s)
                    const int slot = (c0 & ~15) | inv16(c0 & 15);
                    *(__half2*)&Ps[pr * PW + slot]       = __floats2half2_rn(p0, p1);
                    *(__half2*)&Ps[(pr + 8) * PW + slot] = __floats2half2_rn(p2, p3);
                }
                s0 += __shfl_xor_sync(0xffffffffu, s0, 1);
                s0 += __shfl_xor_sync(0xffffffffu, s0, 2);
                s1 += __shfl_xor_sync(0xffffffffu, s1, 1);
                s1 += __shfl_xor_sync(0xffffffffu, s1, 2);
                ll[s][0] += s0; ll[s][1] += s1;
                mm[s][0] = nm0; mm[s][1] = nm1;
            }
            __syncwarp();

            // ---- O += P @ V  (V b-frags via ldmatrix.trans, shared across subtiles)
            const int lt = lane >> 3, lr = lane & 7;
            #pragma unroll
            for (int ks = 0; ks < 4; ks++) {
                uint32_t vb[4][4];
                const int vrow = ks * 16 + (lt & 1) * 8 + lr;
                const int vcb  = (lt >> 1) * 8;
                #pragma unroll
                for (int d4 = 0; d4 < 4; d4++)
                    ldmx4t(vb[d4], sptr(Vs + vrow * VW + vcb + d4 * 16));
                #pragma unroll
                for (int s = 0; s < 2; s++) {
                    const int pr = wid * 32 + s * 16 + g;
                    uint2 lo = *(const uint2*)&Ps[pr * PW + ks * 16 + 4 * tig];
                    uint2 hi = *(const uint2*)&Ps[(pr + 8) * PW + ks * 16 + 4 * tig];
                    uint32_t a[4] = { lo.x, hi.x, lo.y, hi.y };
                    #pragma unroll
                    for (int d4 = 0; d4 < 4; d4++) {
                        mma16(oacc[s][2 * d4],     a, &vb[d4][0]);
                        mma16(oacc[s][2 * d4 + 1], a, &vb[d4][2]);
                    }
                }
            }
        }
        __syncthreads();
    }

    // ---- epilogue: O/l -> g_att (fp16, σ-slot cols) ----
    #pragma unroll
    for (int s = 0; s < 2; s++) {
        const float inv0 = 1.f / ll[s][0], inv1 = 1.f / ll[s][1];
        const size_t ob = ((size_t)(b * SEQ + qr + s * 16 + g)) * DIM + h * HD;
        #pragma unroll
        for (int ni = 0; ni < 8; ni++) {
            const int c = ni * 8 + 2 * tig;
            *(__half2*)&g_att[ob + c] =
                __floats2half2_rn(oacc[s][ni][0] * inv0, oacc[s][ni][1] * inv0);
            *(__half2*)&g_att[ob + (size_t)8 * DIM + c] =
                __floats2half2_rn(oacc[s][ni][2] * inv1, oacc[s][ni][3] * inv1);
        }
    }
}

// ---------------------------------------------------------------------------
extern "C" void kernel_launch(void* const* d_in, const int* in_sizes, int n_in,
                              void* d_out, int out_size) {
    const float* x     = (const float*)d_in[0];
    const float* w_qkv = (const float*)d_in[1];
    const float* b_qkv = (const float*)d_in[2];
    const float* w_out = (const float*)d_in[3];
    const float* b_out = (const float*)d_in[4];
    float* out = (float*)d_out;

    __half* qkv; cudaGetSymbolAddress((void**)&qkv, g_qkv);
    __half* att; cudaGetSymbolAddress((void**)&att, g_att);
    __half* xa;  cudaGetSymbolAddress((void**)&xa,  g_xa);
    __half* wqT; cudaGetSymbolAddress((void**)&wqT, g_wqkvT);
    __half* woT; cudaGetSymbolAddress((void**)&woT, g_woutT);
    float*  bqp; cudaGetSymbolAddress((void**)&bqp, g_bqkvp);

    cudaFuncSetAttribute(hgemm<true>,
                         cudaFuncAttributeMaxDynamicSharedMemorySize, GEMM_SMEM);
    cudaFuncSetAttribute(hgemm<false>,
                         cudaFuncAttributeMaxDynamicSharedMemorySize, GEMM_SMEM);
    cudaFuncSetAttribute(attn_fp16,
                         cudaFuncAttributeMaxDynamicSharedMemorySize, ATTN_SMEM);

    // --- pre-pass ---
    prep_x<<<(ROWS * DIM / 16) / 256, 256>>>(x);
    prep_w<true><<<dim3(DIM / 32, 3 * DIM / 32), dim3(16, 16)>>>(w_qkv, wqT, 3 * DIM);
    prep_w<false><<<dim3(DIM / 32, DIM / 32), dim3(16, 16)>>>(w_out, woT, DIM);
    prep_bias<<<(3 * DIM + 255) / 256, 256>>>(b_qkv);

    // 1) QKV projection (fp16 mma)
    {
        dim3 grid(3 * DIM / 128, ROWS / 256);
        hgemm<true><<<grid, 256, GEMM_SMEM>>>(xa, wqT, bqp, qkv, 3 * DIM);
    }
    // 2) causal multi-head attention (fp16 mma flash)
    {
        dim3 grid(SEQ / AQT, HEADS, BATCH);
        attn_fp16<<<grid, 256, ATTN_SMEM>>>();
    }
    // 3) output projection (fp16 mma, fp32 out)
    {
        dim3 grid(DIM / 128, ROWS / 256);
        hgemm<false><<<grid, 256, GEMM_SMEM>>>(att, woT, b_out, out, DIM);
    }
}

// round 9
// speedup vs baseline: 7.5871x; 1.0265x over previous
#include <cuda_runtime.h>
#include <cuda_fp16.h>
#include <cstdint>

#define BATCH 4
#define SEQ   2048
#define DIM   1024
#define HEADS 16
#define HD    64
#define ROWS (BATCH * SEQ)        // 8192

// Scratch (allocation-free rule: device globals), fp16 operand space
__device__ __half g_qkv[(size_t)ROWS * 3 * DIM];   // qkv, σ-permuted cols
__device__ __half g_att[(size_t)ROWS * DIM];       // attention out, σ-slot cols
__device__ __half g_xa[(size_t)ROWS * DIM];        // x, σ-permuted cols
__device__ __half g_wqkvT[(size_t)(3 * DIM) * DIM];// w_qkv^T, k+n σ-permuted
__device__ __half g_woutT[(size_t)DIM * DIM];      // w_out^T, k σ-permuted
__device__ float  g_bqkvp[3 * DIM];                // σ-permuted bias (fp32)

// ---------------------------------------------------------------------------
// helpers
// ---------------------------------------------------------------------------
// within-16 interleave: slot s holds true index sig(s); pairs stay adjacent.
__device__ __forceinline__ int sig16(int w) {          // w in [0,16)
    return 2 * (w >> 2) + (w & 1) + 8 * ((w >> 1) & 1);
}
__device__ __forceinline__ int sig(int s) { return (s & ~15) | sig16(s & 15); }

__device__ __forceinline__ void mma16(float* c, const uint32_t* a, const uint32_t* b) {
    asm volatile(
        "mma.sync.aligned.m16n8k16.row.col.f32.f16.f16.f32 "
        "{%0,%1,%2,%3}, {%4,%5,%6,%7}, {%8,%9}, {%0,%1,%2,%3};"
        : "+f"(c[0]), "+f"(c[1]), "+f"(c[2]), "+f"(c[3])
        : "r"(a[0]), "r"(a[1]), "r"(a[2]), "r"(a[3]), "r"(b[0]), "r"(b[1]));
}
__device__ __forceinline__ void ldmx4t(uint32_t* r, uint32_t addr) {
    asm volatile("ldmatrix.sync.aligned.m8n8.x4.trans.shared.b16 "
                 "{%0,%1,%2,%3}, [%4];"
                 : "=r"(r[0]), "=r"(r[1]), "=r"(r[2]), "=r"(r[3]) : "r"(addr));
}
__device__ __forceinline__ uint32_t sptr(const void* p) {
    return (uint32_t)__cvta_generic_to_shared(p);
}
__device__ __forceinline__ void cp16(uint32_t s, const void* g) {
    asm volatile("cp.async.ca.shared.global [%0], [%1], 16;" :: "r"(s), "l"(g));
}
#define CP_COMMIT() asm volatile("cp.async.commit_group;")
#define CP_WAIT0()  asm volatile("cp.async.wait_group 0;")
#define CP_WAIT1()  asm volatile("cp.async.wait_group 1;")

// ---------------------------------------------------------------------------
// Pre-pass kernels (fp32 -> fp16, σ-permute, transpose weights)
// ---------------------------------------------------------------------------
__global__ __launch_bounds__(256)
void prep_x(const float* __restrict__ x, const float* __restrict__ bq) {
    const size_t base = ((size_t)blockIdx.x * 256 + threadIdx.x) * 16;
    float v[16];
    #pragma unroll
    for (int i = 0; i < 16; i += 4) *(float4*)&v[i] = *(const float4*)&x[base + i];
    __half2 h[8];
    #pragma unroll
    for (int u = 0; u < 4; u++) {
        h[2 * u]     = __floats2half2_rn(v[2 * u],     v[2 * u + 1]);
        h[2 * u + 1] = __floats2half2_rn(v[2 * u + 8], v[2 * u + 9]);
    }
    *(uint4*)&g_xa[base]     = *(uint4*)&h[0];
    *(uint4*)&g_xa[base + 8] = *(uint4*)&h[4];
    // fold bias permute into first 12 blocks (3072 elems)
    if (blockIdx.x < 12) {
        const int s = blockIdx.x * 256 + threadIdx.x;
        g_bqkvp[s] = bq[sig(s)];
    }
}

// w[1024][N] -> dst[N][1024] fp16: dst[c][ks] = h(w[sig(ks)][PERMN? sig(c): c])
template<bool PERMN>
__global__ void prep_w(const float* __restrict__ src, __half* __restrict__ dst, int N) {
    __shared__ float tile[32][33];
    const int tx = threadIdx.x, ty = threadIdx.y;       // 16 x 16
    const int kb = blockIdx.x * 32, nb = blockIdx.y * 32;
    tile[ty][tx]           = src[(size_t)(kb + ty) * N + nb + tx];
    tile[ty][tx + 16]      = src[(size_t)(kb + ty) * N + nb + tx + 16];
    tile[ty + 16][tx]      = src[(size_t)(kb + ty + 16) * N + nb + tx];
    tile[ty + 16][tx + 16] = src[(size_t)(kb + ty + 16) * N + nb + tx + 16];
    __syncthreads();
    const int s  = 2 * tx;
    const int t0 = (s & 16) | sig16(s & 15);
    #pragma unroll
    for (int i = 0; i < 2; i++) {
        const int ny = ty + 16 * i;
        const int nn = PERMN ? ((ny & ~15) | sig16(ny & 15)) : ny;
        __half2 h = __floats2half2_rn(tile[t0][nn], tile[t0 + 1][nn]);
        *(__half2*)&dst[(size_t)(nb + ny) * DIM + kb + s] = h;
    }
}

// ---------------------------------------------------------------------------
// FP16 MMA GEMM: C[M][N] = A[M][1024] @ B[N][1024]^T + bias
// Block 256x128, BK=64 halves, 256 thr (8 warps 4x2), warp 64x64.
// smem rows 80 halves (160B). Double buffered cp.async.
// ---------------------------------------------------------------------------
#define GKW 80
#define GA_H (256 * GKW)
#define GB_H (128 * GKW)
#define GSTG_H (GA_H + GB_H)
#define GEMM_SMEM (2 * GSTG_H * 2)          // 122880 B

__device__ __forceinline__ void gemm_load(__half* stage,
                                          const __half* __restrict__ A,
                                          const __half* __restrict__ B,
                                          int bm, int bn, int k0, int tid) {
    #pragma unroll
    for (int i = 0; i < 8; i++) {
        int t = tid + i * 256;              // 0..2047
        int row = t >> 3, c = t & 7;
        cp16(sptr(stage + row * GKW + c * 8), A + (size_t)(bm + row) * DIM + k0 + c * 8);
    }
    #pragma unroll
    for (int i = 0; i < 4; i++) {
        int t = tid + i * 256;              // 0..1023
        int row = t >> 3, c = t & 7;
        cp16(sptr(stage + GA_H + row * GKW + c * 8), B + (size_t)(bn + row) * DIM + k0 + c * 8);
    }
}

template<bool HALF_OUT>
__global__ __launch_bounds__(256)
void hgemm(const __half* __restrict__ A, const __half* __restrict__ B,
           const float* __restrict__ bias, void* __restrict__ Cv, int N) {
    extern __shared__ __half smh[];
    const int tid  = threadIdx.x;
    const int lane = tid & 31;
    const int wid  = tid >> 5;
    const int g    = lane >> 2;
    const int tig  = lane & 3;
    const int wm   = wid >> 1;          // 0..3
    const int wn   = wid & 1;           // 0..1
    const int bm   = blockIdx.y * 256;
    const int bn   = blockIdx.x * 128;

    float acc[4][8][4];
    #pragma unroll
    for (int mi = 0; mi < 4; mi++)
        #pragma unroll
        for (int ni = 0; ni < 8; ni++)
            #pragma unroll
            for (int j = 0; j < 4; j++) acc[mi][ni][j] = 0.f;

    constexpr int NT = DIM / 64;        // 16 k-tiles

    gemm_load(smh, A, B, bm, bn, 0, tid);
    CP_COMMIT();

    for (int t = 0; t < NT; t++) {
        if (t + 1 < NT) {
            gemm_load(smh + ((t + 1) & 1) * GSTG_H, A, B, bm, bn, (t + 1) * 64, tid);
            CP_COMMIT();
            CP_WAIT1();
        } else {
            CP_WAIT0();
        }
        __syncthreads();
        const __half* As = smh + (t & 1) * GSTG_H;
        const __half* Bs = As + GA_H;

        #pragma unroll
        for (int ks = 0; ks < 4; ks++) {
            const int co = ks * 16 + 4 * tig;
            uint32_t a[4][4], b[8][2];
            #pragma unroll
            for (int mi = 0; mi < 4; mi++) {
                const int m = wm * 64 + mi * 16 + g;
                uint2 lo = *(const uint2*)&As[m * GKW + co];
                uint2 hi = *(const uint2*)&As[(m + 8) * GKW + co];
                a[mi][0] = lo.x; a[mi][2] = lo.y;
                a[mi][1] = hi.x; a[mi][3] = hi.y;
            }
            #pragma unroll
            for (int ni = 0; ni < 8; ni++) {
                const int n = wn * 64 + ni * 8 + g;
                uint2 bb = *(const uint2*)&Bs[n * GKW + co];
                b[ni][0] = bb.x; b[ni][1] = bb.y;
            }
            #pragma unroll
            for (int mi = 0; mi < 4; mi++)
                #pragma unroll
                for (int ni = 0; ni < 8; ni++)
                    mma16(acc[mi][ni], a[mi], b[ni]);
        }
        __syncthreads();
    }

    #pragma unroll
    for (int mi = 0; mi < 4; mi++) {
        const int r0 = bm + wm * 64 + mi * 16 + g;
        #pragma unroll
        for (int ni = 0; ni < 8; ni++) {
            const int col = bn + wn * 64 + ni * 8 + 2 * tig;
            const float b0 = bias[col], b1 = bias[col + 1];
            const float v00 = acc[mi][ni][0] + b0, v01 = acc[mi][ni][1] + b1;
            const float v10 = acc[mi][ni][2] + b0, v11 = acc[mi][ni][3] + b1;
            if (HALF_OUT) {
                __half* C = (__half*)Cv;
                *(__half2*)&C[(size_t)r0 * N + col]       = __floats2half2_rn(v00, v01);
                *(__half2*)&C[(size_t)(r0 + 8) * N + col] = __floats2half2_rn(v10, v11);
            } else {
                float* C = (float*)Cv;
                *(float2*)&C[(size_t)r0 * N + col]       = make_float2(v00, v01);
                *(float2*)&C[(size_t)(r0 + 8) * N + col] = make_float2(v10, v11);
            }
        }
    }
}

// ---------------------------------------------------------------------------
// FP16 MMA causal flash attention v4.
// grid = (SEQ/256, HEADS, BATCH), 256 thr = 8 warps, warp = 32 q rows.
// KV tile 64, cp.async double buffered. V b-frags via ldmatrix.trans.
// P stays entirely in registers (C-fragment of S == A-fragment for P·V).
// Longest blocks scheduled first. smem halves: K[2][64][80] | V[2][64][72]
// ---------------------------------------------------------------------------
#define AQT 256
#define KW  80
#define VW  72
#define KT_H (64 * KW)
#define VT_H (64 * VW)
#define ATTN_SMEM ((2 * KT_H + 2 * VT_H) * 2)   // 38912 B

__device__ __forceinline__ void attn_load_kv(__half* Ks, __half* Vs,
                                             int b, int h, int kt, int tid) {
    const size_t base = ((size_t)(b * SEQ + kt * 64)) * (3 * DIM) + DIM + h * HD;
    #pragma unroll
    for (int i = 0; i < 2; i++) {
        int t = tid + i * 256;              // 0..511
        int row = t >> 3, c = t & 7;
        const __half* src = &g_qkv[base + (size_t)row * 3 * DIM + c * 8];
        cp16(sptr(Ks + row * KW + c * 8), src);
        cp16(sptr(Vs + row * VW + c * 8), src + DIM);
    }
}

__global__ __launch_bounds__(256)
void attn_fp16() {
    extern __shared__ __half smh[];
    __half* Kb[2] = { smh, smh + KT_H };
    __half* Vb[2] = { smh + 2 * KT_H, smh + 2 * KT_H + VT_H };

    const int qt   = gridDim.x - 1 - blockIdx.x;   // longest-first scheduling
    const int h    = blockIdx.y;
    const int b    = blockIdx.z;
    const int tid  = threadIdx.x;
    const int lane = tid & 31;
    const int wid  = tid >> 5;
    const int g    = lane >> 2;
    const int tig  = lane & 3;

    const int qr  = qt * AQT + wid * 32;
    const int nkt = qt * 4 + 4;

    attn_load_kv(Kb[0], Vb[0], b, h, 0, tid);
    CP_COMMIT();

    // Q fragments (fp16, σ-slot cols), scaled by 1/8 once
    const __half2 qsc = __float2half2_rn(0.125f);
    uint32_t qf[2][4][4];
    #pragma unroll
    for (int s = 0; s < 2; s++) {
        const size_t r0 = ((size_t)(b * SEQ + qr + s * 16 + g)) * (3 * DIM) + h * HD;
        const size_t r1 = r0 + (size_t)8 * 3 * DIM;
        #pragma unroll
        for (int ks = 0; ks < 4; ks++) {
            uint2 lo = *(const uint2*)&g_qkv[r0 + ks * 16 + 4 * tig];
            uint2 hi = *(const uint2*)&g_qkv[r1 + ks * 16 + 4 * tig];
            __half2 t;
            t = __hmul2(*(__half2*)&lo.x, qsc); qf[s][ks][0] = *(uint32_t*)&t;
            t = __hmul2(*(__half2*)&hi.x, qsc); qf[s][ks][1] = *(uint32_t*)&t;
            t = __hmul2(*(__half2*)&lo.y, qsc); qf[s][ks][2] = *(uint32_t*)&t;
            t = __hmul2(*(__half2*)&hi.y, qsc); qf[s][ks][3] = *(uint32_t*)&t;
        }
    }

    float oacc[2][8][4];
    #pragma unroll
    for (int s = 0; s < 2; s++)
        #pragma unroll
        for (int ni = 0; ni < 8; ni++)
            #pragma unroll
            for (int j = 0; j < 4; j++) oacc[s][ni][j] = 0.f;
    float mm[2][2] = {{-1e30f, -1e30f}, {-1e30f, -1e30f}};
    float ll[2][2] = {{0.f, 0.f}, {0.f, 0.f}};

    for (int kt = 0; kt < nkt; kt++) {
        if (kt + 1 < nkt) {
            attn_load_kv(Kb[(kt + 1) & 1], Vb[(kt + 1) & 1], b, h, kt + 1, tid);
            CP_COMMIT();
            CP_WAIT1();
        } else {
            CP_WAIT0();
        }
        __syncthreads();
        const __half* Ks = Kb[kt & 1];
        const __half* Vs = Vb[kt & 1];

        const bool active = (kt * 64 <= qr + 31);
        if (active) {
            const bool diag = ((kt + 1) * 64 > qr);

            // V b-frags once per tile (shared across subtiles)
            uint32_t vb[4][4][4];     // [ks][d4][frag]
            {
                const int lt = lane >> 3, lr = lane & 7;
                #pragma unroll
                for (int ks = 0; ks < 4; ks++) {
                    const int vrow = ks * 16 + (lt & 1) * 8 + lr;
                    const int vcb  = (lt >> 1) * 8;
                    #pragma unroll
                    for (int d4 = 0; d4 < 4; d4++)
                        ldmx4t(vb[ks][d4], sptr(Vs + vrow * VW + vcb + d4 * 16));
                }
            }

            #pragma unroll
            for (int s = 0; s < 2; s++) {
                float sacc[8][4];
                #pragma unroll
                for (int ni = 0; ni < 8; ni++)
                    #pragma unroll
                    for (int j = 0; j < 4; j++) sacc[ni][j] = 0.f;

                #pragma unroll
                for (int ks = 0; ks < 4; ks++) {
                    const int co = ks * 16 + 4 * tig;
                    #pragma unroll
                    for (int ni = 0; ni < 8; ni++) {
                        uint2 bb = *(const uint2*)&Ks[(ni * 8 + g) * KW + co];
                        uint32_t bfr[2] = { bb.x, bb.y };
                        mma16(sacc[ni], qf[s][ks], bfr);
                    }
                }

                const int rA = qr + s * 16 + g, rB = rA + 8;
                if (diag) {
                    #pragma unroll
                    for (int ni = 0; ni < 8; ni++) {
                        const int c0 = kt * 64 + ni * 8 + 2 * tig;
                        if (c0 > rA)     sacc[ni][0] = -1e30f;
                        if (c0 + 1 > rA) sacc[ni][1] = -1e30f;
                        if (c0 > rB)     sacc[ni][2] = -1e30f;
                        if (c0 + 1 > rB) sacc[ni][3] = -1e30f;
                    }
                }

                float t0 = -1e30f, t1 = -1e30f;
                #pragma unroll
                for (int ni = 0; ni < 8; ni++) {
                    t0 = fmaxf(t0, fmaxf(sacc[ni][0], sacc[ni][1]));
                    t1 = fmaxf(t1, fmaxf(sacc[ni][2], sacc[ni][3]));
                }
                t0 = fmaxf(t0, __shfl_xor_sync(0xffffffffu, t0, 1));
                t0 = fmaxf(t0, __shfl_xor_sync(0xffffffffu, t0, 2));
                t1 = fmaxf(t1, __shfl_xor_sync(0xffffffffu, t1, 1));
                t1 = fmaxf(t1, __shfl_xor_sync(0xffffffffu, t1, 2));

                const float nm0 = fmaxf(mm[s][0], t0), nm1 = fmaxf(mm[s][1], t1);
                const float cr0 = __expf(mm[s][0] - nm0), cr1 = __expf(mm[s][1] - nm1);
                ll[s][0] *= cr0; ll[s][1] *= cr1;
                #pragma unroll
                for (int ni = 0; ni < 8; ni++) {
                    oacc[s][ni][0] *= cr0; oacc[s][ni][1] *= cr0;
                    oacc[s][ni][2] *= cr1; oacc[s][ni][3] *= cr1;
                }

                // P = exp(S-m) straight in registers
                float s0 = 0.f, s1 = 0.f;
                #pragma unroll
                for (int ni = 0; ni < 8; ni++) {
                    sacc[ni][0] = __expf(sacc[ni][0] - nm0);
                    sacc[ni][1] = __expf(sacc[ni][1] - nm0);
                    sacc[ni][2] = __expf(sacc[ni][2] - nm1);
                    sacc[ni][3] = __expf(sacc[ni][3] - nm1);
                    s0 += sacc[ni][0] + sacc[ni][1];
                    s1 += sacc[ni][2] + sacc[ni][3];
                }
                s0 += __shfl_xor_sync(0xffffffffu, s0, 1);
                s0 += __shfl_xor_sync(0xffffffffu, s0, 2);
                s1 += __shfl_xor_sync(0xffffffffu, s1, 1);
                s1 += __shfl_xor_sync(0xffffffffu, s1, 2);
                ll[s][0] += s0; ll[s][1] += s1;
                mm[s][0] = nm0; mm[s][1] = nm1;

                // O += P @ V — C-fragment of S IS the A-fragment for P·V:
                // a[ks] = { h2(sacc[2ks][0,1]), h2(sacc[2ks][2,3]),
                //           h2(sacc[2ks+1][0,1]), h2(sacc[2ks+1][2,3]) }
                #pragma unroll
                for (int ks = 0; ks < 4; ks++) {
                    __half2 a0 = __floats2half2_rn(sacc[2*ks][0],   sacc[2*ks][1]);
                    __half2 a1 = __floats2half2_rn(sacc[2*ks][2],   sacc[2*ks][3]);
                    __half2 a2 = __floats2half2_rn(sacc[2*ks+1][0], sacc[2*ks+1][1]);
                    __half2 a3 = __floats2half2_rn(sacc[2*ks+1][2], sacc[2*ks+1][3]);
                    uint32_t a[4] = { *(uint32_t*)&a0, *(uint32_t*)&a1,
                                      *(uint32_t*)&a2, *(uint32_t*)&a3 };
                    #pragma unroll
                    for (int d4 = 0; d4 < 4; d4++) {
                        mma16(oacc[s][2 * d4],     a, &vb[ks][d4][0]);
                        mma16(oacc[s][2 * d4 + 1], a, &vb[ks][d4][2]);
                    }
                }
            }
        }
        __syncthreads();
    }

    // ---- epilogue: O/l -> g_att (fp16, σ-slot cols) ----
    #pragma unroll
    for (int s = 0; s < 2; s++) {
        const float inv0 = 1.f / ll[s][0], inv1 = 1.f / ll[s][1];
        const size_t ob = ((size_t)(b * SEQ + qr + s * 16 + g)) * DIM + h * HD;
        #pragma unroll
        for (int ni = 0; ni < 8; ni++) {
            const int c = ni * 8 + 2 * tig;
            *(__half2*)&g_att[ob + c] =
                __floats2half2_rn(oacc[s][ni][0] * inv0, oacc[s][ni][1] * inv0);
            *(__half2*)&g_att[ob + (size_t)8 * DIM + c] =
                __floats2half2_rn(oacc[s][ni][2] * inv1, oacc[s][ni][3] * inv1);
        }
    }
}

// ---------------------------------------------------------------------------
extern "C" void kernel_launch(void* const* d_in, const int* in_sizes, int n_in,
                              void* d_out, int out_size) {
    const float* x     = (const float*)d_in[0];
    const float* w_qkv = (const float*)d_in[1];
    const float* b_qkv = (const float*)d_in[2];
    const float* w_out = (const float*)d_in[3];
    const float* b_out = (const float*)d_in[4];
    float* out = (float*)d_out;

    __half* qkv; cudaGetSymbolAddress((void**)&qkv, g_qkv);
    __half* att; cudaGetSymbolAddress((void**)&att, g_att);
    __half* xa;  cudaGetSymbolAddress((void**)&xa,  g_xa);
    __half* wqT; cudaGetSymbolAddress((void**)&wqT, g_wqkvT);
    __half* woT; cudaGetSymbolAddress((void**)&woT, g_woutT);
    float*  bqp; cudaGetSymbolAddress((void**)&bqp, g_bqkvp);

    cudaFuncSetAttribute(hgemm<true>,
                         cudaFuncAttributeMaxDynamicSharedMemorySize, GEMM_SMEM);
    cudaFuncSetAttribute(hgemm<false>,
                         cudaFuncAttributeMaxDynamicSharedMemorySize, GEMM_SMEM);
    cudaFuncSetAttribute(attn_fp16,
                         cudaFuncAttributeMaxDynamicSharedMemorySize, ATTN_SMEM);

    // --- pre-pass ---
    prep_x<<<(ROWS * DIM / 16) / 256, 256>>>(x, b_qkv);
    prep_w<true><<<dim3(DIM / 32, 3 * DIM / 32), dim3(16, 16)>>>(w_qkv, wqT, 3 * DIM);
    prep_w<false><<<dim3(DIM / 32, DIM / 32), dim3(16, 16)>>>(w_out, woT, DIM);

    // 1) QKV projection (fp16 mma)
    {
        dim3 grid(3 * DIM / 128, ROWS / 256);
        hgemm<true><<<grid, 256, GEMM_SMEM>>>(xa, wqT, bqp, qkv, 3 * DIM);
    }
    // 2) causal multi-head attention (fp16 mma flash, P in registers)
    {
        dim3 grid(SEQ / AQT, HEADS, BATCH);
        attn_fp16<<<grid, 256, ATTN_SMEM>>>();
    }
    // 3) output projection (fp16 mma, fp32 out)
    {
        dim3 grid(DIM / 128, ROWS / 256);
        hgemm<false><<<grid, 256, GEMM_SMEM>>>(att, woT, b_out, out, DIM);
    }
}

// round 10
// speedup vs baseline: 7.7502x; 1.0215x over previous
#include <cuda_runtime.h>
#include <cuda_fp16.h>
#include <cstdint>

#define BATCH 4
#define SEQ   2048
#define DIM   1024
#define HEADS 16
#define HD    64
#define ROWS (BATCH * SEQ)        // 8192

// Scratch (allocation-free rule: device globals), fp16 operand space
__device__ __half g_qkv[(size_t)ROWS * 3 * DIM];   // qkv, σ-permuted cols
__device__ __half g_att[(size_t)ROWS * DIM];       // attention out, σ-slot cols
__device__ __half g_xa[(size_t)ROWS * DIM];        // x, σ-permuted cols
__device__ __half g_wqkvT[(size_t)(3 * DIM) * DIM];// w_qkv^T, k+n σ-permuted
__device__ __half g_woutT[(size_t)DIM * DIM];      // w_out^T, k σ-permuted
__device__ float  g_bqkvp[3 * DIM];                // σ-permuted bias (fp32)

// ---------------------------------------------------------------------------
// helpers
// ---------------------------------------------------------------------------
// within-16 interleave: slot s holds true index sig(s); pairs stay adjacent.
__device__ __forceinline__ int sig16(int w) {          // w in [0,16)
    return 2 * (w >> 2) + (w & 1) + 8 * ((w >> 1) & 1);
}
__device__ __forceinline__ int sig(int s) { return (s & ~15) | sig16(s & 15); }

__device__ __forceinline__ void mma16(float* c, const uint32_t* a, const uint32_t* b) {
    asm volatile(
        "mma.sync.aligned.m16n8k16.row.col.f32.f16.f16.f32 "
        "{%0,%1,%2,%3}, {%4,%5,%6,%7}, {%8,%9}, {%0,%1,%2,%3};"
        : "+f"(c[0]), "+f"(c[1]), "+f"(c[2]), "+f"(c[3])
        : "r"(a[0]), "r"(a[1]), "r"(a[2]), "r"(a[3]), "r"(b[0]), "r"(b[1]));
}
__device__ __forceinline__ void ldmx4t(uint32_t* r, uint32_t addr) {
    asm volatile("ldmatrix.sync.aligned.m8n8.x4.trans.shared.b16 "
                 "{%0,%1,%2,%3}, [%4];"
                 : "=r"(r[0]), "=r"(r[1]), "=r"(r[2]), "=r"(r[3]) : "r"(addr));
}
__device__ __forceinline__ uint32_t sptr(const void* p) {
    return (uint32_t)__cvta_generic_to_shared(p);
}
__device__ __forceinline__ void cp16(uint32_t s, const void* g) {
    asm volatile("cp.async.ca.shared.global [%0], [%1], 16;" :: "r"(s), "l"(g));
}
#define CP_COMMIT() asm volatile("cp.async.commit_group;")
#define CP_WAIT0()  asm volatile("cp.async.wait_group 0;")
#define CP_WAIT1()  asm volatile("cp.async.wait_group 1;")

// ---------------------------------------------------------------------------
// Pre-pass kernels (fp32 -> fp16, σ-permute, transpose weights)
// ---------------------------------------------------------------------------
__global__ __launch_bounds__(256)
void prep_x(const float* __restrict__ x, const float* __restrict__ bq) {
    const size_t base = ((size_t)blockIdx.x * 256 + threadIdx.x) * 16;
    float v[16];
    #pragma unroll
    for (int i = 0; i < 16; i += 4) *(float4*)&v[i] = *(const float4*)&x[base + i];
    __half2 h[8];
    #pragma unroll
    for (int u = 0; u < 4; u++) {
        h[2 * u]     = __floats2half2_rn(v[2 * u],     v[2 * u + 1]);
        h[2 * u + 1] = __floats2half2_rn(v[2 * u + 8], v[2 * u + 9]);
    }
    *(uint4*)&g_xa[base]     = *(uint4*)&h[0];
    *(uint4*)&g_xa[base + 8] = *(uint4*)&h[4];
    if (blockIdx.x < 12) {
        const int s = blockIdx.x * 256 + threadIdx.x;
        g_bqkvp[s] = bq[sig(s)];
    }
}

// w[1024][N] -> dst[N][1024] fp16: dst[c][ks] = h(w[sig(ks)][PERMN? sig(c): c])
template<bool PERMN>
__global__ void prep_w(const float* __restrict__ src, __half* __restrict__ dst, int N) {
    __shared__ float tile[32][33];
    const int tx = threadIdx.x, ty = threadIdx.y;       // 16 x 16
    const int kb = blockIdx.x * 32, nb = blockIdx.y * 32;
    tile[ty][tx]           = src[(size_t)(kb + ty) * N + nb + tx];
    tile[ty][tx + 16]      = src[(size_t)(kb + ty) * N + nb + tx + 16];
    tile[ty + 16][tx]      = src[(size_t)(kb + ty + 16) * N + nb + tx];
    tile[ty + 16][tx + 16] = src[(size_t)(kb + ty + 16) * N + nb + tx + 16];
    __syncthreads();
    const int s  = 2 * tx;
    const int t0 = (s & 16) | sig16(s & 15);
    #pragma unroll
    for (int i = 0; i < 2; i++) {
        const int ny = ty + 16 * i;
        const int nn = PERMN ? ((ny & ~15) | sig16(ny & 15)) : ny;
        __half2 h = __floats2half2_rn(tile[t0][nn], tile[t0 + 1][nn]);
        *(__half2*)&dst[(size_t)(nb + ny) * DIM + kb + s] = h;
    }
}

// ---------------------------------------------------------------------------
// FP16 MMA GEMM v5: C[M][N] = A[M][1024] @ B[N][1024]^T + bias
// Block 128x128, BK=64 halves, 256 thr (8 warps 2x4), warp 64x32.
// Sized for 2 CTAs/SM: smem 80KB, regs capped at 128 via launch bounds.
// ---------------------------------------------------------------------------
#define GKW 80
#define GA_H (128 * GKW)
#define GB_H (128 * GKW)
#define GSTG_H (GA_H + GB_H)
#define GEMM_SMEM (2 * GSTG_H * 2)          // 81920 B

__device__ __forceinline__ void gemm_load(__half* stage,
                                          const __half* __restrict__ A,
                                          const __half* __restrict__ B,
                                          int bm, int bn, int k0, int tid) {
    #pragma unroll
    for (int i = 0; i < 4; i++) {
        int t = tid + i * 256;              // 0..1023
        int row = t >> 3, c = t & 7;
        cp16(sptr(stage + row * GKW + c * 8), A + (size_t)(bm + row) * DIM + k0 + c * 8);
        cp16(sptr(stage + GA_H + row * GKW + c * 8), B + (size_t)(bn + row) * DIM + k0 + c * 8);
    }
}

template<bool HALF_OUT>
__global__ __launch_bounds__(256, 2)
void hgemm(const __half* __restrict__ A, const __half* __restrict__ B,
           const float* __restrict__ bias, void* __restrict__ Cv, int N) {
    extern __shared__ __half smh[];
    const int tid  = threadIdx.x;
    const int lane = tid & 31;
    const int wid  = tid >> 5;
    const int g    = lane >> 2;
    const int tig  = lane & 3;
    const int wm   = wid >> 2;          // 0..1 (64-row slabs)
    const int wn   = wid & 3;           // 0..3 (32-col slabs)
    const int bm   = blockIdx.y * 128;
    const int bn   = blockIdx.x * 128;

    float acc[4][4][4];
    #pragma unroll
    for (int mi = 0; mi < 4; mi++)
        #pragma unroll
        for (int ni = 0; ni < 4; ni++)
            #pragma unroll
            for (int j = 0; j < 4; j++) acc[mi][ni][j] = 0.f;

    constexpr int NT = DIM / 64;        // 16 k-tiles

    gemm_load(smh, A, B, bm, bn, 0, tid);
    CP_COMMIT();

    for (int t = 0; t < NT; t++) {
        if (t + 1 < NT) {
            gemm_load(smh + ((t + 1) & 1) * GSTG_H, A, B, bm, bn, (t + 1) * 64, tid);
            CP_COMMIT();
            CP_WAIT1();
        } else {
            CP_WAIT0();
        }
        __syncthreads();
        const __half* As = smh + (t & 1) * GSTG_H;
        const __half* Bs = As + GA_H;

        #pragma unroll
        for (int ks = 0; ks < 4; ks++) {
            const int co = ks * 16 + 4 * tig;
            uint32_t a[4][4], b[4][2];
            #pragma unroll
            for (int mi = 0; mi < 4; mi++) {
                const int m = wm * 64 + mi * 16 + g;
                uint2 lo = *(const uint2*)&As[m * GKW + co];
                uint2 hi = *(const uint2*)&As[(m + 8) * GKW + co];
                a[mi][0] = lo.x; a[mi][2] = lo.y;
                a[mi][1] = hi.x; a[mi][3] = hi.y;
            }
            #pragma unroll
            for (int ni = 0; ni < 4; ni++) {
                const int n = wn * 32 + ni * 8 + g;
                uint2 bb = *(const uint2*)&Bs[n * GKW + co];
                b[ni][0] = bb.x; b[ni][1] = bb.y;
            }
            #pragma unroll
            for (int mi = 0; mi < 4; mi++)
                #pragma unroll
                for (int ni = 0; ni < 4; ni++)
                    mma16(acc[mi][ni], a[mi], b[ni]);
        }
        __syncthreads();
    }

    #pragma unroll
    for (int mi = 0; mi < 4; mi++) {
        const int r0 = bm + wm * 64 + mi * 16 + g;
        #pragma unroll
        for (int ni = 0; ni < 4; ni++) {
            const int col = bn + wn * 32 + ni * 8 + 2 * tig;
            const float b0 = bias[col], b1 = bias[col + 1];
            const float v00 = acc[mi][ni][0] + b0, v01 = acc[mi][ni][1] + b1;
            const float v10 = acc[mi][ni][2] + b0, v11 = acc[mi][ni][3] + b1;
            if (HALF_OUT) {
                __half* C = (__half*)Cv;
                *(__half2*)&C[(size_t)r0 * N + col]       = __floats2half2_rn(v00, v01);
                *(__half2*)&C[(size_t)(r0 + 8) * N + col] = __floats2half2_rn(v10, v11);
            } else {
                float* C = (float*)Cv;
                *(float2*)&C[(size_t)r0 * N + col]       = make_float2(v00, v01);
                *(float2*)&C[(size_t)(r0 + 8) * N + col] = make_float2(v10, v11);
            }
        }
    }
}

// ---------------------------------------------------------------------------
// FP16 MMA causal flash attention v4 (unchanged from R8).
// grid = (SEQ/256, HEADS, BATCH), 256 thr = 8 warps, warp = 32 q rows.
// ---------------------------------------------------------------------------
#define AQT 256
#define KW  80
#define VW  72
#define KT_H (64 * KW)
#define VT_H (64 * VW)
#define ATTN_SMEM ((2 * KT_H + 2 * VT_H) * 2)   // 38912 B

__device__ __forceinline__ void attn_load_kv(__half* Ks, __half* Vs,
                                             int b, int h, int kt, int tid) {
    const size_t base = ((size_t)(b * SEQ + kt * 64)) * (3 * DIM) + DIM + h * HD;
    #pragma unroll
    for (int i = 0; i < 2; i++) {
        int t = tid + i * 256;              // 0..511
        int row = t >> 3, c = t & 7;
        const __half* src = &g_qkv[base + (size_t)row * 3 * DIM + c * 8];
        cp16(sptr(Ks + row * KW + c * 8), src);
        cp16(sptr(Vs + row * VW + c * 8), src + DIM);
    }
}

__global__ __launch_bounds__(256)
void attn_fp16() {
    extern __shared__ __half smh[];
    __half* Kb[2] = { smh, smh + KT_H };
    __half* Vb[2] = { smh + 2 * KT_H, smh + 2 * KT_H + VT_H };

    const int qt   = gridDim.x - 1 - blockIdx.x;   // longest-first scheduling
    const int h    = blockIdx.y;
    const int b    = blockIdx.z;
    const int tid  = threadIdx.x;
    const int lane = tid & 31;
    const int wid  = tid >> 5;
    const int g    = lane >> 2;
    const int tig  = lane & 3;

    const int qr  = qt * AQT + wid * 32;
    const int nkt = qt * 4 + 4;

    attn_load_kv(Kb[0], Vb[0], b, h, 0, tid);
    CP_COMMIT();

    const __half2 qsc = __float2half2_rn(0.125f);
    uint32_t qf[2][4][4];
    #pragma unroll
    for (int s = 0; s < 2; s++) {
        const size_t r0 = ((size_t)(b * SEQ + qr + s * 16 + g)) * (3 * DIM) + h * HD;
        const size_t r1 = r0 + (size_t)8 * 3 * DIM;
        #pragma unroll
        for (int ks = 0; ks < 4; ks++) {
            uint2 lo = *(const uint2*)&g_qkv[r0 + ks * 16 + 4 * tig];
            uint2 hi = *(const uint2*)&g_qkv[r1 + ks * 16 + 4 * tig];
            __half2 t;
            t = __hmul2(*(__half2*)&lo.x, qsc); qf[s][ks][0] = *(uint32_t*)&t;
            t = __hmul2(*(__half2*)&hi.x, qsc); qf[s][ks][1] = *(uint32_t*)&t;
            t = __hmul2(*(__half2*)&lo.y, qsc); qf[s][ks][2] = *(uint32_t*)&t;
            t = __hmul2(*(__half2*)&hi.y, qsc); qf[s][ks][3] = *(uint32_t*)&t;
        }
    }

    float oacc[2][8][4];
    #pragma unroll
    for (int s = 0; s < 2; s++)
        #pragma unroll
        for (int ni = 0; ni < 8; ni++)
            #pragma unroll
            for (int j = 0; j < 4; j++) oacc[s][ni][j] = 0.f;
    float mm[2][2] = {{-1e30f, -1e30f}, {-1e30f, -1e30f}};
    float ll[2][2] = {{0.f, 0.f}, {0.f, 0.f}};

    for (int kt = 0; kt < nkt; kt++) {
        if (kt + 1 < nkt) {
            attn_load_kv(Kb[(kt + 1) & 1], Vb[(kt + 1) & 1], b, h, kt + 1, tid);
            CP_COMMIT();
            CP_WAIT1();
        } else {
            CP_WAIT0();
        }
        __syncthreads();
        const __half* Ks = Kb[kt & 1];
        const __half* Vs = Vb[kt & 1];

        const bool active = (kt * 64 <= qr + 31);
        if (active) {
            const bool diag = ((kt + 1) * 64 > qr);

            uint32_t vb[4][4][4];     // [ks][d4][frag]
            {
                const int lt = lane >> 3, lr = lane & 7;
                #pragma unroll
                for (int ks = 0; ks < 4; ks++) {
                    const int vrow = ks * 16 + (lt & 1) * 8 + lr;
                    const int vcb  = (lt >> 1) * 8;
                    #pragma unroll
                    for (int d4 = 0; d4 < 4; d4++)
                        ldmx4t(vb[ks][d4], sptr(Vs + vrow * VW + vcb + d4 * 16));
                }
            }

            #pragma unroll
            for (int s = 0; s < 2; s++) {
                float sacc[8][4];
                #pragma unroll
                for (int ni = 0; ni < 8; ni++)
                    #pragma unroll
                    for (int j = 0; j < 4; j++) sacc[ni][j] = 0.f;

                #pragma unroll
                for (int ks = 0; ks < 4; ks++) {
                    const int co = ks * 16 + 4 * tig;
                    #pragma unroll
                    for (int ni = 0; ni < 8; ni++) {
                        uint2 bb = *(const uint2*)&Ks[(ni * 8 + g) * KW + co];
                        uint32_t bfr[2] = { bb.x, bb.y };
                        mma16(sacc[ni], qf[s][ks], bfr);
                    }
                }

                const int rA = qr + s * 16 + g, rB = rA + 8;
                if (diag) {
                    #pragma unroll
                    for (int ni = 0; ni < 8; ni++) {
                        const int c0 = kt * 64 + ni * 8 + 2 * tig;
                        if (c0 > rA)     sacc[ni][0] = -1e30f;
                        if (c0 + 1 > rA) sacc[ni][1] = -1e30f;
                        if (c0 > rB)     sacc[ni][2] = -1e30f;
                        if (c0 + 1 > rB) sacc[ni][3] = -1e30f;
                    }
                }

                float t0 = -1e30f, t1 = -1e30f;
                #pragma unroll
                for (int ni = 0; ni < 8; ni++) {
                    t0 = fmaxf(t0, fmaxf(sacc[ni][0], sacc[ni][1]));
                    t1 = fmaxf(t1, fmaxf(sacc[ni][2], sacc[ni][3]));
                }
                t0 = fmaxf(t0, __shfl_xor_sync(0xffffffffu, t0, 1));
                t0 = fmaxf(t0, __shfl_xor_sync(0xffffffffu, t0, 2));
                t1 = fmaxf(t1, __shfl_xor_sync(0xffffffffu, t1, 1));
                t1 = fmaxf(t1, __shfl_xor_sync(0xffffffffu, t1, 2));

                const float nm0 = fmaxf(mm[s][0], t0), nm1 = fmaxf(mm[s][1], t1);
                const float cr0 = __expf(mm[s][0] - nm0), cr1 = __expf(mm[s][1] - nm1);
                ll[s][0] *= cr0; ll[s][1] *= cr1;
                #pragma unroll
                for (int ni = 0; ni < 8; ni++) {
                    oacc[s][ni][0] *= cr0; oacc[s][ni][1] *= cr0;
                    oacc[s][ni][2] *= cr1; oacc[s][ni][3] *= cr1;
                }

                float s0 = 0.f, s1 = 0.f;
                #pragma unroll
                for (int ni = 0; ni < 8; ni++) {
                    sacc[ni][0] = __expf(sacc[ni][0] - nm0);
                    sacc[ni][1] = __expf(sacc[ni][1] - nm0);
                    sacc[ni][2] = __expf(sacc[ni][2] - nm1);
                    sacc[ni][3] = __expf(sacc[ni][3] - nm1);
                    s0 += sacc[ni][0] + sacc[ni][1];
                    s1 += sacc[ni][2] + sacc[ni][3];
                }
                s0 += __shfl_xor_sync(0xffffffffu, s0, 1);
                s0 += __shfl_xor_sync(0xffffffffu, s0, 2);
                s1 += __shfl_xor_sync(0xffffffffu, s1, 1);
                s1 += __shfl_xor_sync(0xffffffffu, s1, 2);
                ll[s][0] += s0; ll[s][1] += s1;
                mm[s][0] = nm0; mm[s][1] = nm1;

                #pragma unroll
                for (int ks = 0; ks < 4; ks++) {
                    __half2 a0 = __floats2half2_rn(sacc[2*ks][0],   sacc[2*ks][1]);
                    __half2 a1 = __floats2half2_rn(sacc[2*ks][2],   sacc[2*ks][3]);
                    __half2 a2 = __floats2half2_rn(sacc[2*ks+1][0], sacc[2*ks+1][1]);
                    __half2 a3 = __floats2half2_rn(sacc[2*ks+1][2], sacc[2*ks+1][3]);
                    uint32_t a[4] = { *(uint32_t*)&a0, *(uint32_t*)&a1,
                                      *(uint32_t*)&a2, *(uint32_t*)&a3 };
                    #pragma unroll
                    for (int d4 = 0; d4 < 4; d4++) {
                        mma16(oacc[s][2 * d4],     a, &vb[ks][d4][0]);
                        mma16(oacc[s][2 * d4 + 1], a, &vb[ks][d4][2]);
                    }
                }
            }
        }
        __syncthreads();
    }

    #pragma unroll
    for (int s = 0; s < 2; s++) {
        const float inv0 = 1.f / ll[s][0], inv1 = 1.f / ll[s][1];
        const size_t ob = ((size_t)(b * SEQ + qr + s * 16 + g)) * DIM + h * HD;
        #pragma unroll
        for (int ni = 0; ni < 8; ni++) {
            const int c = ni * 8 + 2 * tig;
            *(__half2*)&g_att[ob + c] =
                __floats2half2_rn(oacc[s][ni][0] * inv0, oacc[s][ni][1] * inv0);
            *(__half2*)&g_att[ob + (size_t)8 * DIM + c] =
                __floats2half2_rn(oacc[s][ni][2] * inv1, oacc[s][ni][3] * inv1);
        }
    }
}

// ---------------------------------------------------------------------------
extern "C" void kernel_launch(void* const* d_in, const int* in_sizes, int n_in,
                              void* d_out, int out_size) {
    const float* x     = (const float*)d_in[0];
    const float* w_qkv = (const float*)d_in[1];
    const float* b_qkv = (const float*)d_in[2];
    const float* w_out = (const float*)d_in[3];
    const float* b_out = (const float*)d_in[4];
    float* out = (float*)d_out;

    __half* qkv; cudaGetSymbolAddress((void**)&qkv, g_qkv);
    __half* att; cudaGetSymbolAddress((void**)&att, g_att);
    __half* xa;  cudaGetSymbolAddress((void**)&xa,  g_xa);
    __half* wqT; cudaGetSymbolAddress((void**)&wqT, g_wqkvT);
    __half* woT; cudaGetSymbolAddress((void**)&woT, g_woutT);
    float*  bqp; cudaGetSymbolAddress((void**)&bqp, g_bqkvp);

    cudaFuncSetAttribute(hgemm<true>,
                         cudaFuncAttributeMaxDynamicSharedMemorySize, GEMM_SMEM);
    cudaFuncSetAttribute(hgemm<false>,
                         cudaFuncAttributeMaxDynamicSharedMemorySize, GEMM_SMEM);
    cudaFuncSetAttribute(attn_fp16,
                         cudaFuncAttributeMaxDynamicSharedMemorySize, ATTN_SMEM);

    // --- pre-pass ---
    prep_x<<<(ROWS * DIM / 16) / 256, 256>>>(x, b_qkv);
    prep_w<true><<<dim3(DIM / 32, 3 * DIM / 32), dim3(16, 16)>>>(w_qkv, wqT, 3 * DIM);
    prep_w<false><<<dim3(DIM / 32, DIM / 32), dim3(16, 16)>>>(w_out, woT, DIM);

    // 1) QKV projection (fp16 mma, 2 CTAs/SM)
    {
        dim3 grid(3 * DIM / 128, ROWS / 128);
        hgemm<true><<<grid, 256, GEMM_SMEM>>>(xa, wqT, bqp, qkv, 3 * DIM);
    }
    // 2) causal multi-head attention (fp16 mma flash, P in registers)
    {
        dim3 grid(SEQ / AQT, HEADS, BATCH);
        attn_fp16<<<grid, 256, ATTN_SMEM>>>();
    }
    // 3) output projection (fp16 mma, fp32 out)
    {
        dim3 grid(DIM / 128, ROWS / 128);
        hgemm<false><<<grid, 256, GEMM_SMEM>>>(att, woT, b_out, out, DIM);
    }
}

// round 11
// speedup vs baseline: 8.7352x; 1.1271x over previous
#include <cuda_runtime.h>
#include <cuda_fp16.h>
#include <cstdint>

#define BATCH 4
#define SEQ   2048
#define DIM   1024
#define HEADS 16
#define HD    64
#define ROWS (BATCH * SEQ)        // 8192

// Scratch (allocation-free rule: device globals), fp16 operand space
__device__ __half g_qkv[(size_t)ROWS * 3 * DIM];   // qkv, σ-permuted cols
__device__ __half g_att[(size_t)ROWS * DIM];       // attention out, σ-slot cols
__device__ __half g_xa[(size_t)ROWS * DIM];        // x, σ-permuted cols
__device__ __half g_wqkvT[(size_t)(3 * DIM) * DIM];// w_qkv^T, k+n σ-permuted
__device__ __half g_woutT[(size_t)DIM * DIM];      // w_out^T, k σ-permuted
__device__ float  g_bqkvp[3 * DIM];                // σ-permuted bias (fp32)

// ---------------------------------------------------------------------------
// helpers
// ---------------------------------------------------------------------------
__device__ __forceinline__ int sig16(int w) {          // w in [0,16)
    return 2 * (w >> 2) + (w & 1) + 8 * ((w >> 1) & 1);
}
__device__ __forceinline__ int sig(int s) { return (s & ~15) | sig16(s & 15); }

__device__ __forceinline__ void mma16(float* c, const uint32_t* a, const uint32_t* b) {
    asm volatile(
        "mma.sync.aligned.m16n8k16.row.col.f32.f16.f16.f32 "
        "{%0,%1,%2,%3}, {%4,%5,%6,%7}, {%8,%9}, {%0,%1,%2,%3};"
        : "+f"(c[0]), "+f"(c[1]), "+f"(c[2]), "+f"(c[3])
        : "r"(a[0]), "r"(a[1]), "r"(a[2]), "r"(a[3]), "r"(b[0]), "r"(b[1]));
}
__device__ __forceinline__ void ldmx4t(uint32_t* r, uint32_t addr) {
    asm volatile("ldmatrix.sync.aligned.m8n8.x4.trans.shared.b16 "
                 "{%0,%1,%2,%3}, [%4];"
                 : "=r"(r[0]), "=r"(r[1]), "=r"(r[2]), "=r"(r[3]) : "r"(addr));
}
__device__ __forceinline__ uint32_t sptr(const void* p) {
    return (uint32_t)__cvta_generic_to_shared(p);
}
__device__ __forceinline__ void cp16(uint32_t s, const void* g) {
    asm volatile("cp.async.ca.shared.global [%0], [%1], 16;" :: "r"(s), "l"(g));
}
#define CP_COMMIT() asm volatile("cp.async.commit_group;")
#define CP_WAIT0()  asm volatile("cp.async.wait_group 0;")
#define CP_WAIT1()  asm volatile("cp.async.wait_group 1;")

// ---------------------------------------------------------------------------
// Pre-pass kernels (fp32 -> fp16, σ-permute, transpose weights)
// ---------------------------------------------------------------------------
__global__ __launch_bounds__(256)
void prep_x(const float* __restrict__ x, const float* __restrict__ bq) {
    const size_t base = ((size_t)blockIdx.x * 256 + threadIdx.x) * 16;
    float v[16];
    #pragma unroll
    for (int i = 0; i < 16; i += 4) *(float4*)&v[i] = *(const float4*)&x[base + i];
    __half2 h[8];
    #pragma unroll
    for (int u = 0; u < 4; u++) {
        h[2 * u]     = __floats2half2_rn(v[2 * u],     v[2 * u + 1]);
        h[2 * u + 1] = __floats2half2_rn(v[2 * u + 8], v[2 * u + 9]);
    }
    *(uint4*)&g_xa[base]     = *(uint4*)&h[0];
    *(uint4*)&g_xa[base + 8] = *(uint4*)&h[4];
    if (blockIdx.x < 12) {
        const int s = blockIdx.x * 256 + threadIdx.x;
        g_bqkvp[s] = bq[sig(s)];
    }
}

template<bool PERMN>
__global__ void prep_w(const float* __restrict__ src, __half* __restrict__ dst, int N) {
    __shared__ float tile[32][33];
    const int tx = threadIdx.x, ty = threadIdx.y;       // 16 x 16
    const int kb = blockIdx.x * 32, nb = blockIdx.y * 32;
    tile[ty][tx]           = src[(size_t)(kb + ty) * N + nb + tx];
    tile[ty][tx + 16]      = src[(size_t)(kb + ty) * N + nb + tx + 16];
    tile[ty + 16][tx]      = src[(size_t)(kb + ty + 16) * N + nb + tx];
    tile[ty + 16][tx + 16] = src[(size_t)(kb + ty + 16) * N + nb + tx + 16];
    __syncthreads();
    const int s  = 2 * tx;
    const int t0 = (s & 16) | sig16(s & 15);
    #pragma unroll
    for (int i = 0; i < 2; i++) {
        const int ny = ty + 16 * i;
        const int nn = PERMN ? ((ny & ~15) | sig16(ny & 15)) : ny;
        __half2 h = __floats2half2_rn(tile[t0][nn], tile[t0 + 1][nn]);
        *(__half2*)&dst[(size_t)(nb + ny) * DIM + kb + s] = h;
    }
}

// ---------------------------------------------------------------------------
// FP16 MMA GEMM: block 128x128, BK=64, 256 thr (8 warps 2x4), warp 64x32.
// 2 CTAs/SM. Prefetch issued AFTER barrier (race-free double buffer).
// ---------------------------------------------------------------------------
#define GKW 80
#define GA_H (128 * GKW)
#define GB_H (128 * GKW)
#define GSTG_H (GA_H + GB_H)
#define GEMM_SMEM (2 * GSTG_H * 2)          // 81920 B

__device__ __forceinline__ void gemm_load(__half* stage,
                                          const __half* __restrict__ A,
                                          const __half* __restrict__ B,
                                          int bm, int bn, int k0, int tid) {
    #pragma unroll
    for (int i = 0; i < 4; i++) {
        int t = tid + i * 256;              // 0..1023
        int row = t >> 3, c = t & 7;
        cp16(sptr(stage + row * GKW + c * 8), A + (size_t)(bm + row) * DIM + k0 + c * 8);
        cp16(sptr(stage + GA_H + row * GKW + c * 8), B + (size_t)(bn + row) * DIM + k0 + c * 8);
    }
}

template<bool HALF_OUT>
__global__ __launch_bounds__(256, 2)
void hgemm(const __half* __restrict__ A, const __half* __restrict__ B,
           const float* __restrict__ bias, void* __restrict__ Cv, int N) {
    extern __shared__ __half smh[];
    const int tid  = threadIdx.x;
    const int lane = tid & 31;
    const int wid  = tid >> 5;
    const int g    = lane >> 2;
    const int tig  = lane & 3;
    const int wm   = wid >> 2;          // 0..1
    const int wn   = wid & 3;           // 0..3
    const int bm   = blockIdx.y * 128;
    const int bn   = blockIdx.x * 128;

    float acc[4][4][4];
    #pragma unroll
    for (int mi = 0; mi < 4; mi++)
        #pragma unroll
        for (int ni = 0; ni < 4; ni++)
            #pragma unroll
            for (int j = 0; j < 4; j++) acc[mi][ni][j] = 0.f;

    constexpr int NT = DIM / 64;        // 16 k-tiles

    gemm_load(smh, A, B, bm, bn, 0, tid);
    CP_COMMIT();

    for (int t = 0; t < NT; t++) {
        CP_WAIT0();                       // stage t resident
        __syncthreads();                  // all warps done with buffer t^1
        if (t + 1 < NT) {                 // safe to overwrite it now
            gemm_load(smh + ((t + 1) & 1) * GSTG_H, A, B, bm, bn, (t + 1) * 64, tid);
            CP_COMMIT();
        }
        const __half* As = smh + (t & 1) * GSTG_H;
        const __half* Bs = As + GA_H;

        #pragma unroll
        for (int ks = 0; ks < 4; ks++) {
            const int co = ks * 16 + 4 * tig;
            uint32_t a[4][4], b[4][2];
            #pragma unroll
            for (int mi = 0; mi < 4; mi++) {
                const int m = wm * 64 + mi * 16 + g;
                uint2 lo = *(const uint2*)&As[m * GKW + co];
                uint2 hi = *(const uint2*)&As[(m + 8) * GKW + co];
                a[mi][0] = lo.x; a[mi][2] = lo.y;
                a[mi][1] = hi.x; a[mi][3] = hi.y;
            }
            #pragma unroll
            for (int ni = 0; ni < 4; ni++) {
                const int n = wn * 32 + ni * 8 + g;
                uint2 bb = *(const uint2*)&Bs[n * GKW + co];
                b[ni][0] = bb.x; b[ni][1] = bb.y;
            }
            #pragma unroll
            for (int mi = 0; mi < 4; mi++)
                #pragma unroll
                for (int ni = 0; ni < 4; ni++)
                    mma16(acc[mi][ni], a[mi], b[ni]);
        }
        __syncthreads();
    }

    #pragma unroll
    for (int mi = 0; mi < 4; mi++) {
        const int r0 = bm + wm * 64 + mi * 16 + g;
        #pragma unroll
        for (int ni = 0; ni < 4; ni++) {
            const int col = bn + wn * 32 + ni * 8 + 2 * tig;
            const float b0 = bias[col], b1 = bias[col + 1];
            const float v00 = acc[mi][ni][0] + b0, v01 = acc[mi][ni][1] + b1;
            const float v10 = acc[mi][ni][2] + b0, v11 = acc[mi][ni][3] + b1;
            if (HALF_OUT) {
                __half* C = (__half*)Cv;
                *(__half2*)&C[(size_t)r0 * N + col]       = __floats2half2_rn(v00, v01);
                *(__half2*)&C[(size_t)(r0 + 8) * N + col] = __floats2half2_rn(v10, v11);
            } else {
                float* C = (float*)Cv;
                *(float2*)&C[(size_t)r0 * N + col]       = make_float2(v00, v01);
                *(float2*)&C[(size_t)(r0 + 8) * N + col] = make_float2(v10, v11);
            }
        }
    }
}

// ---------------------------------------------------------------------------
// FP16 MMA causal flash attention v5.
// grid = (SEQ/128, HEADS, BATCH), 128 thr = 4 warps, warp = 32 q rows.
// K fragments hoisted (loaded once, used by both m16 subtiles).
// V fragments loaded per-ks inside P·V (low register pressure -> 2 CTAs/SM).
// smem halves: K[2][64][80] | V[2][64][72]  (38912 B)
// ---------------------------------------------------------------------------
#define AQT 128
#define KW  80
#define VW  72
#define KT_H (64 * KW)
#define VT_H (64 * VW)
#define ATTN_SMEM ((2 * KT_H + 2 * VT_H) * 2)   // 38912 B

__device__ __forceinline__ void attn_load_kv(__half* Ks, __half* Vs,
                                             int b, int h, int kt, int tid) {
    const size_t base = ((size_t)(b * SEQ + kt * 64)) * (3 * DIM) + DIM + h * HD;
    #pragma unroll
    for (int i = 0; i < 4; i++) {
        int t = tid + i * 128;              // 0..511
        int row = t >> 3, c = t & 7;
        const __half* src = &g_qkv[base + (size_t)row * 3 * DIM + c * 8];
        cp16(sptr(Ks + row * KW + c * 8), src);
        cp16(sptr(Vs + row * VW + c * 8), src + DIM);
    }
}

__global__ __launch_bounds__(128)
void attn_fp16() {
    extern __shared__ __half smh[];
    __half* Kb[2] = { smh, smh + KT_H };
    __half* Vb[2] = { smh + 2 * KT_H, smh + 2 * KT_H + VT_H };

    const int qt   = gridDim.x - 1 - blockIdx.x;   // longest-first scheduling
    const int h    = blockIdx.y;
    const int b    = blockIdx.z;
    const int tid  = threadIdx.x;
    const int lane = tid & 31;
    const int wid  = tid >> 5;
    const int g    = lane >> 2;
    const int tig  = lane & 3;

    const int qr  = qt * AQT + wid * 32;
    const int nkt = qt * 2 + 2;

    attn_load_kv(Kb[0], Vb[0], b, h, 0, tid);
    CP_COMMIT();

    const __half2 qsc = __float2half2_rn(0.125f);
    uint32_t qf[2][4][4];
    #pragma unroll
    for (int s = 0; s < 2; s++) {
        const size_t r0 = ((size_t)(b * SEQ + qr + s * 16 + g)) * (3 * DIM) + h * HD;
        const size_t r1 = r0 + (size_t)8 * 3 * DIM;
        #pragma unroll
        for (int ks = 0; ks < 4; ks++) {
            uint2 lo = *(const uint2*)&g_qkv[r0 + ks * 16 + 4 * tig];
            uint2 hi = *(const uint2*)&g_qkv[r1 + ks * 16 + 4 * tig];
            __half2 t;
            t = __hmul2(*(__half2*)&lo.x, qsc); qf[s][ks][0] = *(uint32_t*)&t;
            t = __hmul2(*(__half2*)&hi.x, qsc); qf[s][ks][1] = *(uint32_t*)&t;
            t = __hmul2(*(__half2*)&lo.y, qsc); qf[s][ks][2] = *(uint32_t*)&t;
            t = __hmul2(*(__half2*)&hi.y, qsc); qf[s][ks][3] = *(uint32_t*)&t;
        }
    }

    float oacc[2][8][4];
    #pragma unroll
    for (int s = 0; s < 2; s++)
        #pragma unroll
        for (int ni = 0; ni < 8; ni++)
            #pragma unroll
            for (int j = 0; j < 4; j++) oacc[s][ni][j] = 0.f;
    float mm[2][2] = {{-1e30f, -1e30f}, {-1e30f, -1e30f}};
    float ll[2][2] = {{0.f, 0.f}, {0.f, 0.f}};

    for (int kt = 0; kt < nkt; kt++) {
        if (kt + 1 < nkt) {
            attn_load_kv(Kb[(kt + 1) & 1], Vb[(kt + 1) & 1], b, h, kt + 1, tid);
            CP_COMMIT();
            CP_WAIT1();
        } else {
            CP_WAIT0();
        }
        __syncthreads();
        const __half* Ks = Kb[kt & 1];
        const __half* Vs = Vb[kt & 1];

        const bool active = (kt * 64 <= qr + 31);
        if (active) {
            const bool diag = ((kt + 1) * 64 > qr);

            // ---- S = Q K^T : K frags loaded ONCE, used by both subtiles ----
            float sacc[2][8][4];
            #pragma unroll
            for (int s = 0; s < 2; s++)
                #pragma unroll
                for (int ni = 0; ni < 8; ni++)
                    #pragma unroll
                    for (int j = 0; j < 4; j++) sacc[s][ni][j] = 0.f;

            #pragma unroll
            for (int ks = 0; ks < 4; ks++) {
                const int co = ks * 16 + 4 * tig;
                #pragma unroll
                for (int ni = 0; ni < 8; ni++) {
                    uint2 bb = *(const uint2*)&Ks[(ni * 8 + g) * KW + co];
                    uint32_t bfr[2] = { bb.x, bb.y };
                    mma16(sacc[0][ni], qf[0][ks], bfr);
                    mma16(sacc[1][ni], qf[1][ks], bfr);
                }
            }

            // ---- per-subtile: mask, softmax, pack P to half2 ----
            uint32_t pa[2][4][4];
            #pragma unroll
            for (int s = 0; s < 2; s++) {
                const int rA = qr + s * 16 + g, rB = rA + 8;
                if (diag) {
                    #pragma unroll
                    for (int ni = 0; ni < 8; ni++) {
                        const int c0 = kt * 64 + ni * 8 + 2 * tig;
                        if (c0 > rA)     sacc[s][ni][0] = -1e30f;
                        if (c0 + 1 > rA) sacc[s][ni][1] = -1e30f;
                        if (c0 > rB)     sacc[s][ni][2] = -1e30f;
                        if (c0 + 1 > rB) sacc[s][ni][3] = -1e30f;
                    }
                }

                float t0 = -1e30f, t1 = -1e30f;
                #pragma unroll
                for (int ni = 0; ni < 8; ni++) {
                    t0 = fmaxf(t0, fmaxf(sacc[s][ni][0], sacc[s][ni][1]));
                    t1 = fmaxf(t1, fmaxf(sacc[s][ni][2], sacc[s][ni][3]));
                }
                t0 = fmaxf(t0, __shfl_xor_sync(0xffffffffu, t0, 1));
                t0 = fmaxf(t0, __shfl_xor_sync(0xffffffffu, t0, 2));
                t1 = fmaxf(t1, __shfl_xor_sync(0xffffffffu, t1, 1));
                t1 = fmaxf(t1, __shfl_xor_sync(0xffffffffu, t1, 2));

                const float nm0 = fmaxf(mm[s][0], t0), nm1 = fmaxf(mm[s][1], t1);
                const float cr0 = __expf(mm[s][0] - nm0), cr1 = __expf(mm[s][1] - nm1);
                ll[s][0] *= cr0; ll[s][1] *= cr1;
                #pragma unroll
                for (int ni = 0; ni < 8; ni++) {
                    oacc[s][ni][0] *= cr0; oacc[s][ni][1] *= cr0;
                    oacc[s][ni][2] *= cr1; oacc[s][ni][3] *= cr1;
                }

                float s0 = 0.f, s1 = 0.f;
                #pragma unroll
                for (int ni = 0; ni < 8; ni++) {
                    sacc[s][ni][0] = __expf(sacc[s][ni][0] - nm0);
                    sacc[s][ni][1] = __expf(sacc[s][ni][1] - nm0);
                    sacc[s][ni][2] = __expf(sacc[s][ni][2] - nm1);
                    sacc[s][ni][3] = __expf(sacc[s][ni][3] - nm1);
                    s0 += sacc[s][ni][0] + sacc[s][ni][1];
                    s1 += sacc[s][ni][2] + sacc[s][ni][3];
                }
                s0 += __shfl_xor_sync(0xffffffffu, s0, 1);
                s0 += __shfl_xor_sync(0xffffffffu, s0, 2);
                s1 += __shfl_xor_sync(0xffffffffu, s1, 1);
                s1 += __shfl_xor_sync(0xffffffffu, s1, 2);
                ll[s][0] += s0; ll[s][1] += s1;
                mm[s][0] = nm0; mm[s][1] = nm1;

                #pragma unroll
                for (int ks = 0; ks < 4; ks++) {
                    __half2 a0 = __floats2half2_rn(sacc[s][2*ks][0],   sacc[s][2*ks][1]);
                    __half2 a1 = __floats2half2_rn(sacc[s][2*ks][2],   sacc[s][2*ks][3]);
                    __half2 a2 = __floats2half2_rn(sacc[s][2*ks+1][0], sacc[s][2*ks+1][1]);
                    __half2 a3 = __floats2half2_rn(sacc[s][2*ks+1][2], sacc[s][2*ks+1][3]);
                    pa[s][ks][0] = *(uint32_t*)&a0;
                    pa[s][ks][1] = *(uint32_t*)&a1;
                    pa[s][ks][2] = *(uint32_t*)&a2;
                    pa[s][ks][3] = *(uint32_t*)&a3;
                }
            }

            // ---- O += P @ V : V frags per-ks (low live registers) ----
            const int lt = lane >> 3, lr = lane & 7;
            #pragma unroll
            for (int ks = 0; ks < 4; ks++) {
                uint32_t vb[4][4];
                const int vrow = ks * 16 + (lt & 1) * 8 + lr;
                const int vcb  = (lt >> 1) * 8;
                #pragma unroll
                for (int d4 = 0; d4 < 4; d4++)
                    ldmx4t(vb[d4], sptr(Vs + vrow * VW + vcb + d4 * 16));
                #pragma unroll
                for (int s = 0; s < 2; s++) {
                    #pragma unroll
                    for (int d4 = 0; d4 < 4; d4++) {
                        mma16(oacc[s][2 * d4],     pa[s][ks], &vb[d4][0]);
                        mma16(oacc[s][2 * d4 + 1], pa[s][ks], &vb[d4][2]);
                    }
                }
            }
        }
        __syncthreads();
    }

    // ---- epilogue: O/l -> g_att (fp16, σ-slot cols) ----
    #pragma unroll
    for (int s = 0; s < 2; s++) {
        const float inv0 = 1.f / ll[s][0], inv1 = 1.f / ll[s][1];
        const size_t ob = ((size_t)(b * SEQ + qr + s * 16 + g)) * DIM + h * HD;
        #pragma unroll
        for (int ni = 0; ni < 8; ni++) {
            const int c = ni * 8 + 2 * tig;
            *(__half2*)&g_att[ob + c] =
                __floats2half2_rn(oacc[s][ni][0] * inv0, oacc[s][ni][1] * inv0);
            *(__half2*)&g_att[ob + (size_t)8 * DIM + c] =
                __floats2half2_rn(oacc[s][ni][2] * inv1, oacc[s][ni][3] * inv1);
        }
    }
}

// ---------------------------------------------------------------------------
extern "C" void kernel_launch(void* const* d_in, const int* in_sizes, int n_in,
                              void* d_out, int out_size) {
    const float* x     = (const float*)d_in[0];
    const float* w_qkv = (const float*)d_in[1];
    const float* b_qkv = (const float*)d_in[2];
    const float* w_out = (const float*)d_in[3];
    const float* b_out = (const float*)d_in[4];
    float* out = (float*)d_out;

    __half* qkv; cudaGetSymbolAddress((void**)&qkv, g_qkv);
    __half* att; cudaGetSymbolAddress((void**)&att, g_att);
    __half* xa;  cudaGetSymbolAddress((void**)&xa,  g_xa);
    __half* wqT; cudaGetSymbolAddress((void**)&wqT, g_wqkvT);
    __half* woT; cudaGetSymbolAddress((void**)&woT, g_woutT);
    float*  bqp; cudaGetSymbolAddress((void**)&bqp, g_bqkvp);

    cudaFuncSetAttribute(hgemm<true>,
                         cudaFuncAttributeMaxDynamicSharedMemorySize, GEMM_SMEM);
    cudaFuncSetAttribute(hgemm<false>,
                         cudaFuncAttributeMaxDynamicSharedMemorySize, GEMM_SMEM);
    cudaFuncSetAttribute(attn_fp16,
                         cudaFuncAttributeMaxDynamicSharedMemorySize, ATTN_SMEM);

    // --- pre-pass ---
    prep_x<<<(ROWS * DIM / 16) / 256, 256>>>(x, b_qkv);
    prep_w<true><<<dim3(DIM / 32, 3 * DIM / 32), dim3(16, 16)>>>(w_qkv, wqT, 3 * DIM);
    prep_w<false><<<dim3(DIM / 32, DIM / 32), dim3(16, 16)>>>(w_out, woT, DIM);

    // 1) QKV projection (fp16 mma, 2 CTAs/SM)
    {
        dim3 grid(3 * DIM / 128, ROWS / 128);
        hgemm<true><<<grid, 256, GEMM_SMEM>>>(xa, wqT, bqp, qkv, 3 * DIM);
    }
    // 2) causal multi-head attention (fp16 mma flash, hoisted K frags, 2 CTAs/SM)
    {
        dim3 grid(SEQ / AQT, HEADS, BATCH);
        attn_fp16<<<grid, 128, ATTN_SMEM>>>();
    }
    // 3) output projection (fp16 mma, fp32 out)
    {
        dim3 grid(DIM / 128, ROWS / 128);
        hgemm<false><<<grid, 256, GEMM_SMEM>>>(att, woT, b_out, out, DIM);
    }
}

// round 12
// speedup vs baseline: 8.9928x; 1.0295x over previous
#include <cuda_runtime.h>
#include <cuda_fp16.h>
#include <cstdint>

#define BATCH 4
#define SEQ   2048
#define DIM   1024
#define HEADS 16
#define HD    64
#define ROWS (BATCH * SEQ)        // 8192

// Scratch (allocation-free rule: device globals), fp16 operand space
__device__ __half g_qkv[(size_t)ROWS * 3 * DIM];   // qkv, σ-permuted cols
__device__ __half g_att[(size_t)ROWS * DIM];       // attention out, σ-slot cols
__device__ __half g_xa[(size_t)ROWS * DIM];        // x, σ-permuted cols
__device__ __half g_wqkvT[(size_t)(3 * DIM) * DIM];// w_qkv^T, k+n σ-permuted
__device__ __half g_woutT[(size_t)DIM * DIM];      // w_out^T, k σ-permuted
__device__ float  g_bqkvp[3 * DIM];                // σ-permuted bias (fp32)

// ---------------------------------------------------------------------------
// helpers
// ---------------------------------------------------------------------------
__device__ __forceinline__ int sig16(int w) {          // w in [0,16)
    return 2 * (w >> 2) + (w & 1) + 8 * ((w >> 1) & 1);
}
__device__ __forceinline__ int sig(int s) { return (s & ~15) | sig16(s & 15); }

__device__ __forceinline__ void mma16(float* c, const uint32_t* a, const uint32_t* b) {
    asm volatile(
        "mma.sync.aligned.m16n8k16.row.col.f32.f16.f16.f32 "
        "{%0,%1,%2,%3}, {%4,%5,%6,%7}, {%8,%9}, {%0,%1,%2,%3};"
        : "+f"(c[0]), "+f"(c[1]), "+f"(c[2]), "+f"(c[3])
        : "r"(a[0]), "r"(a[1]), "r"(a[2]), "r"(a[3]), "r"(b[0]), "r"(b[1]));
}
__device__ __forceinline__ void ldmx4t(uint32_t* r, uint32_t addr) {
    asm volatile("ldmatrix.sync.aligned.m8n8.x4.trans.shared.b16 "
                 "{%0,%1,%2,%3}, [%4];"
                 : "=r"(r[0]), "=r"(r[1]), "=r"(r[2]), "=r"(r[3]) : "r"(addr));
}
__device__ __forceinline__ uint32_t sptr(const void* p) {
    return (uint32_t)__cvta_generic_to_shared(p);
}
__device__ __forceinline__ void cp16(uint32_t s, const void* g) {
    asm volatile("cp.async.ca.shared.global [%0], [%1], 16;" :: "r"(s), "l"(g));
}
#define CP_COMMIT() asm volatile("cp.async.commit_group;")
#define CP_WAIT0()  asm volatile("cp.async.wait_group 0;")

// ---------------------------------------------------------------------------
// Fused pre-pass kernel: x convert+permute (+bias), both weight transposes.
// Block-range dispatch over a 1D grid of 256-thread blocks.
//   [0, 2048)        : prep_x  (one block = 4096 elements)
//   [2048, 5120)     : w_qkv^T tiles (96 nb x 32 kb)
//   [5120, 6144)     : w_out^T tiles (32 nb x 32 kb)
// ---------------------------------------------------------------------------
__device__ __forceinline__ void prep_w_tile(const float* __restrict__ src,
                                            __half* __restrict__ dst,
                                            int N, int kb, int nb, bool permn,
                                            int tid) {
    __shared__ float tile[32][33];
    const int tx = tid & 15, ty = tid >> 4;
    tile[ty][tx]           = src[(size_t)(kb + ty) * N + nb + tx];
    tile[ty][tx + 16]      = src[(size_t)(kb + ty) * N + nb + tx + 16];
    tile[ty + 16][tx]      = src[(size_t)(kb + ty + 16) * N + nb + tx];
    tile[ty + 16][tx + 16] = src[(size_t)(kb + ty + 16) * N + nb + tx + 16];
    __syncthreads();
    const int s  = 2 * tx;
    const int t0 = (s & 16) | sig16(s & 15);
    #pragma unroll
    for (int i = 0; i < 2; i++) {
        const int ny = ty + 16 * i;
        const int nn = permn ? ((ny & ~15) | sig16(ny & 15)) : ny;
        __half2 h = __floats2half2_rn(tile[t0][nn], tile[t0 + 1][nn]);
        *(__half2*)&dst[(size_t)(nb + ny) * DIM + kb + s] = h;
    }
}

__global__ __launch_bounds__(256)
void prep_all(const float* __restrict__ x, const float* __restrict__ wq,
              const float* __restrict__ wo, const float* __restrict__ bq) {
    const int bid = blockIdx.x;
    const int tid = threadIdx.x;
    if (bid < 2048) {
        const size_t base = ((size_t)bid * 256 + tid) * 16;
        float v[16];
        #pragma unroll
        for (int i = 0; i < 16; i += 4) *(float4*)&v[i] = *(const float4*)&x[base + i];
        __half2 h[8];
        #pragma unroll
        for (int u = 0; u < 4; u++) {
            h[2 * u]     = __floats2half2_rn(v[2 * u],     v[2 * u + 1]);
            h[2 * u + 1] = __floats2half2_rn(v[2 * u + 8], v[2 * u + 9]);
        }
        *(uint4*)&g_xa[base]     = *(uint4*)&h[0];
        *(uint4*)&g_xa[base + 8] = *(uint4*)&h[4];
        if (bid < 12) {
            const int s = bid * 256 + tid;
            g_bqkvp[s] = bq[sig(s)];
        }
    } else if (bid < 2048 + 3072) {
        const int b2 = bid - 2048;
        prep_w_tile(wq, g_wqkvT, 3 * DIM, (b2 & 31) * 32, (b2 >> 5) * 32, true, tid);
    } else {
        const int b3 = bid - 5120;
        prep_w_tile(wo, g_woutT, DIM, (b3 & 31) * 32, (b3 >> 5) * 32, false, tid);
    }
}

// ---------------------------------------------------------------------------
// FP16 MMA GEMM: block 128x128, BK=64, 256 thr (8 warps 2x4), warp 64x32.
// 2 CTAs/SM. ONE barrier per k-tile (prefetch after barrier; race-free).
// ---------------------------------------------------------------------------
#define GKW 80
#define GA_H (128 * GKW)
#define GB_H (128 * GKW)
#define GSTG_H (GA_H + GB_H)
#define GEMM_SMEM (2 * GSTG_H * 2)          // 81920 B

__device__ __forceinline__ void gemm_load(__half* stage,
                                          const __half* __restrict__ A,
                                          const __half* __restrict__ B,
                                          int bm, int bn, int k0, int tid) {
    #pragma unroll
    for (int i = 0; i < 4; i++) {
        int t = tid + i * 256;              // 0..1023
        int row = t >> 3, c = t & 7;
        cp16(sptr(stage + row * GKW + c * 8), A + (size_t)(bm + row) * DIM + k0 + c * 8);
        cp16(sptr(stage + GA_H + row * GKW + c * 8), B + (size_t)(bn + row) * DIM + k0 + c * 8);
    }
}

template<bool HALF_OUT>
__global__ __launch_bounds__(256, 2)
void hgemm(const __half* __restrict__ A, const __half* __restrict__ B,
           const float* __restrict__ bias, void* __restrict__ Cv, int N) {
    extern __shared__ __half smh[];
    const int tid  = threadIdx.x;
    const int lane = tid & 31;
    const int wid  = tid >> 5;
    const int g    = lane >> 2;
    const int tig  = lane & 3;
    const int wm   = wid >> 2;          // 0..1
    const int wn   = wid & 3;           // 0..3
    const int bm   = blockIdx.y * 128;
    const int bn   = blockIdx.x * 128;

    float acc[4][4][4];
    #pragma unroll
    for (int mi = 0; mi < 4; mi++)
        #pragma unroll
        for (int ni = 0; ni < 4; ni++)
            #pragma unroll
            for (int j = 0; j < 4; j++) acc[mi][ni][j] = 0.f;

    constexpr int NT = DIM / 64;        // 16 k-tiles

    gemm_load(smh, A, B, bm, bn, 0, tid);
    CP_COMMIT();

    for (int t = 0; t < NT; t++) {
        CP_WAIT0();                       // stage t resident
        __syncthreads();                  // + all warps done with prior compute
        if (t + 1 < NT) {                 // buffer t^1 free to overwrite
            gemm_load(smh + ((t + 1) & 1) * GSTG_H, A, B, bm, bn, (t + 1) * 64, tid);
            CP_COMMIT();
        }
        const __half* As = smh + (t & 1) * GSTG_H;
        const __half* Bs = As + GA_H;

        #pragma unroll
        for (int ks = 0; ks < 4; ks++) {
            const int co = ks * 16 + 4 * tig;
            uint32_t a[4][4], b[4][2];
            #pragma unroll
            for (int mi = 0; mi < 4; mi++) {
                const int m = wm * 64 + mi * 16 + g;
                uint2 lo = *(const uint2*)&As[m * GKW + co];
                uint2 hi = *(const uint2*)&As[(m + 8) * GKW + co];
                a[mi][0] = lo.x; a[mi][2] = lo.y;
                a[mi][1] = hi.x; a[mi][3] = hi.y;
            }
            #pragma unroll
            for (int ni = 0; ni < 4; ni++) {
                const int n = wn * 32 + ni * 8 + g;
                uint2 bb = *(const uint2*)&Bs[n * GKW + co];
                b[ni][0] = bb.x; b[ni][1] = bb.y;
            }
            #pragma unroll
            for (int mi = 0; mi < 4; mi++)
                #pragma unroll
                for (int ni = 0; ni < 4; ni++)
                    mma16(acc[mi][ni], a[mi], b[ni]);
        }
        // no trailing barrier: next iteration's top barrier provides the fence
    }

    #pragma unroll
    for (int mi = 0; mi < 4; mi++) {
        const int r0 = bm + wm * 64 + mi * 16 + g;
        #pragma unroll
        for (int ni = 0; ni < 4; ni++) {
            const int col = bn + wn * 32 + ni * 8 + 2 * tig;
            const float b0 = bias[col], b1 = bias[col + 1];
            const float v00 = acc[mi][ni][0] + b0, v01 = acc[mi][ni][1] + b1;
            const float v10 = acc[mi][ni][2] + b0, v11 = acc[mi][ni][3] + b1;
            if (HALF_OUT) {
                __half* C = (__half*)Cv;
                *(__half2*)&C[(size_t)r0 * N + col]       = __floats2half2_rn(v00, v01);
                *(__half2*)&C[(size_t)(r0 + 8) * N + col] = __floats2half2_rn(v10, v11);
            } else {
                float* C = (float*)Cv;
                *(float2*)&C[(size_t)r0 * N + col]       = make_float2(v00, v01);
                *(float2*)&C[(size_t)(r0 + 8) * N + col] = make_float2(v10, v11);
            }
        }
    }
}

// ---------------------------------------------------------------------------
// FP16 MMA causal flash attention v6.
// grid = (SEQ/128, HEADS, BATCH), 128 thr = 4 warps, warp = 32 q rows.
// Hoisted K frags; V frags per-ks; 2 CTAs/SM.
// ONE barrier per KV tile (prefetch moved after the barrier).
// smem halves: K[2][64][80] | V[2][64][72]  (38912 B)
// ---------------------------------------------------------------------------
#define AQT 128
#define KW  80
#define VW  72
#define KT_H (64 * KW)
#define VT_H (64 * VW)
#define ATTN_SMEM ((2 * KT_H + 2 * VT_H) * 2)   // 38912 B

__device__ __forceinline__ void attn_load_kv(__half* Ks, __half* Vs,
                                             int b, int h, int kt, int tid) {
    const size_t base = ((size_t)(b * SEQ + kt * 64)) * (3 * DIM) + DIM + h * HD;
    #pragma unroll
    for (int i = 0; i < 4; i++) {
        int t = tid + i * 128;              // 0..511
        int row = t >> 3, c = t & 7;
        const __half* src = &g_qkv[base + (size_t)row * 3 * DIM + c * 8];
        cp16(sptr(Ks + row * KW + c * 8), src);
        cp16(sptr(Vs + row * VW + c * 8), src + DIM);
    }
}

__global__ __launch_bounds__(128)
void attn_fp16() {
    extern __shared__ __half smh[];
    __half* Kb[2] = { smh, smh + KT_H };
    __half* Vb[2] = { smh + 2 * KT_H, smh + 2 * KT_H + VT_H };

    const int qt   = gridDim.x - 1 - blockIdx.x;   // longest-first scheduling
    const int h    = blockIdx.y;
    const int b    = blockIdx.z;
    const int tid  = threadIdx.x;
    const int lane = tid & 31;
    const int wid  = tid >> 5;
    const int g    = lane >> 2;
    const int tig  = lane & 3;

    const int qr  = qt * AQT + wid * 32;
    const int nkt = qt * 2 + 2;

    attn_load_kv(Kb[0], Vb[0], b, h, 0, tid);
    CP_COMMIT();

    const __half2 qsc = __float2half2_rn(0.125f);
    uint32_t qf[2][4][4];
    #pragma unroll
    for (int s = 0; s < 2; s++) {
        const size_t r0 = ((size_t)(b * SEQ + qr + s * 16 + g)) * (3 * DIM) + h * HD;
        const size_t r1 = r0 + (size_t)8 * 3 * DIM;
        #pragma unroll
        for (int ks = 0; ks < 4; ks++) {
            uint2 lo = *(const uint2*)&g_qkv[r0 + ks * 16 + 4 * tig];
            uint2 hi = *(const uint2*)&g_qkv[r1 + ks * 16 + 4 * tig];
            __half2 t;
            t = __hmul2(*(__half2*)&lo.x, qsc); qf[s][ks][0] = *(uint32_t*)&t;
            t = __hmul2(*(__half2*)&hi.x, qsc); qf[s][ks][1] = *(uint32_t*)&t;
            t = __hmul2(*(__half2*)&lo.y, qsc); qf[s][ks][2] = *(uint32_t*)&t;
            t = __hmul2(*(__half2*)&hi.y, qsc); qf[s][ks][3] = *(uint32_t*)&t;
        }
    }

    float oacc[2][8][4];
    #pragma unroll
    for (int s = 0; s < 2; s++)
        #pragma unroll
        for (int ni = 0; ni < 8; ni++)
            #pragma unroll
            for (int j = 0; j < 4; j++) oacc[s][ni][j] = 0.f;
    float mm[2][2] = {{-1e30f, -1e30f}, {-1e30f, -1e30f}};
    float ll[2][2] = {{0.f, 0.f}, {0.f, 0.f}};

    for (int kt = 0; kt < nkt; kt++) {
        CP_WAIT0();                       // stage kt resident
        __syncthreads();                  // + all warps done with prior tile
        if (kt + 1 < nkt) {               // buffer kt^1 free to overwrite
            attn_load_kv(Kb[(kt + 1) & 1], Vb[(kt + 1) & 1], b, h, kt + 1, tid);
            CP_COMMIT();
        }
        const __half* Ks = Kb[kt & 1];
        const __half* Vs = Vb[kt & 1];

        const bool active = (kt * 64 <= qr + 31);
        if (active) {
            const bool diag = ((kt + 1) * 64 > qr);

            // ---- S = Q K^T : K frags loaded ONCE, used by both subtiles ----
            float sacc[2][8][4];
            #pragma unroll
            for (int s = 0; s < 2; s++)
                #pragma unroll
                for (int ni = 0; ni < 8; ni++)
                    #pragma unroll
                    for (int j = 0; j < 4; j++) sacc[s][ni][j] = 0.f;

            #pragma unroll
            for (int ks = 0; ks < 4; ks++) {
                const int co = ks * 16 + 4 * tig;
                #pragma unroll
                for (int ni = 0; ni < 8; ni++) {
                    uint2 bb = *(const uint2*)&Ks[(ni * 8 + g) * KW + co];
                    uint32_t bfr[2] = { bb.x, bb.y };
                    mma16(sacc[0][ni], qf[0][ks], bfr);
                    mma16(sacc[1][ni], qf[1][ks], bfr);
                }
            }

            // ---- per-subtile: mask, softmax, pack P ----
            uint32_t pa[2][4][4];
            #pragma unroll
            for (int s = 0; s < 2; s++) {
                const int rA = qr + s * 16 + g, rB = rA + 8;
                if (diag) {
                    #pragma unroll
                    for (int ni = 0; ni < 8; ni++) {
                        const int c0 = kt * 64 + ni * 8 + 2 * tig;
                        if (c0 > rA)     sacc[s][ni][0] = -1e30f;
                        if (c0 + 1 > rA) sacc[s][ni][1] = -1e30f;
                        if (c0 > rB)     sacc[s][ni][2] = -1e30f;
                        if (c0 + 1 > rB) sacc[s][ni][3] = -1e30f;
                    }
                }

                float t0 = -1e30f, t1 = -1e30f;
                #pragma unroll
                for (int ni = 0; ni < 8; ni++) {
                    t0 = fmaxf(t0, fmaxf(sacc[s][ni][0], sacc[s][ni][1]));
                    t1 = fmaxf(t1, fmaxf(sacc[s][ni][2], sacc[s][ni][3]));
                }
                t0 = fmaxf(t0, __shfl_xor_sync(0xffffffffu, t0, 1));
                t0 = fmaxf(t0, __shfl_xor_sync(0xffffffffu, t0, 2));
                t1 = fmaxf(t1, __shfl_xor_sync(0xffffffffu, t1, 1));
                t1 = fmaxf(t1, __shfl_xor_sync(0xffffffffu, t1, 2));

                const float nm0 = fmaxf(mm[s][0], t0), nm1 = fmaxf(mm[s][1], t1);
                const float cr0 = __expf(mm[s][0] - nm0), cr1 = __expf(mm[s][1] - nm1);
                ll[s][0] *= cr0; ll[s][1] *= cr1;
                #pragma unroll
                for (int ni = 0; ni < 8; ni++) {
                    oacc[s][ni][0] *= cr0; oacc[s][ni][1] *= cr0;
                    oacc[s][ni][2] *= cr1; oacc[s][ni][3] *= cr1;
                }

                float s0 = 0.f, s1 = 0.f;
                #pragma unroll
                for (int ni = 0; ni < 8; ni++) {
                    sacc[s][ni][0] = __expf(sacc[s][ni][0] - nm0);
                    sacc[s][ni][1] = __expf(sacc[s][ni][1] - nm0);
                    sacc[s][ni][2] = __expf(sacc[s][ni][2] - nm1);
                    sacc[s][ni][3] = __expf(sacc[s][ni][3] - nm1);
                    s0 += sacc[s][ni][0] + sacc[s][ni][1];
                    s1 += sacc[s][ni][2] + sacc[s][ni][3];
                }
                s0 += __shfl_xor_sync(0xffffffffu, s0, 1);
                s0 += __shfl_xor_sync(0xffffffffu, s0, 2);
                s1 += __shfl_xor_sync(0xffffffffu, s1, 1);
                s1 += __shfl_xor_sync(0xffffffffu, s1, 2);
                ll[s][0] += s0; ll[s][1] += s1;
                mm[s][0] = nm0; mm[s][1] = nm1;

                #pragma unroll
                for (int ks = 0; ks < 4; ks++) {
                    __half2 a0 = __floats2half2_rn(sacc[s][2*ks][0],   sacc[s][2*ks][1]);
                    __half2 a1 = __floats2half2_rn(sacc[s][2*ks][2],   sacc[s][2*ks][3]);
                    __half2 a2 = __floats2half2_rn(sacc[s][2*ks+1][0], sacc[s][2*ks+1][1]);
                    __half2 a3 = __floats2half2_rn(sacc[s][2*ks+1][2], sacc[s][2*ks+1][3]);
                    pa[s][ks][0] = *(uint32_t*)&a0;
                    pa[s][ks][1] = *(uint32_t*)&a1;
                    pa[s][ks][2] = *(uint32_t*)&a2;
                    pa[s][ks][3] = *(uint32_t*)&a3;
                }
            }

            // ---- O += P @ V : V frags per-ks ----
            const int lt = lane >> 3, lr = lane & 7;
            #pragma unroll
            for (int ks = 0; ks < 4; ks++) {
                uint32_t vb[4][4];
                const int vrow = ks * 16 + (lt & 1) * 8 + lr;
                const int vcb  = (lt >> 1) * 8;
                #pragma unroll
                for (int d4 = 0; d4 < 4; d4++)
                    ldmx4t(vb[d4], sptr(Vs + vrow * VW + vcb + d4 * 16));
                #pragma unroll
                for (int s = 0; s < 2; s++) {
                    #pragma unroll
                    for (int d4 = 0; d4 < 4; d4++) {
                        mma16(oacc[s][2 * d4],     pa[s][ks], &vb[d4][0]);
                        mma16(oacc[s][2 * d4 + 1], pa[s][ks], &vb[d4][2]);
                    }
                }
            }
        }
        // no trailing barrier: next iteration's top barrier provides the fence
    }

    // ---- epilogue: O/l -> g_att (fp16, σ-slot cols) ----
    #pragma unroll
    for (int s = 0; s < 2; s++) {
        const float inv0 = 1.f / ll[s][0], inv1 = 1.f / ll[s][1];
        const size_t ob = ((size_t)(b * SEQ + qr + s * 16 + g)) * DIM + h * HD;
        #pragma unroll
        for (int ni = 0; ni < 8; ni++) {
            const int c = ni * 8 + 2 * tig;
            *(__half2*)&g_att[ob + c] =
                __floats2half2_rn(oacc[s][ni][0] * inv0, oacc[s][ni][1] * inv0);
            *(__half2*)&g_att[ob + (size_t)8 * DIM + c] =
                __floats2half2_rn(oacc[s][ni][2] * inv1, oacc[s][ni][3] * inv1);
        }
    }
}

// ---------------------------------------------------------------------------
extern "C" void kernel_launch(void* const* d_in, const int* in_sizes, int n_in,
                              void* d_out, int out_size) {
    const float* x     = (const float*)d_in[0];
    const float* w_qkv = (const float*)d_in[1];
    const float* b_qkv = (const float*)d_in[2];
    const float* w_out = (const float*)d_in[3];
    const float* b_out = (const float*)d_in[4];
    float* out = (float*)d_out;

    __half* qkv; cudaGetSymbolAddress((void**)&qkv, g_qkv);
    __half* att; cudaGetSymbolAddress((void**)&att, g_att);
    __half* xa;  cudaGetSymbolAddress((void**)&xa,  g_xa);
    __half* wqT; cudaGetSymbolAddress((void**)&wqT, g_wqkvT);
    __half* woT; cudaGetSymbolAddress((void**)&woT, g_woutT);
    float*  bqp; cudaGetSymbolAddress((void**)&bqp, g_bqkvp);

    cudaFuncSetAttribute(hgemm<true>,
                         cudaFuncAttributeMaxDynamicSharedMemorySize, GEMM_SMEM);
    cudaFuncSetAttribute(hgemm<false>,
                         cudaFuncAttributeMaxDynamicSharedMemorySize, GEMM_SMEM);
    cudaFuncSetAttribute(attn_fp16,
                         cudaFuncAttributeMaxDynamicSharedMemorySize, ATTN_SMEM);

    // --- fused pre-pass (x convert + bias + both weight transposes) ---
    prep_all<<<6144, 256>>>(x, w_qkv, w_out, b_qkv);

    // 1) QKV projection (fp16 mma, 2 CTAs/SM, 1 barrier/k-tile)
    {
        dim3 grid(3 * DIM / 128, ROWS / 128);
        hgemm<true><<<grid, 256, GEMM_SMEM>>>(xa, wqT, bqp, qkv, 3 * DIM);
    }
    // 2) causal multi-head attention (fp16 mma flash, 1 barrier/KV tile)
    {
        dim3 grid(SEQ / AQT, HEADS, BATCH);
        attn_fp16<<<grid, 128, ATTN_SMEM>>>();
    }
    // 3) output projection (fp16 mma, fp32 out)
    {
        dim3 grid(DIM / 128, ROWS / 128);
        hgemm<false><<<grid, 256, GEMM_SMEM>>>(att, woT, b_out, out, DIM);
    }
}

// round 13
// speedup vs baseline: 9.7062x; 1.0793x over previous
#include <cuda_runtime.h>
#include <cuda_fp16.h>
#include <cstdint>

#define BATCH 4
#define SEQ   2048
#define DIM   1024
#define HEADS 16
#define HD    64
#define ROWS (BATCH * SEQ)        // 8192

// Scratch (allocation-free rule: device globals), fp16 operand space
__device__ __half g_qkv[(size_t)ROWS * 3 * DIM];   // qkv, σ-permuted cols
__device__ __half g_att[(size_t)ROWS * DIM];       // attention out, σ-slot cols
__device__ __half g_xa[(size_t)ROWS * DIM];        // x, σ-permuted cols
__device__ __half g_wqkvT[(size_t)(3 * DIM) * DIM];// w_qkv^T, k+n σ-permuted
__device__ __half g_woutT[(size_t)DIM * DIM];      // w_out^T, k σ-permuted
__device__ float  g_bqkvp[3 * DIM];                // σ-permuted bias (fp32)

// ---------------------------------------------------------------------------
// helpers
// ---------------------------------------------------------------------------
__device__ __forceinline__ int sig16(int w) {          // w in [0,16)
    return 2 * (w >> 2) + (w & 1) + 8 * ((w >> 1) & 1);
}
__device__ __forceinline__ int sig(int s) { return (s & ~15) | sig16(s & 15); }

__device__ __forceinline__ void mma16(float* c, const uint32_t* a, const uint32_t* b) {
    asm volatile(
        "mma.sync.aligned.m16n8k16.row.col.f32.f16.f16.f32 "
        "{%0,%1,%2,%3}, {%4,%5,%6,%7}, {%8,%9}, {%0,%1,%2,%3};"
        : "+f"(c[0]), "+f"(c[1]), "+f"(c[2]), "+f"(c[3])
        : "r"(a[0]), "r"(a[1]), "r"(a[2]), "r"(a[3]), "r"(b[0]), "r"(b[1]));
}
__device__ __forceinline__ void ldmx4t(uint32_t* r, uint32_t addr) {
    asm volatile("ldmatrix.sync.aligned.m8n8.x4.trans.shared.b16 "
                 "{%0,%1,%2,%3}, [%4];"
                 : "=r"(r[0]), "=r"(r[1]), "=r"(r[2]), "=r"(r[3]) : "r"(addr));
}
__device__ __forceinline__ uint32_t h2exp2(uint32_t x) {
    uint32_t r;
    asm("ex2.approx.f16x2 %0, %1;" : "=r"(r) : "r"(x));
    return r;
}
__device__ __forceinline__ uint32_t sptr(const void* p) {
    return (uint32_t)__cvta_generic_to_shared(p);
}
__device__ __forceinline__ void cp16(uint32_t s, const void* g) {
    asm volatile("cp.async.ca.shared.global [%0], [%1], 16;" :: "r"(s), "l"(g));
}
#define CP_COMMIT() asm volatile("cp.async.commit_group;")
#define CP_WAIT0()  asm volatile("cp.async.wait_group 0;")

// ---------------------------------------------------------------------------
// Fused pre-pass kernel (unchanged from R11)
// ---------------------------------------------------------------------------
__device__ __forceinline__ void prep_w_tile(const float* __restrict__ src,
                                            __half* __restrict__ dst,
                                            int N, int kb, int nb, bool permn,
                                            int tid) {
    __shared__ float tile[32][33];
    const int tx = tid & 15, ty = tid >> 4;
    tile[ty][tx]           = src[(size_t)(kb + ty) * N + nb + tx];
    tile[ty][tx + 16]      = src[(size_t)(kb + ty) * N + nb + tx + 16];
    tile[ty + 16][tx]      = src[(size_t)(kb + ty + 16) * N + nb + tx];
    tile[ty + 16][tx + 16] = src[(size_t)(kb + ty + 16) * N + nb + tx + 16];
    __syncthreads();
    const int s  = 2 * tx;
    const int t0 = (s & 16) | sig16(s & 15);
    #pragma unroll
    for (int i = 0; i < 2; i++) {
        const int ny = ty + 16 * i;
        const int nn = permn ? ((ny & ~15) | sig16(ny & 15)) : ny;
        __half2 h = __floats2half2_rn(tile[t0][nn], tile[t0 + 1][nn]);
        *(__half2*)&dst[(size_t)(nb + ny) * DIM + kb + s] = h;
    }
}

__global__ __launch_bounds__(256)
void prep_all(const float* __restrict__ x, const float* __restrict__ wq,
              const float* __restrict__ wo, const float* __restrict__ bq) {
    const int bid = blockIdx.x;
    const int tid = threadIdx.x;
    if (bid < 2048) {
        const size_t base = ((size_t)bid * 256 + tid) * 16;
        float v[16];
        #pragma unroll
        for (int i = 0; i < 16; i += 4) *(float4*)&v[i] = *(const float4*)&x[base + i];
        __half2 h[8];
        #pragma unroll
        for (int u = 0; u < 4; u++) {
            h[2 * u]     = __floats2half2_rn(v[2 * u],     v[2 * u + 1]);
            h[2 * u + 1] = __floats2half2_rn(v[2 * u + 8], v[2 * u + 9]);
        }
        *(uint4*)&g_xa[base]     = *(uint4*)&h[0];
        *(uint4*)&g_xa[base + 8] = *(uint4*)&h[4];
        if (bid < 12) {
            const int s = bid * 256 + tid;
            g_bqkvp[s] = bq[sig(s)];
        }
    } else if (bid < 2048 + 3072) {
        const int b2 = bid - 2048;
        prep_w_tile(wq, g_wqkvT, 3 * DIM, (b2 & 31) * 32, (b2 >> 5) * 32, true, tid);
    } else {
        const int b3 = bid - 5120;
        prep_w_tile(wo, g_woutT, DIM, (b3 & 31) * 32, (b3 >> 5) * 32, false, tid);
    }
}

// ---------------------------------------------------------------------------
// FP16 MMA GEMM v6: block 128x128, BK=64, 128 thr (4 warps 2x2), warp 64x64.
// 128 smem-B/MMA (crossbar-balanced). 2 CTAs/SM. 1 barrier per k-tile.
// ---------------------------------------------------------------------------
#define GKW 80
#define GA_H (128 * GKW)
#define GSTG_H (2 * GA_H)
#define GEMM_SMEM (2 * GSTG_H * 2)          // 81920 B

__device__ __forceinline__ void gemm_load(__half* stage,
                                          const __half* __restrict__ A,
                                          const __half* __restrict__ B,
                                          int bm, int bn, int k0, int tid) {
    #pragma unroll
    for (int i = 0; i < 8; i++) {
        int t = tid + i * 128;              // 0..1023
        int row = t >> 3, c = t & 7;
        cp16(sptr(stage + row * GKW + c * 8), A + (size_t)(bm + row) * DIM + k0 + c * 8);
        cp16(sptr(stage + GA_H + row * GKW + c * 8), B + (size_t)(bn + row) * DIM + k0 + c * 8);
    }
}

template<bool HALF_OUT>
__global__ __launch_bounds__(128, 2)
void hgemm(const __half* __restrict__ A, const __half* __restrict__ B,
           const float* __restrict__ bias, void* __restrict__ Cv, int N) {
    extern __shared__ __half smh[];
    const int tid  = threadIdx.x;
    const int lane = tid & 31;
    const int wid  = tid >> 5;
    const int g    = lane >> 2;
    const int tig  = lane & 3;
    const int wm   = wid >> 1;          // 0..1
    const int wn   = wid & 1;           // 0..1
    const int bm   = blockIdx.y * 128;
    const int bn   = blockIdx.x * 128;

    float acc[4][8][4];
    #pragma unroll
    for (int mi = 0; mi < 4; mi++)
        #pragma unroll
        for (int ni = 0; ni < 8; ni++)
            #pragma unroll
            for (int j = 0; j < 4; j++) acc[mi][ni][j] = 0.f;

    constexpr int NT = DIM / 64;        // 16 k-tiles

    gemm_load(smh, A, B, bm, bn, 0, tid);
    CP_COMMIT();

    for (int t = 0; t < NT; t++) {
        CP_WAIT0();
        __syncthreads();
        if (t + 1 < NT) {
            gemm_load(smh + ((t + 1) & 1) * GSTG_H, A, B, bm, bn, (t + 1) * 64, tid);
            CP_COMMIT();
        }
        const __half* As = smh + (t & 1) * GSTG_H;
        const __half* Bs = As + GA_H;

        #pragma unroll
        for (int ks = 0; ks < 4; ks++) {
            const int co = ks * 16 + 4 * tig;
            uint32_t a[4][4], b[8][2];
            #pragma unroll
            for (int mi = 0; mi < 4; mi++) {
                const int m = wm * 64 + mi * 16 + g;
                uint2 lo = *(const uint2*)&As[m * GKW + co];
                uint2 hi = *(const uint2*)&As[(m + 8) * GKW + co];
                a[mi][0] = lo.x; a[mi][2] = lo.y;
                a[mi][1] = hi.x; a[mi][3] = hi.y;
            }
            #pragma unroll
            for (int ni = 0; ni < 8; ni++) {
                const int n = wn * 64 + ni * 8 + g;
                uint2 bb = *(const uint2*)&Bs[n * GKW + co];
                b[ni][0] = bb.x; b[ni][1] = bb.y;
            }
            #pragma unroll
            for (int mi = 0; mi < 4; mi++)
                #pragma unroll
                for (int ni = 0; ni < 8; ni++)
                    mma16(acc[mi][ni], a[mi], b[ni]);
        }
    }

    #pragma unroll
    for (int mi = 0; mi < 4; mi++) {
        const int r0 = bm + wm * 64 + mi * 16 + g;
        #pragma unroll
        for (int ni = 0; ni < 8; ni++) {
            const int col = bn + wn * 64 + ni * 8 + 2 * tig;
            const float b0 = bias[col], b1 = bias[col + 1];
            const float v00 = acc[mi][ni][0] + b0, v01 = acc[mi][ni][1] + b1;
            const float v10 = acc[mi][ni][2] + b0, v11 = acc[mi][ni][3] + b1;
            if (HALF_OUT) {
                __half* C = (__half*)Cv;
                *(__half2*)&C[(size_t)r0 * N + col]       = __floats2half2_rn(v00, v01);
                *(__half2*)&C[(size_t)(r0 + 8) * N + col] = __floats2half2_rn(v10, v11);
            } else {
                float* C = (float*)Cv;
                *(float2*)&C[(size_t)r0 * N + col]       = make_float2(v00, v01);
                *(float2*)&C[(size_t)(r0 + 8) * N + col] = make_float2(v10, v11);
            }
        }
    }
}

// ---------------------------------------------------------------------------
// FP16 MMA causal flash attention v7.
// Log2-domain softmax: log2(e) folded into q scale; P = ex2.approx.f16x2;
// row-sum l via ones-B MMA (fp32 accum, no shuffles).
// grid = (SEQ/128, HEADS, BATCH), 128 thr, warp = 32 q rows, 2 CTAs/SM.
// ---------------------------------------------------------------------------
#define AQT 128
#define KW  80
#define VW  72
#define KT_H (64 * KW)
#define VT_H (64 * VW)
#define ATTN_SMEM ((2 * KT_H + 2 * VT_H) * 2)   // 38912 B

__device__ __forceinline__ void attn_load_kv(__half* Ks, __half* Vs,
                                             int b, int h, int kt, int tid) {
    const size_t base = ((size_t)(b * SEQ + kt * 64)) * (3 * DIM) + DIM + h * HD;
    #pragma unroll
    for (int i = 0; i < 4; i++) {
        int t = tid + i * 128;              // 0..511
        int row = t >> 3, c = t & 7;
        const __half* src = &g_qkv[base + (size_t)row * 3 * DIM + c * 8];
        cp16(sptr(Ks + row * KW + c * 8), src);
        cp16(sptr(Vs + row * VW + c * 8), src + DIM);
    }
}

__global__ __launch_bounds__(128)
void attn_fp16() {
    extern __shared__ __half smh[];
    __half* Kb[2] = { smh, smh + KT_H };
    __half* Vb[2] = { smh + 2 * KT_H, smh + 2 * KT_H + VT_H };

    const int qt   = gridDim.x - 1 - blockIdx.x;   // longest-first scheduling
    const int h    = blockIdx.y;
    const int b    = blockIdx.z;
    const int tid  = threadIdx.x;
    const int lane = tid & 31;
    const int wid  = tid >> 5;
    const int g    = lane >> 2;
    const int tig  = lane & 3;

    const int qr  = qt * AQT + wid * 32;
    const int nkt = qt * 2 + 2;

    attn_load_kv(Kb[0], Vb[0], b, h, 0, tid);
    CP_COMMIT();

    // q scale folds 1/sqrt(64) AND log2(e): softmax runs in base-2 domain
    const __half2 qsc = __float2half2_rn(0.125f * 1.44269504f);
    uint32_t qf[2][4][4];
    #pragma unroll
    for (int s = 0; s < 2; s++) {
        const size_t r0 = ((size_t)(b * SEQ + qr + s * 16 + g)) * (3 * DIM) + h * HD;
        const size_t r1 = r0 + (size_t)8 * 3 * DIM;
        #pragma unroll
        for (int ks = 0; ks < 4; ks++) {
            uint2 lo = *(const uint2*)&g_qkv[r0 + ks * 16 + 4 * tig];
            uint2 hi = *(const uint2*)&g_qkv[r1 + ks * 16 + 4 * tig];
            __half2 t;
            t = __hmul2(*(__half2*)&lo.x, qsc); qf[s][ks][0] = *(uint32_t*)&t;
            t = __hmul2(*(__half2*)&hi.x, qsc); qf[s][ks][1] = *(uint32_t*)&t;
            t = __hmul2(*(__half2*)&lo.y, qsc); qf[s][ks][2] = *(uint32_t*)&t;
            t = __hmul2(*(__half2*)&hi.y, qsc); qf[s][ks][3] = *(uint32_t*)&t;
        }
    }

    float oacc[2][8][4];
    #pragma unroll
    for (int s = 0; s < 2; s++)
        #pragma unroll
        for (int ni = 0; ni < 8; ni++)
            #pragma unroll
            for (int j = 0; j < 4; j++) oacc[s][ni][j] = 0.f;
    float mm[2][2] = {{-1e30f, -1e30f}, {-1e30f, -1e30f}};
    float ll[2][2] = {{0.f, 0.f}, {0.f, 0.f}};
    const uint32_t ones2 = 0x3C003C00u;            // half2(1,1)
    const uint32_t onesb[2] = { ones2, ones2 };

    for (int kt = 0; kt < nkt; kt++) {
        CP_WAIT0();
        __syncthreads();
        if (kt + 1 < nkt) {
            attn_load_kv(Kb[(kt + 1) & 1], Vb[(kt + 1) & 1], b, h, kt + 1, tid);
            CP_COMMIT();
        }
        const __half* Ks = Kb[kt & 1];
        const __half* Vs = Vb[kt & 1];

        const bool active = (kt * 64 <= qr + 31);
        if (active) {
            const bool diag = ((kt + 1) * 64 > qr);

            // ---- S = Q K^T (log2-e domain): K frags shared by both subtiles
            float sacc[2][8][4];
            #pragma unroll
            for (int s = 0; s < 2; s++)
                #pragma unroll
                for (int ni = 0; ni < 8; ni++)
                    #pragma unroll
                    for (int j = 0; j < 4; j++) sacc[s][ni][j] = 0.f;

            #pragma unroll
            for (int ks = 0; ks < 4; ks++) {
                const int co = ks * 16 + 4 * tig;
                #pragma unroll
                for (int ni = 0; ni < 8; ni++) {
                    uint2 bb = *(const uint2*)&Ks[(ni * 8 + g) * KW + co];
                    uint32_t bfr[2] = { bb.x, bb.y };
                    mma16(sacc[0][ni], qf[0][ks], bfr);
                    mma16(sacc[1][ni], qf[1][ks], bfr);
                }
            }

            // ---- per-subtile: mask, max, P = ex2(S-m) in fp16x2, l via MMA
            uint32_t pa[2][4][4];
            #pragma unroll
            for (int s = 0; s < 2; s++) {
                const int rA = qr + s * 16 + g, rB = rA + 8;
                if (diag) {
                    #pragma unroll
                    for (int ni = 0; ni < 8; ni++) {
                        const int c0 = kt * 64 + ni * 8 + 2 * tig;
                        if (c0 > rA)     sacc[s][ni][0] = -1e30f;
                        if (c0 + 1 > rA) sacc[s][ni][1] = -1e30f;
                        if (c0 > rB)     sacc[s][ni][2] = -1e30f;
                        if (c0 + 1 > rB) sacc[s][ni][3] = -1e30f;
                    }
                }

                float t0 = -1e30f, t1 = -1e30f;
                #pragma unroll
                for (int ni = 0; ni < 8; ni++) {
                    t0 = fmaxf(t0, fmaxf(sacc[s][ni][0], sacc[s][ni][1]));
                    t1 = fmaxf(t1, fmaxf(sacc[s][ni][2], sacc[s][ni][3]));
                }
                t0 = fmaxf(t0, __shfl_xor_sync(0xffffffffu, t0, 1));
                t0 = fmaxf(t0, __shfl_xor_sync(0xffffffffu, t0, 2));
                t1 = fmaxf(t1, __shfl_xor_sync(0xffffffffu, t1, 1));
                t1 = fmaxf(t1, __shfl_xor_sync(0xffffffffu, t1, 2));

                const float nm0 = fmaxf(mm[s][0], t0), nm1 = fmaxf(mm[s][1], t1);
                const float cr0 = exp2f(mm[s][0] - nm0), cr1 = exp2f(mm[s][1] - nm1);
                ll[s][0] *= cr0; ll[s][1] *= cr1;
                #pragma unroll
                for (int ni = 0; ni < 8; ni++) {
                    oacc[s][ni][0] *= cr0; oacc[s][ni][1] *= cr0;
                    oacc[s][ni][2] *= cr1; oacc[s][ni][3] *= cr1;
                }

                // P in fp16x2: pa[ks] = {p(2ks,lo), p(2ks,hi), p(2ks+1,lo), p(2ks+1,hi)}
                #pragma unroll
                for (int ks = 0; ks < 4; ks++) {
                    const int n0 = 2 * ks, n1 = 2 * ks + 1;
                    __half2 d;
                    d = __floats2half2_rn(sacc[s][n0][0] - nm0, sacc[s][n0][1] - nm0);
                    pa[s][ks][0] = h2exp2(*(uint32_t*)&d);
                    d = __floats2half2_rn(sacc[s][n0][2] - nm1, sacc[s][n0][3] - nm1);
                    pa[s][ks][1] = h2exp2(*(uint32_t*)&d);
                    d = __floats2half2_rn(sacc[s][n1][0] - nm0, sacc[s][n1][1] - nm0);
                    pa[s][ks][2] = h2exp2(*(uint32_t*)&d);
                    d = __floats2half2_rn(sacc[s][n1][2] - nm1, sacc[s][n1][3] - nm1);
                    pa[s][ks][3] = h2exp2(*(uint32_t*)&d);
                }

                // l += P @ ones  (fp32 accum; every thread gets its row's sum)
                float lacc[4] = {0.f, 0.f, 0.f, 0.f};
                #pragma unroll
                for (int ks = 0; ks < 4; ks++) mma16(lacc, pa[s][ks], onesb);
                ll[s][0] += lacc[0];
                ll[s][1] += lacc[2];
                mm[s][0] = nm0; mm[s][1] = nm1;
            }

            // ---- O += P @ V ----
            const int lt = lane >> 3, lr = lane & 7;
            #pragma unroll
            for (int ks = 0; ks < 4; ks++) {
                uint32_t vb[4][4];
                const int vrow = ks * 16 + (lt & 1) * 8 + lr;
                const int vcb  = (lt >> 1) * 8;
                #pragma unroll
                for (int d4 = 0; d4 < 4; d4++)
                    ldmx4t(vb[d4], sptr(Vs + vrow * VW + vcb + d4 * 16));
                #pragma unroll
                for (int s = 0; s < 2; s++) {
                    #pragma unroll
                    for (int d4 = 0; d4 < 4; d4++) {
                        mma16(oacc[s][2 * d4],     pa[s][ks], &vb[d4][0]);
                        mma16(oacc[s][2 * d4 + 1], pa[s][ks], &vb[d4][2]);
                    }
                }
            }
        }
    }

    // ---- epilogue: O/l -> g_att (fp16, σ-slot cols) ----
    #pragma unroll
    for (int s = 0; s < 2; s++) {
        const float inv0 = 1.f / ll[s][0], inv1 = 1.f / ll[s][1];
        const size_t ob = ((size_t)(b * SEQ + qr + s * 16 + g)) * DIM + h * HD;
        #pragma unroll
        for (int ni = 0; ni < 8; ni++) {
            const int c = ni * 8 + 2 * tig;
            *(__half2*)&g_att[ob + c] =
                __floats2half2_rn(oacc[s][ni][0] * inv0, oacc[s][ni][1] * inv0);
            *(__half2*)&g_att[ob + (size_t)8 * DIM + c] =
                __floats2half2_rn(oacc[s][ni][2] * inv1, oacc[s][ni][3] * inv1);
        }
    }
}

// ---------------------------------------------------------------------------
extern "C" void kernel_launch(void* const* d_in, const int* in_sizes, int n_in,
                              void* d_out, int out_size) {
    const float* x     = (const float*)d_in[0];
    const float* w_qkv = (const float*)d_in[1];
    const float* b_qkv = (const float*)d_in[2];
    const float* w_out = (const float*)d_in[3];
    const float* b_out = (const float*)d_in[4];
    float* out = (float*)d_out;

    __half* qkv; cudaGetSymbolAddress((void**)&qkv, g_qkv);
    __half* att; cudaGetSymbolAddress((void**)&att, g_att);
    __half* xa;  cudaGetSymbolAddress((void**)&xa,  g_xa);
    __half* wqT; cudaGetSymbolAddress((void**)&wqT, g_wqkvT);
    __half* woT; cudaGetSymbolAddress((void**)&woT, g_woutT);
    float*  bqp; cudaGetSymbolAddress((void**)&bqp, g_bqkvp);

    cudaFuncSetAttribute(hgemm<true>,
                         cudaFuncAttributeMaxDynamicSharedMemorySize, GEMM_SMEM);
    cudaFuncSetAttribute(hgemm<false>,
                         cudaFuncAttributeMaxDynamicSharedMemorySize, GEMM_SMEM);
    cudaFuncSetAttribute(attn_fp16,
                         cudaFuncAttributeMaxDynamicSharedMemorySize, ATTN_SMEM);

    // --- fused pre-pass ---
    prep_all<<<6144, 256>>>(x, w_qkv, w_out, b_qkv);

    // 1) QKV projection (fp16 mma, warp tile 64x64, 2 CTAs/SM)
    {
        dim3 grid(3 * DIM / 128, ROWS / 128);
        hgemm<true><<<grid, 128, GEMM_SMEM>>>(xa, wqT, bqp, qkv, 3 * DIM);
    }
    // 2) causal multi-head attention (log2-softmax, fp16x2 exp, l via MMA)
    {
        dim3 grid(SEQ / AQT, HEADS, BATCH);
        attn_fp16<<<grid, 128, ATTN_SMEM>>>();
    }
    // 3) output projection
    {
        dim3 grid(DIM / 128, ROWS / 128);
        hgemm<false><<<grid, 128, GEMM_SMEM>>>(att, woT, b_out, out, DIM);
    }
}